// round 4
// baseline (speedup 1.0000x reference)
#include <cuda_runtime.h>

#define BATCH 4
#define CH 128
#define HH 96
#define WW 96
#define HW (HH*WW)
#define EPSBN 1e-5f

#define SP2 136   // sample smem pitch (floats) for 128-px tiles
#define WP 132    // weight smem pitch
#define SMEM_DYN2 ((CH*SP2 + CH*WP)*4)

typedef unsigned long long u64;

// ------------------ packed f32x2 helpers ------------------------------------
__device__ __forceinline__ void fma2(u64 &d, u64 a, u64 b) {
    asm("fma.rn.f32x2 %0, %1, %2, %0;" : "+l"(d) : "l"(a), "l"(b));
}
__device__ __forceinline__ u64 bc2(float x) {
    u64 r; asm("mov.b64 %0, {%1, %1};" : "=l"(r) : "f"(x)); return r;
}
__device__ __forceinline__ float2 unp2(u64 v) {
    float2 f; asm("mov.b64 {%0, %1}, %2;" : "=f"(f.x), "=f"(f.y) : "l"(v)); return f;
}

// 8px x 8co micro-step: acc[px][cp] += x[px] * w[cp]
#define GSTEP8(SROW, WROW) { \
    float4 x0 = *(const float4*)(SROW); \
    float4 x1 = *(const float4*)((SROW)+4); \
    ulonglong2 wA = *(const ulonglong2*)(WROW); \
    ulonglong2 wB = *(const ulonglong2*)((WROW)+4); \
    u64 xb[8]; \
    xb[0]=bc2(x0.x); xb[1]=bc2(x0.y); xb[2]=bc2(x0.z); xb[3]=bc2(x0.w); \
    xb[4]=bc2(x1.x); xb[5]=bc2(x1.y); xb[6]=bc2(x1.z); xb[7]=bc2(x1.w); \
    _Pragma("unroll") for (int _p = 0; _p < 8; _p++) { \
        fma2(acc[_p][0], wA.x, xb[_p]); fma2(acc[_p][1], wA.y, xb[_p]); \
        fma2(acc[_p][2], wB.x, xb[_p]); fma2(acc[_p][3], wB.y, xb[_p]); \
    } }

#define ACC_INIT8 u64 acc[8][4]; _Pragma("unroll") for (int _i=0;_i<8;_i++) _Pragma("unroll") for(int _j=0;_j<4;_j++) acc[_i][_j]=0ull;

// unpack accumulators to v[px][co_local 0..7]
#define UNPACK8(V) float V[8][8]; \
    _Pragma("unroll") for (int _p=0;_p<8;_p++) _Pragma("unroll") for (int _k=0;_k<4;_k++) { \
        float2 _f = unp2(acc[_p][_k]); V[_p][2*_k]=_f.x; V[_p][2*_k+1]=_f.y; }

// ------------------ scratch: static device globals (no allocation) ----------
__device__ float g_xc [BATCH*CH*HW];   // x_c NCHW
__device__ float g_xn [BATCH*HW*CH];   // x_c NHWC (coalesced bilinear gather)
__device__ float g_off[BATCH*18*HW];   // offset conv output
__device__ float g_wdT[9*CH*CH];       // w_def  -> [n][ci][co]
__device__ float g_wsT[9*CH*CH];       // w_std  -> [k][ci][co]
__device__ float g_x1 [BATCH*CH*HW];   // deform branch post BN+ReLU
__device__ float g_x2c[BATCH*CH*HW];   // std branch post BN+ReLU + x_c

// ------------------ k_prep: weight transposes -------------------------------
__global__ void k_prep(const float* __restrict__ wdef, const float* __restrict__ wstd) {
    int i = blockIdx.x * 256 + threadIdx.x;
    if (i >= 9*CH*CH) return;
    int co = i & 127;
    int t  = i >> 7;          // n*128 + ci
    int n  = t >> 7, ci = t & 127;
    int src = co*1152 + ci*9 + n;
    g_wdT[i] = wdef[src];
    g_wsT[i] = wstd[src];
}

// ------------------ k_conv_in: 1x1 conv 128->128, NCHW + NHWC out -----------
__global__ __launch_bounds__(256) void k_conv_in(const float* __restrict__ x,
                                                 const float* __restrict__ w,
                                                 const float* __restrict__ bias) {
    __shared__ float Ws[32*WP];
    __shared__ float Xs[32*64];
    int tid = threadIdx.x;
    int b  = blockIdx.y;
    int p0 = blockIdx.x * 64;
    int ty = tid >> 4, tx = tid & 15;
    int cob = ty*8, pxb = tx*4;

    u64 acc[4][4];
#pragma unroll
    for (int i = 0; i < 4; i++)
#pragma unroll
        for (int j = 0; j < 4; j++) acc[i][j] = 0ull;

    for (int cb = 0; cb < CH; cb += 32) {
        __syncthreads();
        for (int idx = tid; idx < 4096; idx += 256) {
            int co = idx >> 5, c = idx & 31;
            Ws[c*WP + co] = w[co*CH + cb + c];
        }
        for (int idx = tid; idx < 2048; idx += 256) {
            int c = idx >> 6, p = idx & 63;
            Xs[c*64 + p] = x[((size_t)b*CH + cb + c)*HW + p0 + p];
        }
        __syncthreads();
#pragma unroll 8
        for (int c = 0; c < 32; c++) {
            float4 xv = *(const float4*)&Xs[c*64 + pxb];
            ulonglong2 wA = *(const ulonglong2*)&Ws[c*WP + cob];
            ulonglong2 wB = *(const ulonglong2*)&Ws[c*WP + cob + 4];
            u64 x0=bc2(xv.x), x1=bc2(xv.y), x2=bc2(xv.z), x3=bc2(xv.w);
            fma2(acc[0][0],wA.x,x0); fma2(acc[0][1],wA.y,x0); fma2(acc[0][2],wB.x,x0); fma2(acc[0][3],wB.y,x0);
            fma2(acc[1][0],wA.x,x1); fma2(acc[1][1],wA.y,x1); fma2(acc[1][2],wB.x,x1); fma2(acc[1][3],wB.y,x1);
            fma2(acc[2][0],wA.x,x2); fma2(acc[2][1],wA.y,x2); fma2(acc[2][2],wB.x,x2); fma2(acc[2][3],wB.y,x2);
            fma2(acc[3][0],wA.x,x3); fma2(acc[3][1],wA.y,x3); fma2(acc[3][2],wB.x,x3); fma2(acc[3][3],wB.y,x3);
        }
    }
    float v[4][8];
#pragma unroll
    for (int k = 0; k < 4; k++)
#pragma unroll
        for (int px = 0; px < 4; px++) {
            float2 f = unp2(acc[px][k]);
            v[px][2*k] = f.x; v[px][2*k+1] = f.y;
        }
    float bb[8];
#pragma unroll
    for (int u = 0; u < 8; u++) bb[u] = __ldg(&bias[cob + u]);
#pragma unroll
    for (int u = 0; u < 8; u++) {
        float4 o = make_float4(v[0][u]+bb[u], v[1][u]+bb[u], v[2][u]+bb[u], v[3][u]+bb[u]);
        *(float4*)&g_xc[((size_t)b*CH + cob + u)*HW + p0 + pxb] = o;
    }
#pragma unroll
    for (int px = 0; px < 4; px++) {
        float4 o0 = make_float4(v[px][0]+bb[0], v[px][1]+bb[1], v[px][2]+bb[2], v[px][3]+bb[3]);
        float4 o1 = make_float4(v[px][4]+bb[4], v[px][5]+bb[5], v[px][6]+bb[6], v[px][7]+bb[7]);
        float* np = g_xn + ((size_t)(b*HW) + p0 + pxb + px)*CH + cob;
        *(float4*)np = o0; *(float4*)(np+4) = o1;
    }
}

// ------------------ k_off: 3x3 conv 128->18 (offsets), pad=1 ----------------
__global__ __launch_bounds__(384) void k_off(const float* __restrict__ w,
                                             const float* __restrict__ bias) {
    __shared__ float ws[1152*9];    // [ci*9+k][co_local]
    int tid = threadIdx.x;
    int b = blockIdx.y, cog = blockIdx.z;   // cog in {0,1}
    for (int idx = tid; idx < 10368; idx += 384) {
        int co = idx / 1152, cik = idx % 1152;
        ws[cik*9 + co] = w[(cog*9 + co)*1152 + cik];
    }
    __syncthreads();
    int i = blockIdx.x*4 + tid/96;
    int j = tid % 96;
    float acc[9];
#pragma unroll
    for (int c = 0; c < 9; c++) acc[c] = 0.f;
    const float* xb = g_xc + (size_t)b*CH*HW;
    for (int ci = 0; ci < CH; ci++) {
#pragma unroll
        for (int kh = 0; kh < 3; kh++) {
            int row = i + kh - 1;
            bool rok = ((unsigned)row < 96u);
            const float* xr = xb + (size_t)ci*HW + row*WW;
#pragma unroll
            for (int kw = 0; kw < 3; kw++) {
                int col = j + kw - 1;
                float xv = (rok && (unsigned)col < 96u) ? xr[col] : 0.f;
                int wb = (ci*9 + kh*3 + kw)*9;
#pragma unroll
                for (int c = 0; c < 9; c++) acc[c] += ws[wb + c] * xv;
            }
        }
    }
#pragma unroll
    for (int c = 0; c < 9; c++)
        g_off[(size_t)((b*18 + cog*9 + c)*HH + i)*WW + j] = acc[c] + __ldg(&bias[cog*9 + c]);
}

// ------------------ k_deform: bilinear gather + K=1152 GEMM + BN1/ReLU ------
// block tile: 128 px x 128 co, thread tile 8x8
__global__ __launch_bounds__(256) void k_deform(const float* __restrict__ bdef,
                                                const float* __restrict__ bn1) {
    extern __shared__ float sm[];
    float* s  = sm;             // [128 ci][SP2 px]
    float* ws = sm + CH*SP2;    // [128 ci][WP co]
    int tid = threadIdx.x;
    int b  = blockIdx.y;
    int p0 = blockIdx.x * 128;
    int warp = tid >> 5, lane = tid & 31;
    int ty = tid >> 4, tx = tid & 15;
    int cob = ty*8, pxb = tx*8;

    ACC_INIT8
    const float* xnb = g_xn + (size_t)b*HW*CH;

    for (int n = 0; n < 9; n++) {
        __syncthreads();
        // stage weights [ci][co] for this tap
        for (int idx = tid*4; idx < 16384; idx += 1024) {
            float4 wv = *(const float4*)&g_wdT[n*16384 + idx];
            int ci = idx >> 7, co = idx & 127;
            *(float4*)&ws[ci*WP + co] = wv;
        }
        // stage bilinear samples: warp per pixel (16 px/warp), lanes over channels
        float dnx = (float)(n/3 - 1), dny = (float)(n%3 - 1);
#pragma unroll 4
        for (int k = 0; k < 16; k++) {
            int px = warp*16 + k;
            int pix = p0 + px;
            int i = pix / 96, j = pix - i*96;
            float ox = __ldg(&g_off[(size_t)(b*18 + n    )*HW + pix]);
            float oy = __ldg(&g_off[(size_t)(b*18 + n + 9)*HW + pix]);
            float pfx = ox + dnx + (float)(i + 1);
            float pfy = oy + dny + (float)(j + 1);
            float qx = floorf(pfx), qy = floorf(pfy);
            float ltx = fminf(fmaxf(qx,       0.f), 97.f);
            float lty = fminf(fmaxf(qy,       0.f), 97.f);
            float rbx = fminf(fmaxf(qx + 1.f, 0.f), 97.f);
            float rby = fminf(fmaxf(qy + 1.f, 0.f), 97.f);
            float pcx = fminf(fmaxf(pfx, 0.f), 97.f);
            float pcy = fminf(fmaxf(pfy, 0.f), 97.f);
            float glt = (1.f + (ltx - pcx)) * (1.f + (lty - pcy));
            float grb = (1.f - (rbx - pcx)) * (1.f - (rby - pcy));
            float glb = (1.f + (ltx - pcx)) * (1.f - (rby - pcy));
            float grt = (1.f - (rbx - pcx)) * (1.f + (lty - pcy));
            int ax = (int)ltx - 1, ay = (int)lty - 1;
            int bx = (int)rbx - 1, by = (int)rby - 1;
            bool vax = ((unsigned)ax < 96u), vay = ((unsigned)ay < 96u);
            bool vbx = ((unsigned)bx < 96u), vby = ((unsigned)by < 96u);
            bool v_lt = vax && vay, v_rb = vbx && vby;
            bool v_lb = vax && vby, v_rt = vbx && vay;
            const float* plt = xnb + (size_t)(ax*96 + ay)*CH;
            const float* prb = xnb + (size_t)(bx*96 + by)*CH;
            const float* plb = xnb + (size_t)(ax*96 + by)*CH;
            const float* prt = xnb + (size_t)(bx*96 + ay)*CH;
#pragma unroll
            for (int it = 0; it < 4; it++) {
                int ci = it*32 + lane;
                float vv = 0.f;
                if (v_lt) vv += glt * plt[ci];
                if (v_rb) vv += grb * prb[ci];
                if (v_lb) vv += glb * plb[ci];
                if (v_rt) vv += grt * prt[ci];
                s[ci*SP2 + px] = vv;
            }
        }
        __syncthreads();
#pragma unroll 8
        for (int c = 0; c < CH; c++) {
            GSTEP8(&s[c*SP2 + pxb], &ws[c*WP + cob])
        }
    }
    // epilogue: +bias, BN1, ReLU
    UNPACK8(v)
#pragma unroll
    for (int u = 0; u < 8; u++) {
        int co = cob + u;
        float inv = __ldg(&bn1[co]) / sqrtf(__ldg(&bn1[384 + co]) + EPSBN);
        float add = __ldg(&bn1[128 + co]) - __ldg(&bn1[256 + co]) * inv;
        float bi  = __ldg(&bdef[co]);
        float4 o0 = make_float4(v[0][u], v[1][u], v[2][u], v[3][u]);
        float4 o1 = make_float4(v[4][u], v[5][u], v[6][u], v[7][u]);
        o0.x = fmaxf((o0.x + bi)*inv + add, 0.f); o0.y = fmaxf((o0.y + bi)*inv + add, 0.f);
        o0.z = fmaxf((o0.z + bi)*inv + add, 0.f); o0.w = fmaxf((o0.w + bi)*inv + add, 0.f);
        o1.x = fmaxf((o1.x + bi)*inv + add, 0.f); o1.y = fmaxf((o1.y + bi)*inv + add, 0.f);
        o1.z = fmaxf((o1.z + bi)*inv + add, 0.f); o1.w = fmaxf((o1.w + bi)*inv + add, 0.f);
        float* op = &g_x1[((size_t)b*CH + co)*HW + p0 + pxb];
        *(float4*)op = o0; *(float4*)(op+4) = o1;
    }
}

// ------------------ k_std: 3x3 conv + BN2/ReLU + residual add ---------------
__global__ __launch_bounds__(256) void k_std(const float* __restrict__ bstd,
                                             const float* __restrict__ bn2) {
    extern __shared__ float sm[];
    float* s  = sm;
    float* ws = sm + CH*SP2;
    int tid = threadIdx.x;
    int b  = blockIdx.y;
    int p0 = blockIdx.x * 128;
    int ty = tid >> 4, tx = tid & 15;
    int cob = ty*8, pxb = tx*8;

    ACC_INIT8

    for (int n = 0; n < 9; n++) {
        __syncthreads();
        for (int idx = tid*4; idx < 16384; idx += 1024) {
            float4 wv = *(const float4*)&g_wsT[n*16384 + idx];
            int ci = idx >> 7, co = idx & 127;
            *(float4*)&ws[ci*WP + co] = wv;
        }
        int di = n/3 - 1, dj = n%3 - 1;
        for (int idx = tid; idx < 16384; idx += 256) {
            int ci = idx >> 7, px = idx & 127;
            int pix = p0 + px;
            int i = pix / 96, j = pix - i*96;
            int ii = i + di, jj = j + dj;
            float vv = ((unsigned)ii < 96u && (unsigned)jj < 96u)
                      ? g_xc[((size_t)b*CH + ci)*HW + ii*WW + jj] : 0.f;
            s[ci*SP2 + px] = vv;
        }
        __syncthreads();
#pragma unroll 8
        for (int c = 0; c < CH; c++) {
            GSTEP8(&s[c*SP2 + pxb], &ws[c*WP + cob])
        }
    }
    UNPACK8(v)
#pragma unroll
    for (int u = 0; u < 8; u++) {
        int co = cob + u;
        float inv = __ldg(&bn2[co]) / sqrtf(__ldg(&bn2[384 + co]) + EPSBN);
        float add = __ldg(&bn2[128 + co]) - __ldg(&bn2[256 + co]) * inv;
        float bi  = __ldg(&bstd[co]);
        const float* xp = &g_xc[((size_t)b*CH + co)*HW + p0 + pxb];
        float4 xc0 = *(const float4*)xp;
        float4 xc1 = *(const float4*)(xp+4);
        float4 o0 = make_float4(v[0][u], v[1][u], v[2][u], v[3][u]);
        float4 o1 = make_float4(v[4][u], v[5][u], v[6][u], v[7][u]);
        o0.x = fmaxf((o0.x + bi)*inv + add, 0.f) + xc0.x;
        o0.y = fmaxf((o0.y + bi)*inv + add, 0.f) + xc0.y;
        o0.z = fmaxf((o0.z + bi)*inv + add, 0.f) + xc0.z;
        o0.w = fmaxf((o0.w + bi)*inv + add, 0.f) + xc0.w;
        o1.x = fmaxf((o1.x + bi)*inv + add, 0.f) + xc1.x;
        o1.y = fmaxf((o1.y + bi)*inv + add, 0.f) + xc1.y;
        o1.z = fmaxf((o1.z + bi)*inv + add, 0.f) + xc1.z;
        o1.w = fmaxf((o1.w + bi)*inv + add, 0.f) + xc1.w;
        float* op = &g_x2c[((size_t)b*CH + co)*HW + p0 + pxb];
        *(float4*)op = o0; *(float4*)(op+4) = o1;
    }
}

// ------------------ k_out: final 1x1 conv 256->256 --------------------------
// block tile: 128 px x 128 co (z selects co half), K=256 staged in 32-ci chunks
__global__ __launch_bounds__(256) void k_out(const float* __restrict__ w,
                                             const float* __restrict__ bias,
                                             float* __restrict__ out) {
    __shared__ float Ws[32*WP];
    __shared__ float Xs[32*SP2];
    int tid = threadIdx.x;
    int b  = blockIdx.y;
    int z  = blockIdx.z;
    int p0 = blockIdx.x * 128;
    int ty = tid >> 4, tx = tid & 15;
    int cob = ty*8, pxb = tx*8;

    ACC_INIT8

    for (int cb = 0; cb < 256; cb += 32) {
        __syncthreads();
        for (int idx = tid; idx < 4096; idx += 256) {
            int co = idx >> 5, c = idx & 31;
            Ws[c*WP + co] = w[(z*128 + co)*256 + cb + c];
        }
        const float* src = (cb < 128) ? g_x1 + ((size_t)b*CH + cb)*HW
                                      : g_x2c + ((size_t)b*CH + cb - 128)*HW;
        for (int idx = tid; idx < 4096; idx += 256) {
            int c = idx >> 7, p = idx & 127;
            Xs[c*SP2 + p] = src[(size_t)c*HW + p0 + p];
        }
        __syncthreads();
#pragma unroll 8
        for (int c = 0; c < 32; c++) {
            GSTEP8(&Xs[c*SP2 + pxb], &Ws[c*WP + cob])
        }
    }
    UNPACK8(v)
#pragma unroll
    for (int u = 0; u < 8; u++) {
        int co = cob + u;
        float bi = __ldg(&bias[z*128 + co]);
        float4 o0 = make_float4(v[0][u]+bi, v[1][u]+bi, v[2][u]+bi, v[3][u]+bi);
        float4 o1 = make_float4(v[4][u]+bi, v[5][u]+bi, v[6][u]+bi, v[7][u]+bi);
        float* op = &out[((size_t)(b*256 + z*128 + co))*HW + p0 + pxb];
        *(float4*)op = o0; *(float4*)(op+4) = o1;
    }
}

// ------------------ launch ---------------------------------------------------
extern "C" void kernel_launch(void* const* d_in, const int* in_sizes, int n_in,
                              void* d_out, int out_size) {
    const float* x     = (const float*)d_in[0];
    const float* w_in  = (const float*)d_in[1];
    const float* b_in  = (const float*)d_in[2];
    const float* w_off = (const float*)d_in[3];
    const float* b_off = (const float*)d_in[4];
    const float* w_def = (const float*)d_in[5];
    const float* b_def = (const float*)d_in[6];
    const float* bn1   = (const float*)d_in[7];
    const float* w_std = (const float*)d_in[8];
    const float* b_std = (const float*)d_in[9];
    const float* bn2   = (const float*)d_in[10];
    const float* w_out = (const float*)d_in[11];
    const float* b_out = (const float*)d_in[12];
    float* out = (float*)d_out;

    cudaFuncSetAttribute(k_deform, cudaFuncAttributeMaxDynamicSharedMemorySize, SMEM_DYN2);
    cudaFuncSetAttribute(k_std,    cudaFuncAttributeMaxDynamicSharedMemorySize, SMEM_DYN2);

    k_prep   <<<576, 256>>>(w_def, w_std);
    k_conv_in<<<dim3(144, BATCH), 256>>>(x, w_in, b_in);
    k_off    <<<dim3(24, BATCH, 2), 384>>>(w_off, b_off);
    k_deform <<<dim3(72, BATCH), 256, SMEM_DYN2>>>(b_def, bn1);
    k_std    <<<dim3(72, BATCH), 256, SMEM_DYN2>>>(b_std, bn2);
    k_out    <<<dim3(72, BATCH, 2), 256>>>(w_out, b_out, out);
}

// round 5
// speedup vs baseline: 1.1743x; 1.1743x over previous
#include <cuda_runtime.h>

#define BATCH 4
#define CH 128
#define HH 96
#define WW 96
#define HW (HH*WW)
#define EPSBN 1e-5f

#define SP 68    // sample smem pitch (mult of 4 -> float4 aligned)
#define WP 132   // weight smem pitch
#define SMEM_DYN ((CH*SP + CH*WP)*4)

typedef unsigned long long u64;

// ------------------ packed f32x2 helpers ------------------------------------
__device__ __forceinline__ void fma2(u64 &d, u64 a, u64 b) {
    asm("fma.rn.f32x2 %0, %1, %2, %0;" : "+l"(d) : "l"(a), "l"(b));
}
__device__ __forceinline__ u64 bc2(float x) {
    u64 r; asm("mov.b64 %0, {%1, %1};" : "=l"(r) : "f"(x)); return r;
}
__device__ __forceinline__ float2 unp2(u64 v) {
    float2 f; asm("mov.b64 {%0, %1}, %2;" : "=f"(f.x), "=f"(f.y) : "l"(v)); return f;
}

// GEMM micro-step: acc[px][cp] += x[px] * w[cp], cp packs co pairs
#define GSTEP(SROW, WROW) { \
    float4 xv = *(const float4*)(SROW); \
    ulonglong2 wA = *(const ulonglong2*)(WROW); \
    ulonglong2 wB = *(const ulonglong2*)((WROW)+4); \
    u64 xb0=bc2(xv.x), xb1=bc2(xv.y), xb2=bc2(xv.z), xb3=bc2(xv.w); \
    fma2(acc[0][0],wA.x,xb0); fma2(acc[0][1],wA.y,xb0); fma2(acc[0][2],wB.x,xb0); fma2(acc[0][3],wB.y,xb0); \
    fma2(acc[1][0],wA.x,xb1); fma2(acc[1][1],wA.y,xb1); fma2(acc[1][2],wB.x,xb1); fma2(acc[1][3],wB.y,xb1); \
    fma2(acc[2][0],wA.x,xb2); fma2(acc[2][1],wA.y,xb2); fma2(acc[2][2],wB.x,xb2); fma2(acc[2][3],wB.y,xb2); \
    fma2(acc[3][0],wA.x,xb3); fma2(acc[3][1],wA.y,xb3); fma2(acc[3][2],wB.x,xb3); fma2(acc[3][3],wB.y,xb3); }

#define ACC_INIT u64 acc[4][4]; _Pragma("unroll") for (int _i=0;_i<4;_i++) _Pragma("unroll") for(int _j=0;_j<4;_j++) acc[_i][_j]=0ull;

// ------------------ scratch: static device globals (no allocation) ----------
__device__ float g_xc [BATCH*CH*HW];   // x_c NCHW
__device__ float g_xn [BATCH*HW*CH];   // x_c NHWC (coalesced bilinear gather)
__device__ float g_off[BATCH*18*HW];   // offset conv output
__device__ float g_wdT[9*CH*CH];       // w_def  -> [n][ci][co]
__device__ float g_wsT[9*CH*CH];       // w_std  -> [k][ci][co]
__device__ float g_x1 [BATCH*CH*HW];   // deform branch post BN+ReLU
__device__ float g_x2c[BATCH*CH*HW];   // std branch post BN+ReLU + x_c

// ------------------ k_prep: weight transposes -------------------------------
__global__ void k_prep(const float* __restrict__ wdef, const float* __restrict__ wstd) {
    int i = blockIdx.x * 256 + threadIdx.x;
    if (i >= 9*CH*CH) return;
    int co = i & 127;
    int t  = i >> 7;          // n*128 + ci
    int n  = t >> 7, ci = t & 127;
    int src = co*1152 + ci*9 + n;
    g_wdT[i] = wdef[src];
    g_wsT[i] = wstd[src];
}

// ------------------ k_conv_in: 1x1 conv 128->128, NCHW + NHWC out -----------
__global__ __launch_bounds__(256) void k_conv_in(const float* __restrict__ x,
                                                 const float* __restrict__ w,
                                                 const float* __restrict__ bias) {
    __shared__ float Ws[32*WP];
    __shared__ float Xs[32*64];
    int tid = threadIdx.x;
    int b  = blockIdx.y;
    int p0 = blockIdx.x * 64;
    int ty = tid >> 4, tx = tid & 15;
    int cob = ty*8, pxb = tx*4;

    ACC_INIT

    for (int cb = 0; cb < CH; cb += 32) {
        __syncthreads();
        for (int idx = tid; idx < 4096; idx += 256) {
            int co = idx >> 5, c = idx & 31;
            Ws[c*WP + co] = w[co*CH + cb + c];
        }
        for (int idx = tid; idx < 2048; idx += 256) {
            int c = idx >> 6, p = idx & 63;
            Xs[c*64 + p] = x[((size_t)b*CH + cb + c)*HW + p0 + p];
        }
        __syncthreads();
#pragma unroll 8
        for (int c = 0; c < 32; c++) {
            GSTEP(&Xs[c*64 + pxb], &Ws[c*WP + cob])
        }
    }
    // unpack to v[px][co_local]
    float v[4][8];
#pragma unroll
    for (int k = 0; k < 4; k++) {
#pragma unroll
        for (int px = 0; px < 4; px++) {
            float2 f = unp2(acc[px][k]);
            v[px][2*k] = f.x; v[px][2*k+1] = f.y;
        }
    }
    float bb[8];
#pragma unroll
    for (int u = 0; u < 8; u++) bb[u] = __ldg(&bias[cob + u]);
#pragma unroll
    for (int u = 0; u < 8; u++) {
        float4 o = make_float4(v[0][u]+bb[u], v[1][u]+bb[u], v[2][u]+bb[u], v[3][u]+bb[u]);
        *(float4*)&g_xc[((size_t)b*CH + cob + u)*HW + p0 + pxb] = o;
    }
#pragma unroll
    for (int px = 0; px < 4; px++) {
        float4 o0 = make_float4(v[px][0]+bb[0], v[px][1]+bb[1], v[px][2]+bb[2], v[px][3]+bb[3]);
        float4 o1 = make_float4(v[px][4]+bb[4], v[px][5]+bb[5], v[px][6]+bb[6], v[px][7]+bb[7]);
        float* np = g_xn + ((size_t)(b*HW) + p0 + pxb + px)*CH + cob;
        *(float4*)np = o0; *(float4*)(np+4) = o1;
    }
}

// ------------------ k_off: 3x3 conv 128->18 (offsets), pad=1 ----------------
__global__ __launch_bounds__(384) void k_off(const float* __restrict__ w,
                                             const float* __restrict__ bias) {
    __shared__ float ws[1152*9];    // [ci*9+k][co_local]
    int tid = threadIdx.x;
    int b = blockIdx.y, cog = blockIdx.z;   // cog in {0,1}
    for (int idx = tid; idx < 10368; idx += 384) {
        int co = idx / 1152, cik = idx % 1152;
        ws[cik*9 + co] = w[(cog*9 + co)*1152 + cik];
    }
    __syncthreads();
    int i = blockIdx.x*4 + tid/96;
    int j = tid % 96;
    float acc[9];
#pragma unroll
    for (int c = 0; c < 9; c++) acc[c] = 0.f;
    const float* xb = g_xc + (size_t)b*CH*HW;
    for (int ci = 0; ci < CH; ci++) {
#pragma unroll
        for (int kh = 0; kh < 3; kh++) {
            int row = i + kh - 1;
            bool rok = ((unsigned)row < 96u);
            const float* xr = xb + (size_t)ci*HW + row*WW;
#pragma unroll
            for (int kw = 0; kw < 3; kw++) {
                int col = j + kw - 1;
                float xv = (rok && (unsigned)col < 96u) ? xr[col] : 0.f;
                int wb = (ci*9 + kh*3 + kw)*9;
#pragma unroll
                for (int c = 0; c < 9; c++) acc[c] += ws[wb + c] * xv;
            }
        }
    }
#pragma unroll
    for (int c = 0; c < 9; c++)
        g_off[(size_t)((b*18 + cog*9 + c)*HH + i)*WW + j] = acc[c] + __ldg(&bias[cog*9 + c]);
}

// ------------------ deform path: bilinear gather + K=1152 GEMM + BN1/ReLU ---
__device__ __forceinline__ void deform_path(float* sm, int bx, int b,
                                            const float* __restrict__ bdef,
                                            const float* __restrict__ bn1) {
    float* s  = sm;            // [128][SP]
    float* ws = sm + CH*SP;    // [128][WP]
    int tid = threadIdx.x;
    int p0 = bx * 64;
    int warp = tid >> 5, lane = tid & 31;
    int ty = tid >> 4, tx = tid & 15;
    int cob = ty*8, pxb = tx*4;

    ACC_INIT
    const float* xnb = g_xn + (size_t)b*HW*CH;

    for (int n = 0; n < 9; n++) {
        __syncthreads();
        // stage weights [ci][co] for this tap
        for (int idx = tid*4; idx < 16384; idx += 1024) {
            float4 wv = *(const float4*)&g_wdT[n*16384 + idx];
            int ci = idx >> 7, co = idx & 127;
            *(float4*)&ws[ci*WP + co] = wv;
        }
        // stage bilinear samples: warp per pixel, lanes over channels
        float dnx = (float)(n/3 - 1), dny = (float)(n%3 - 1);
#pragma unroll
        for (int k = 0; k < 8; k++) {
            int px = warp*8 + k;
            int pix = p0 + px;
            int i = pix / 96, j = pix - i*96;
            float ox = __ldg(&g_off[(size_t)(b*18 + n    )*HW + pix]);
            float oy = __ldg(&g_off[(size_t)(b*18 + n + 9)*HW + pix]);
            float pfx = ox + dnx + (float)(i + 1);
            float pfy = oy + dny + (float)(j + 1);
            float qx = floorf(pfx), qy = floorf(pfy);
            float ltx = fminf(fmaxf(qx,       0.f), 97.f);
            float lty = fminf(fmaxf(qy,       0.f), 97.f);
            float rbx = fminf(fmaxf(qx + 1.f, 0.f), 97.f);
            float rby = fminf(fmaxf(qy + 1.f, 0.f), 97.f);
            float pcx = fminf(fmaxf(pfx, 0.f), 97.f);
            float pcy = fminf(fmaxf(pfy, 0.f), 97.f);
            float glt = (1.f + (ltx - pcx)) * (1.f + (lty - pcy));
            float grb = (1.f - (rbx - pcx)) * (1.f - (rby - pcy));
            float glb = (1.f + (ltx - pcx)) * (1.f - (rby - pcy));
            float grt = (1.f - (rbx - pcx)) * (1.f + (lty - pcy));
            int ax = (int)ltx - 1, ay = (int)lty - 1;
            int bx2 = (int)rbx - 1, by2 = (int)rby - 1;
            bool vax = ((unsigned)ax  < 96u), vay = ((unsigned)ay  < 96u);
            bool vbx = ((unsigned)bx2 < 96u), vby = ((unsigned)by2 < 96u);
            bool v_lt = vax && vay, v_rb = vbx && vby;
            bool v_lb = vax && vby, v_rt = vbx && vay;
            const float* plt = xnb + (size_t)(ax*96  + ay )*CH;
            const float* prb = xnb + (size_t)(bx2*96 + by2)*CH;
            const float* plb = xnb + (size_t)(ax*96  + by2)*CH;
            const float* prt = xnb + (size_t)(bx2*96 + ay )*CH;
#pragma unroll
            for (int it = 0; it < 4; it++) {
                int ci = it*32 + lane;
                float vv = 0.f;
                if (v_lt) vv += glt * plt[ci];
                if (v_rb) vv += grb * prb[ci];
                if (v_lb) vv += glb * plb[ci];
                if (v_rt) vv += grt * prt[ci];
                s[ci*SP + px] = vv;
            }
        }
        __syncthreads();
#pragma unroll 8
        for (int c = 0; c < CH; c++) {
            GSTEP(&s[c*SP + pxb], &ws[c*WP + cob])
        }
    }
    // epilogue: +bias, BN1, ReLU
#pragma unroll
    for (int k = 0; k < 4; k++) {
        float2 e0 = unp2(acc[0][k]), e1 = unp2(acc[1][k]);
        float2 e2 = unp2(acc[2][k]), e3 = unp2(acc[3][k]);
#pragma unroll
        for (int h = 0; h < 2; h++) {
            int co = cob + 2*k + h;
            float inv = __ldg(&bn1[co]) / sqrtf(__ldg(&bn1[384 + co]) + EPSBN);
            float add = __ldg(&bn1[128 + co]) - __ldg(&bn1[256 + co]) * inv;
            float bi  = __ldg(&bdef[co]);
            float4 o;
            if (h == 0) o = make_float4(e0.x, e1.x, e2.x, e3.x);
            else        o = make_float4(e0.y, e1.y, e2.y, e3.y);
            o.x = fmaxf((o.x + bi)*inv + add, 0.f);
            o.y = fmaxf((o.y + bi)*inv + add, 0.f);
            o.z = fmaxf((o.z + bi)*inv + add, 0.f);
            o.w = fmaxf((o.w + bi)*inv + add, 0.f);
            *(float4*)&g_x1[((size_t)b*CH + co)*HW + p0 + pxb] = o;
        }
    }
}

// ------------------ std path: 3x3 conv + BN2/ReLU + residual add ------------
__device__ __forceinline__ void std_path(float* sm, int bx, int b,
                                         const float* __restrict__ bstd,
                                         const float* __restrict__ bn2) {
    float* s  = sm;
    float* ws = sm + CH*SP;
    int tid = threadIdx.x;
    int p0 = bx * 64;
    int ty = tid >> 4, tx = tid & 15;
    int cob = ty*8, pxb = tx*4;

    ACC_INIT

    for (int n = 0; n < 9; n++) {
        __syncthreads();
        for (int idx = tid*4; idx < 16384; idx += 1024) {
            float4 wv = *(const float4*)&g_wsT[n*16384 + idx];
            int ci = idx >> 7, co = idx & 127;
            *(float4*)&ws[ci*WP + co] = wv;
        }
        int di = n/3 - 1, dj = n%3 - 1;
        for (int idx = tid; idx < 8192; idx += 256) {
            int ci = idx >> 6, px = idx & 63;
            int pix = p0 + px;
            int i = pix / 96, j = pix - i*96;
            int ii = i + di, jj = j + dj;
            float vv = ((unsigned)ii < 96u && (unsigned)jj < 96u)
                      ? g_xc[((size_t)b*CH + ci)*HW + ii*WW + jj] : 0.f;
            s[ci*SP + px] = vv;
        }
        __syncthreads();
#pragma unroll 8
        for (int c = 0; c < CH; c++) {
            GSTEP(&s[c*SP + pxb], &ws[c*WP + cob])
        }
    }
#pragma unroll
    for (int k = 0; k < 4; k++) {
        float2 e0 = unp2(acc[0][k]), e1 = unp2(acc[1][k]);
        float2 e2 = unp2(acc[2][k]), e3 = unp2(acc[3][k]);
#pragma unroll
        for (int h = 0; h < 2; h++) {
            int co = cob + 2*k + h;
            float inv = __ldg(&bn2[co]) / sqrtf(__ldg(&bn2[384 + co]) + EPSBN);
            float add = __ldg(&bn2[128 + co]) - __ldg(&bn2[256 + co]) * inv;
            float bi  = __ldg(&bstd[co]);
            float4 xc = *(float4*)&g_xc[((size_t)b*CH + co)*HW + p0 + pxb];
            float4 o;
            if (h == 0) o = make_float4(e0.x, e1.x, e2.x, e3.x);
            else        o = make_float4(e0.y, e1.y, e2.y, e3.y);
            o.x = fmaxf((o.x + bi)*inv + add, 0.f) + xc.x;
            o.y = fmaxf((o.y + bi)*inv + add, 0.f) + xc.y;
            o.z = fmaxf((o.z + bi)*inv + add, 0.f) + xc.z;
            o.w = fmaxf((o.w + bi)*inv + add, 0.f) + xc.w;
            *(float4*)&g_x2c[((size_t)b*CH + co)*HW + p0 + pxb] = o;
        }
    }
}

// ------------------ k_branches: fused deform + std (block-interleaved) ------
__global__ __launch_bounds__(256,2) void k_branches(const float* __restrict__ bdef,
                                                    const float* __restrict__ bn1,
                                                    const float* __restrict__ bstd,
                                                    const float* __restrict__ bn2) {
    extern __shared__ float sm[];
    int b = blockIdx.y;
    int bx = blockIdx.x >> 1;
    if (blockIdx.x & 1) std_path(sm, bx, b, bstd, bn2);
    else                deform_path(sm, bx, b, bdef, bn1);
}

// ------------------ k_out: final 1x1 conv 256->256 --------------------------
__global__ __launch_bounds__(256) void k_out(const float* __restrict__ w,
                                             const float* __restrict__ bias,
                                             float* __restrict__ out) {
    __shared__ float Ws[32*WP];
    __shared__ float Xs[32*SP];
    int tid = threadIdx.x;
    int b  = blockIdx.y;
    int z  = blockIdx.z;              // co half: 0 -> 0..127, 1 -> 128..255
    int p0 = blockIdx.x * 64;
    int ty = tid >> 4, tx = tid & 15;
    int cob = ty*8, pxb = tx*4;

    ACC_INIT

    for (int cb = 0; cb < 256; cb += 32) {
        __syncthreads();
        for (int idx = tid; idx < 4096; idx += 256) {
            int co = idx >> 5, c = idx & 31;
            Ws[c*WP + co] = w[(z*128 + co)*256 + cb + c];
        }
        const float* src = (cb < 128) ? g_x1 + ((size_t)b*CH + cb)*HW
                                      : g_x2c + ((size_t)b*CH + cb - 128)*HW;
        for (int idx = tid; idx < 2048; idx += 256) {
            int c = idx >> 6, p = idx & 63;
            Xs[c*SP + p] = src[(size_t)c*HW + p0 + p];
        }
        __syncthreads();
#pragma unroll 8
        for (int c = 0; c < 32; c++) {
            GSTEP(&Xs[c*SP + pxb], &Ws[c*WP + cob])
        }
    }
#pragma unroll
    for (int k = 0; k < 4; k++) {
        float2 e0 = unp2(acc[0][k]), e1 = unp2(acc[1][k]);
        float2 e2 = unp2(acc[2][k]), e3 = unp2(acc[3][k]);
#pragma unroll
        for (int h = 0; h < 2; h++) {
            int co = cob + 2*k + h;
            float bi = __ldg(&bias[z*128 + co]);
            float4 o;
            if (h == 0) o = make_float4(e0.x, e1.x, e2.x, e3.x);
            else        o = make_float4(e0.y, e1.y, e2.y, e3.y);
            o.x += bi; o.y += bi; o.z += bi; o.w += bi;
            *(float4*)&out[((size_t)(b*256 + z*128 + co))*HW + p0 + pxb] = o;
        }
    }
}

// ------------------ launch ---------------------------------------------------
extern "C" void kernel_launch(void* const* d_in, const int* in_sizes, int n_in,
                              void* d_out, int out_size) {
    const float* x     = (const float*)d_in[0];
    const float* w_in  = (const float*)d_in[1];
    const float* b_in  = (const float*)d_in[2];
    const float* w_off = (const float*)d_in[3];
    const float* b_off = (const float*)d_in[4];
    const float* w_def = (const float*)d_in[5];
    const float* b_def = (const float*)d_in[6];
    const float* bn1   = (const float*)d_in[7];
    const float* w_std = (const float*)d_in[8];
    const float* b_std = (const float*)d_in[9];
    const float* bn2   = (const float*)d_in[10];
    const float* w_out = (const float*)d_in[11];
    const float* b_out = (const float*)d_in[12];
    float* out = (float*)d_out;

    cudaFuncSetAttribute(k_branches, cudaFuncAttributeMaxDynamicSharedMemorySize, SMEM_DYN);

    k_prep    <<<576, 256>>>(w_def, w_std);
    k_conv_in <<<dim3(144, BATCH), 256>>>(x, w_in, b_in);
    k_off     <<<dim3(24, BATCH, 2), 384>>>(w_off, b_off);
    k_branches<<<dim3(288, BATCH), 256, SMEM_DYN>>>(b_def, bn1, b_std, bn2);
    k_out     <<<dim3(144, BATCH, 2), 256>>>(w_out, b_out, out);
}

// round 7
// speedup vs baseline: 1.5769x; 1.3428x over previous
#include <cuda_runtime.h>
#include <cuda_bf16.h>
#include <cstdint>

#define BATCH 4
#define CH 128
#define HH 96
#define WW 96
#define HW (HH*WW)
#define EPSBN 1e-5f
#define NTILES 72          // 9216 px / 128

#define WP 132

typedef unsigned long long u64;
typedef uint32_t u32;

// ===================== scalar fp32x2 helpers (conv_in) ======================
__device__ __forceinline__ void fma2(u64 &d, u64 a, u64 b) {
    asm("fma.rn.f32x2 %0, %1, %2, %0;" : "+l"(d) : "l"(a), "l"(b));
}
__device__ __forceinline__ u64 bc2(float x) {
    u64 r; asm("mov.b64 %0, {%1, %1};" : "=l"(r) : "f"(x)); return r;
}
__device__ __forceinline__ float2 unp2(u64 v) {
    float2 f; asm("mov.b64 {%0, %1}, %2;" : "=f"(f.x), "=f"(f.y) : "l"(v)); return f;
}
#define GSTEP(SROW, WROW) { \
    float4 xv = *(const float4*)(SROW); \
    ulonglong2 wA = *(const ulonglong2*)(WROW); \
    ulonglong2 wB = *(const ulonglong2*)((WROW)+4); \
    u64 xb0=bc2(xv.x), xb1=bc2(xv.y), xb2=bc2(xv.z), xb3=bc2(xv.w); \
    fma2(acc[0][0],wA.x,xb0); fma2(acc[0][1],wA.y,xb0); fma2(acc[0][2],wB.x,xb0); fma2(acc[0][3],wB.y,xb0); \
    fma2(acc[1][0],wA.x,xb1); fma2(acc[1][1],wA.y,xb1); fma2(acc[1][2],wB.x,xb1); fma2(acc[1][3],wB.y,xb1); \
    fma2(acc[2][0],wA.x,xb2); fma2(acc[2][1],wA.y,xb2); fma2(acc[2][2],wB.x,xb2); fma2(acc[2][3],wB.y,xb2); \
    fma2(acc[3][0],wA.x,xb3); fma2(acc[3][1],wA.y,xb3); fma2(acc[3][2],wB.x,xb3); fma2(acc[3][3],wB.y,xb3); }
#define ACC_INIT u64 acc[4][4]; _Pragma("unroll") for (int _i=0;_i<4;_i++) _Pragma("unroll") for(int _j=0;_j<4;_j++) acc[_i][_j]=0ull;

// ===================== mma.sync helpers =====================================
// swizzle: XOR 16B-granule index with row low-3-bits (rows are 256B)
#define SWZ(x) ((x) ^ ((((x) >> 8) & 7) << 4))

#define MMA_BF16(D, A, B0, B1) \
    asm volatile("mma.sync.aligned.m16n8k16.row.col.f32.bf16.bf16.f32 " \
        "{%0,%1,%2,%3}, {%4,%5,%6,%7}, {%8,%9}, {%0,%1,%2,%3};" \
        : "+f"((D)[0]), "+f"((D)[1]), "+f"((D)[2]), "+f"((D)[3]) \
        : "r"((A)[0]), "r"((A)[1]), "r"((A)[2]), "r"((A)[3]), "r"(B0), "r"(B1))

__device__ __forceinline__ void split2(float v, __nv_bfloat16 &h, __nv_bfloat16 &l) {
    h = __float2bfloat16(v);
    l = __float2bfloat16(v - __bfloat162float(h));
}

// smem layout for MMA kernels: four 32KB bf16 tiles (128 rows x 256B)
#define OFF_AH 0
#define OFF_AL 32768
#define OFF_BH 65536
#define OFF_BL 98304
#define SMEM_MM 131072

// ===================== scratch globals ======================================
__device__ float g_xc [BATCH*CH*HW];
__device__ float g_xn [BATCH*HW*CH];
__device__ float g_off[BATCH*18*HW];
__device__ __nv_bfloat16 g_wdH[9*16384], g_wdL[9*16384];
__device__ __nv_bfloat16 g_wsH[9*16384], g_wsL[9*16384];
__device__ __nv_bfloat16 g_woH[4*16384], g_woL[4*16384];
__device__ __nv_bfloat16 g_a1H[BATCH*NTILES*16384], g_a1L[BATCH*NTILES*16384];
__device__ __nv_bfloat16 g_a2H[BATCH*NTILES*16384], g_a2L[BATCH*NTILES*16384];

// ===================== k_prep: weight split + swizzled tiles ================
__global__ void k_prep(const float* __restrict__ wdef, const float* __restrict__ wstd,
                       const float* __restrict__ wout) {
    int idx = blockIdx.x * 256 + threadIdx.x;
    if (idx < 147456) {
        int n = idx / 16384, r = idx % 16384;
        int co = r >> 7, ci = r & 127;
        int off = SWZ(co*256 + ci*2);
        int dst = n*16384 + (off >> 1);
        int src = co*1152 + ci*9 + n;
        __nv_bfloat16 h, l;
        split2(wdef[src], h, l); g_wdH[dst] = h; g_wdL[dst] = l;
        split2(wstd[src], h, l); g_wsH[dst] = h; g_wsL[dst] = l;
    } else if (idx < 147456 + 65536) {
        int j = idx - 147456;
        int ci = j & 127, co = (j >> 7) & 127, kc = (j >> 14) & 1, z = (j >> 15) & 1;
        int off = SWZ(co*256 + ci*2);
        int dst = (z*2 + kc)*16384 + (off >> 1);
        __nv_bfloat16 h, l;
        split2(wout[(z*128 + co)*256 + kc*128 + ci], h, l);
        g_woH[dst] = h; g_woL[dst] = l;
    }
}

// ===================== k_conv_in: 1x1 conv -> NCHW + NHWC ===================
__global__ __launch_bounds__(256) void k_conv_in(const float* __restrict__ x,
                                                 const float* __restrict__ w,
                                                 const float* __restrict__ bias) {
    __shared__ float Ws[32*WP];
    __shared__ float Xs[32*64];
    int tid = threadIdx.x;
    int b  = blockIdx.y;
    int p0 = blockIdx.x * 64;
    int ty = tid >> 4, tx = tid & 15;
    int cob = ty*8, pxb = tx*4;

    ACC_INIT
    for (int cb = 0; cb < CH; cb += 32) {
        __syncthreads();
        for (int idx = tid; idx < 4096; idx += 256) {
            int co = idx >> 5, c = idx & 31;
            Ws[c*WP + co] = w[co*CH + cb + c];
        }
        for (int idx = tid; idx < 2048; idx += 256) {
            int c = idx >> 6, p = idx & 63;
            Xs[c*64 + p] = x[((size_t)b*CH + cb + c)*HW + p0 + p];
        }
        __syncthreads();
#pragma unroll 8
        for (int c = 0; c < 32; c++) { GSTEP(&Xs[c*64 + pxb], &Ws[c*WP + cob]) }
    }
    float v[4][8];
#pragma unroll
    for (int k = 0; k < 4; k++)
#pragma unroll
        for (int px = 0; px < 4; px++) {
            float2 f = unp2(acc[px][k]);
            v[px][2*k] = f.x; v[px][2*k+1] = f.y;
        }
    float bb[8];
#pragma unroll
    for (int u = 0; u < 8; u++) bb[u] = __ldg(&bias[cob + u]);
#pragma unroll
    for (int u = 0; u < 8; u++) {
        float4 o = make_float4(v[0][u]+bb[u], v[1][u]+bb[u], v[2][u]+bb[u], v[3][u]+bb[u]);
        *(float4*)&g_xc[((size_t)b*CH + cob + u)*HW + p0 + pxb] = o;
    }
#pragma unroll
    for (int px = 0; px < 4; px++) {
        float4 o0 = make_float4(v[px][0]+bb[0], v[px][1]+bb[1], v[px][2]+bb[2], v[px][3]+bb[3]);
        float4 o1 = make_float4(v[px][4]+bb[4], v[px][5]+bb[5], v[px][6]+bb[6], v[px][7]+bb[7]);
        float* np = g_xn + ((size_t)(b*HW) + p0 + pxb + px)*CH + cob;
        *(float4*)np = o0; *(float4*)(np+4) = o1;
    }
}

// ===================== k_off: 3x3 conv 128->18 ==============================
__global__ __launch_bounds__(384) void k_off(const float* __restrict__ w,
                                             const float* __restrict__ bias) {
    __shared__ float ws[1152*9];
    int tid = threadIdx.x;
    int b = blockIdx.y, cog = blockIdx.z;
    for (int idx = tid; idx < 10368; idx += 384) {
        int co = idx / 1152, cik = idx % 1152;
        ws[cik*9 + co] = w[(cog*9 + co)*1152 + cik];
    }
    __syncthreads();
    int i = blockIdx.x*4 + tid/96;
    int j = tid % 96;
    float acc[9];
#pragma unroll
    for (int c = 0; c < 9; c++) acc[c] = 0.f;
    const float* xb = g_xc + (size_t)b*CH*HW;
    for (int ci = 0; ci < CH; ci++) {
#pragma unroll
        for (int kh = 0; kh < 3; kh++) {
            int row = i + kh - 1;
            bool rok = ((unsigned)row < 96u);
            const float* xr = xb + (size_t)ci*HW + row*WW;
#pragma unroll
            for (int kw = 0; kw < 3; kw++) {
                int col = j + kw - 1;
                float xv = (rok && (unsigned)col < 96u) ? xr[col] : 0.f;
                int wb = (ci*9 + kh*3 + kw)*9;
#pragma unroll
                for (int c = 0; c < 9; c++) acc[c] += ws[wb + c] * xv;
            }
        }
    }
#pragma unroll
    for (int c = 0; c < 9; c++)
        g_off[(size_t)((b*18 + cog*9 + c)*HH + i)*WW + j] = acc[c] + __ldg(&bias[cog*9 + c]);
}

// ===================== MMA K=128 tap: warp computes 32x64 ===================
// pb = warp M base (0..96), cb = warp N base (0/64); g = lane>>2, t = lane&3
__device__ __forceinline__ void mma_tap(const char* smem, float acc[2][8][4],
                                        int pb, int cb, int g, int t) {
#pragma unroll
    for (int ks = 0; ks < 8; ks++) {
        int kb = ks*32 + t*4;
        u32 ah[2][4], al[2][4];
#pragma unroll
        for (int mt = 0; mt < 2; mt++) {
            int r0 = (pb + mt*16 + g)*256 + kb;
            int r1 = r0 + 8*256;
            int o0 = SWZ(r0), o1 = SWZ(r1), o2 = SWZ(r0 + 16), o3 = SWZ(r1 + 16);
            ah[mt][0] = *(const u32*)(smem + OFF_AH + o0);
            ah[mt][1] = *(const u32*)(smem + OFF_AH + o1);
            ah[mt][2] = *(const u32*)(smem + OFF_AH + o2);
            ah[mt][3] = *(const u32*)(smem + OFF_AH + o3);
            al[mt][0] = *(const u32*)(smem + OFF_AL + o0);
            al[mt][1] = *(const u32*)(smem + OFF_AL + o1);
            al[mt][2] = *(const u32*)(smem + OFF_AL + o2);
            al[mt][3] = *(const u32*)(smem + OFF_AL + o3);
        }
#pragma unroll
        for (int nt = 0; nt < 8; nt++) {
            int rb = (cb + nt*8 + g)*256 + kb;
            int ob0 = SWZ(rb), ob1 = SWZ(rb + 16);
            u32 bh0 = *(const u32*)(smem + OFF_BH + ob0);
            u32 bh1 = *(const u32*)(smem + OFF_BH + ob1);
            u32 bl0 = *(const u32*)(smem + OFF_BL + ob0);
            u32 bl1 = *(const u32*)(smem + OFF_BL + ob1);
#pragma unroll
            for (int mt = 0; mt < 2; mt++) {
                MMA_BF16(acc[mt][nt], ah[mt], bh0, bh1);
                MMA_BF16(acc[mt][nt], ah[mt], bl0, bl1);
                MMA_BF16(acc[mt][nt], al[mt], bh0, bh1);
            }
        }
    }
}

// ===================== k_tdef: deform branch (mma.sync) =====================
__global__ __launch_bounds__(256) void k_tdef(const float* __restrict__ bdef,
                                              const float* __restrict__ bn1) {
    extern __shared__ char smem[];
    int tid = threadIdx.x, wid = tid >> 5, lane = tid & 31;
    int g = lane >> 2, t = lane & 3;
    int wm = wid & 3, wn = wid >> 2;
    int pb = wm*32, cb = wn*64;
    int tile = blockIdx.x, b = blockIdx.y;
    int p0 = tile * 128;

    float acc[2][8][4];
#pragma unroll
    for (int i = 0; i < 2; i++)
#pragma unroll
        for (int j = 0; j < 8; j++)
#pragma unroll
            for (int k = 0; k < 4; k++) acc[i][j][k] = 0.f;

    const float* xnb = g_xn + (size_t)b*HW*CH;

    for (int n = 0; n < 9; n++) {
        __syncthreads();
        {   // stage weights (linear, pre-swizzled)
            const float4* shp = (const float4*)(g_wdH + n*16384);
            const float4* slp = (const float4*)(g_wdL + n*16384);
            float4* dh = (float4*)(smem + OFF_BH);
            float4* dl = (float4*)(smem + OFF_BL);
            for (int i2 = tid; i2 < 2048; i2 += 256) { dh[i2] = shp[i2]; dl[i2] = slp[i2]; }
        }
        float dnx = (float)(n/3 - 1), dny = (float)(n%3 - 1);
#pragma unroll 4
        for (int k = 0; k < 16; k++) {
            int px = wid*16 + k;
            int pix = p0 + px;
            int i = pix / 96, j = pix - i*96;
            float ox = __ldg(&g_off[(size_t)(b*18 + n    )*HW + pix]);
            float oy = __ldg(&g_off[(size_t)(b*18 + n + 9)*HW + pix]);
            float pfx = ox + dnx + (float)(i + 1);
            float pfy = oy + dny + (float)(j + 1);
            float qx = floorf(pfx), qy = floorf(pfy);
            float ltx = fminf(fmaxf(qx,       0.f), 97.f);
            float lty = fminf(fmaxf(qy,       0.f), 97.f);
            float rbx = fminf(fmaxf(qx + 1.f, 0.f), 97.f);
            float rby = fminf(fmaxf(qy + 1.f, 0.f), 97.f);
            float pcx = fminf(fmaxf(pfx, 0.f), 97.f);
            float pcy = fminf(fmaxf(pfy, 0.f), 97.f);
            float glt = (1.f + (ltx - pcx)) * (1.f + (lty - pcy));
            float grb = (1.f - (rbx - pcx)) * (1.f - (rby - pcy));
            float glb = (1.f + (ltx - pcx)) * (1.f - (rby - pcy));
            float grt = (1.f - (rbx - pcx)) * (1.f + (lty - pcy));
            int ax = (int)ltx - 1, ay = (int)lty - 1;
            int bx = (int)rbx - 1, by = (int)rby - 1;
            bool vax = ((unsigned)ax < 96u), vay = ((unsigned)ay < 96u);
            bool vbx = ((unsigned)bx < 96u), vby = ((unsigned)by < 96u);
            bool v_lt = vax && vay, v_rb = vbx && vby;
            bool v_lb = vax && vby, v_rt = vbx && vay;
            const float* plt = xnb + (size_t)(ax*96 + ay)*CH;
            const float* prb = xnb + (size_t)(bx*96 + by)*CH;
            const float* plb = xnb + (size_t)(ax*96 + by)*CH;
            const float* prt = xnb + (size_t)(bx*96 + ay)*CH;
#pragma unroll
            for (int it = 0; it < 2; it++) {
                int ci0 = it*64 + lane*2;
                float v0 = 0.f, v1 = 0.f;
                if (v_lt) { float2 tt = *(const float2*)(plt + ci0); v0 += glt*tt.x; v1 += glt*tt.y; }
                if (v_rb) { float2 tt = *(const float2*)(prb + ci0); v0 += grb*tt.x; v1 += grb*tt.y; }
                if (v_lb) { float2 tt = *(const float2*)(plb + ci0); v0 += glb*tt.x; v1 += glb*tt.y; }
                if (v_rt) { float2 tt = *(const float2*)(prt + ci0); v0 += grt*tt.x; v1 += grt*tt.y; }
                __nv_bfloat16 h0, l0, h1, l1;
                split2(v0, h0, l0); split2(v1, h1, l1);
                int off = SWZ(px*256 + ci0*2);
                __nv_bfloat162 hv; hv.x = h0; hv.y = h1;
                __nv_bfloat162 lv; lv.x = l0; lv.y = l1;
                *(__nv_bfloat162*)(smem + OFF_AH + off) = hv;
                *(__nv_bfloat162*)(smem + OFF_AL + off) = lv;
            }
        }
        __syncthreads();
        mma_tap(smem, acc, pb, cb, g, t);
    }
    // epilogue: +bias, BN1, ReLU -> bf16 split A-tile for k_tout
    char* oH = (char*)(g_a1H + (size_t)(b*NTILES + tile)*16384);
    char* oL = (char*)(g_a1L + (size_t)(b*NTILES + tile)*16384);
#pragma unroll
    for (int mt = 0; mt < 2; mt++)
#pragma unroll
        for (int nt = 0; nt < 8; nt++) {
            int row = pb + mt*16 + g;
            int co  = cb + nt*8 + 2*t;
            float i0 = __ldg(&bn1[co]) / sqrtf(__ldg(&bn1[384+co]) + EPSBN);
            float a0 = __ldg(&bn1[128+co]) - __ldg(&bn1[256+co]) * i0;
            float i1 = __ldg(&bn1[co+1]) / sqrtf(__ldg(&bn1[385+co]) + EPSBN);
            float a1 = __ldg(&bn1[129+co]) - __ldg(&bn1[257+co]) * i1;
            float b0v = __ldg(&bdef[co]), b1v = __ldg(&bdef[co+1]);
            const float* d = acc[mt][nt];
            float f00 = fmaxf((d[0] + b0v)*i0 + a0, 0.f);
            float f01 = fmaxf((d[1] + b1v)*i1 + a1, 0.f);
            float f10 = fmaxf((d[2] + b0v)*i0 + a0, 0.f);
            float f11 = fmaxf((d[3] + b1v)*i1 + a1, 0.f);
            __nv_bfloat16 h0,l0,h1,l1;
            split2(f00,h0,l0); split2(f01,h1,l1);
            int off = SWZ(row*256 + co*2);
            __nv_bfloat162 hv; hv.x=h0; hv.y=h1;
            __nv_bfloat162 lv; lv.x=l0; lv.y=l1;
            *(__nv_bfloat162*)(oH + off) = hv;
            *(__nv_bfloat162*)(oL + off) = lv;
            split2(f10,h0,l0); split2(f11,h1,l1);
            off = SWZ((row+8)*256 + co*2);
            hv.x=h0; hv.y=h1; lv.x=l0; lv.y=l1;
            *(__nv_bfloat162*)(oH + off) = hv;
            *(__nv_bfloat162*)(oL + off) = lv;
        }
}

// ===================== k_tstd: std 3x3 branch (mma.sync) ====================
__global__ __launch_bounds__(256) void k_tstd(const float* __restrict__ bstd,
                                              const float* __restrict__ bn2) {
    extern __shared__ char smem[];
    int tid = threadIdx.x, wid = tid >> 5, lane = tid & 31;
    int g = lane >> 2, t = lane & 3;
    int wm = wid & 3, wn = wid >> 2;
    int pb = wm*32, cb = wn*64;
    int tile = blockIdx.x, b = blockIdx.y;
    int p0 = tile * 128;

    float acc[2][8][4];
#pragma unroll
    for (int i = 0; i < 2; i++)
#pragma unroll
        for (int j = 0; j < 8; j++)
#pragma unroll
            for (int k = 0; k < 4; k++) acc[i][j][k] = 0.f;

    const float* xnb = g_xn + (size_t)b*HW*CH;

    for (int n = 0; n < 9; n++) {
        __syncthreads();
        {
            const float4* shp = (const float4*)(g_wsH + n*16384);
            const float4* slp = (const float4*)(g_wsL + n*16384);
            float4* dh = (float4*)(smem + OFF_BH);
            float4* dl = (float4*)(smem + OFF_BL);
            for (int i2 = tid; i2 < 2048; i2 += 256) { dh[i2] = shp[i2]; dl[i2] = slp[i2]; }
        }
        int di = n/3 - 1, dj = n%3 - 1;
#pragma unroll 4
        for (int k = 0; k < 16; k++) {
            int px = wid*16 + k;
            int pix = p0 + px;
            int i = pix / 96, j = pix - i*96;
            int ii = i + di, jj = j + dj;
            bool ok = ((unsigned)ii < 96u) && ((unsigned)jj < 96u);
            const float* src = xnb + (size_t)(ii*96 + jj)*CH;
#pragma unroll
            for (int it = 0; it < 2; it++) {
                int ci0 = it*64 + lane*2;
                float2 tt = ok ? *(const float2*)(src + ci0) : make_float2(0.f, 0.f);
                __nv_bfloat16 h0, l0, h1, l1;
                split2(tt.x, h0, l0); split2(tt.y, h1, l1);
                int off = SWZ(px*256 + ci0*2);
                __nv_bfloat162 hv; hv.x = h0; hv.y = h1;
                __nv_bfloat162 lv; lv.x = l0; lv.y = l1;
                *(__nv_bfloat162*)(smem + OFF_AH + off) = hv;
                *(__nv_bfloat162*)(smem + OFF_AL + off) = lv;
            }
        }
        __syncthreads();
        mma_tap(smem, acc, pb, cb, g, t);
    }
    char* oH = (char*)(g_a2H + (size_t)(b*NTILES + tile)*16384);
    char* oL = (char*)(g_a2L + (size_t)(b*NTILES + tile)*16384);
#pragma unroll
    for (int mt = 0; mt < 2; mt++)
#pragma unroll
        for (int nt = 0; nt < 8; nt++) {
            int row = pb + mt*16 + g;
            int co  = cb + nt*8 + 2*t;
            float i0 = __ldg(&bn2[co]) / sqrtf(__ldg(&bn2[384+co]) + EPSBN);
            float a0 = __ldg(&bn2[128+co]) - __ldg(&bn2[256+co]) * i0;
            float i1 = __ldg(&bn2[co+1]) / sqrtf(__ldg(&bn2[385+co]) + EPSBN);
            float a1 = __ldg(&bn2[129+co]) - __ldg(&bn2[257+co]) * i1;
            float b0v = __ldg(&bstd[co]), b1v = __ldg(&bstd[co+1]);
            const float* d = acc[mt][nt];
            float2 xc0 = *(const float2*)(xnb + (size_t)(p0 + row)*CH + co);
            float2 xc1 = *(const float2*)(xnb + (size_t)(p0 + row + 8)*CH + co);
            float f00 = fmaxf((d[0] + b0v)*i0 + a0, 0.f) + xc0.x;
            float f01 = fmaxf((d[1] + b1v)*i1 + a1, 0.f) + xc0.y;
            float f10 = fmaxf((d[2] + b0v)*i0 + a0, 0.f) + xc1.x;
            float f11 = fmaxf((d[3] + b1v)*i1 + a1, 0.f) + xc1.y;
            __nv_bfloat16 h0,l0,h1,l1;
            split2(f00,h0,l0); split2(f01,h1,l1);
            int off = SWZ(row*256 + co*2);
            __nv_bfloat162 hv; hv.x=h0; hv.y=h1;
            __nv_bfloat162 lv; lv.x=l0; lv.y=l1;
            *(__nv_bfloat162*)(oH + off) = hv;
            *(__nv_bfloat162*)(oL + off) = lv;
            split2(f10,h0,l0); split2(f11,h1,l1);
            off = SWZ((row+8)*256 + co*2);
            hv.x=h0; hv.y=h1; lv.x=l0; lv.y=l1;
            *(__nv_bfloat162*)(oH + off) = hv;
            *(__nv_bfloat162*)(oL + off) = lv;
        }
}

// ===================== k_tout: final 1x1 conv (mma.sync) ====================
__global__ __launch_bounds__(256) void k_tout(const float* __restrict__ bias,
                                              float* __restrict__ out) {
    extern __shared__ char smem[];
    int tid = threadIdx.x, wid = tid >> 5, lane = tid & 31;
    int g = lane >> 2, t = lane & 3;
    int wm = wid & 3, wn = wid >> 2;
    int pb = wm*32, cb = wn*64;
    int tile = blockIdx.x, b = blockIdx.y, z = blockIdx.z;
    int p0 = tile * 128;

    float acc[2][8][4];
#pragma unroll
    for (int i = 0; i < 2; i++)
#pragma unroll
        for (int j = 0; j < 8; j++)
#pragma unroll
            for (int k = 0; k < 4; k++) acc[i][j][k] = 0.f;

    for (int kc = 0; kc < 2; kc++) {
        __syncthreads();
        {
            const float4* wh = (const float4*)(g_woH + (z*2 + kc)*16384);
            const float4* wl = (const float4*)(g_woL + (z*2 + kc)*16384);
            const float4* ah = (const float4*)((kc ? g_a2H : g_a1H) + (size_t)(b*NTILES + tile)*16384);
            const float4* al = (const float4*)((kc ? g_a2L : g_a1L) + (size_t)(b*NTILES + tile)*16384);
            float4* dbh = (float4*)(smem + OFF_BH);
            float4* dbl = (float4*)(smem + OFF_BL);
            float4* dah = (float4*)(smem + OFF_AH);
            float4* dal = (float4*)(smem + OFF_AL);
            for (int i2 = tid; i2 < 2048; i2 += 256) {
                dbh[i2] = wh[i2]; dbl[i2] = wl[i2];
                dah[i2] = ah[i2]; dal[i2] = al[i2];
            }
        }
        __syncthreads();
        mma_tap(smem, acc, pb, cb, g, t);
    }
#pragma unroll
    for (int mt = 0; mt < 2; mt++)
#pragma unroll
        for (int nt = 0; nt < 8; nt++) {
            int row = p0 + pb + mt*16 + g;
            int co  = z*128 + cb + nt*8 + 2*t;
            float b0v = __ldg(&bias[co]), b1v = __ldg(&bias[co+1]);
            const float* d = acc[mt][nt];
            out[((size_t)(b*256 + co  ))*HW + row]     = d[0] + b0v;
            out[((size_t)(b*256 + co+1))*HW + row]     = d[1] + b1v;
            out[((size_t)(b*256 + co  ))*HW + row + 8] = d[2] + b0v;
            out[((size_t)(b*256 + co+1))*HW + row + 8] = d[3] + b1v;
        }
}

// ===================== launch ===============================================
extern "C" void kernel_launch(void* const* d_in, const int* in_sizes, int n_in,
                              void* d_out, int out_size) {
    const float* x     = (const float*)d_in[0];
    const float* w_in  = (const float*)d_in[1];
    const float* b_in  = (const float*)d_in[2];
    const float* w_off = (const float*)d_in[3];
    const float* b_off = (const float*)d_in[4];
    const float* w_def = (const float*)d_in[5];
    const float* b_def = (const float*)d_in[6];
    const float* bn1   = (const float*)d_in[7];
    const float* w_std = (const float*)d_in[8];
    const float* b_std = (const float*)d_in[9];
    const float* bn2   = (const float*)d_in[10];
    const float* w_out = (const float*)d_in[11];
    const float* b_out = (const float*)d_in[12];
    float* out = (float*)d_out;

    cudaFuncSetAttribute(k_tdef, cudaFuncAttributeMaxDynamicSharedMemorySize, SMEM_MM);
    cudaFuncSetAttribute(k_tstd, cudaFuncAttributeMaxDynamicSharedMemorySize, SMEM_MM);
    cudaFuncSetAttribute(k_tout, cudaFuncAttributeMaxDynamicSharedMemorySize, SMEM_MM);

    k_prep   <<<832, 256>>>(w_def, w_std, w_out);
    k_conv_in<<<dim3(144, BATCH), 256>>>(x, w_in, b_in);
    k_off    <<<dim3(24, BATCH, 2), 384>>>(w_off, b_off);
    k_tdef   <<<dim3(NTILES, BATCH), 256, SMEM_MM>>>(b_def, bn1);
    k_tstd   <<<dim3(NTILES, BATCH), 256, SMEM_MM>>>(b_std, bn2);
    k_tout   <<<dim3(NTILES, BATCH, 2), 256, SMEM_MM>>>(b_out, out);
}

// round 9
// speedup vs baseline: 1.7236x; 1.0931x over previous
#include <cuda_runtime.h>
#include <cuda_bf16.h>
#include <cstdint>

#define BATCH 4
#define CH 128
#define HH 96
#define WW 96
#define HW (HH*WW)
#define EPSBN 1e-5f
#define NTILES 72          // 9216 px / 128

#define WP 132
#define TMM 512            // threads per MMA kernel block

typedef unsigned long long u64;
typedef uint32_t u32;

// ===================== scalar fp32x2 helpers (conv_in) ======================
__device__ __forceinline__ void fma2(u64 &d, u64 a, u64 b) {
    asm("fma.rn.f32x2 %0, %1, %2, %0;" : "+l"(d) : "l"(a), "l"(b));
}
__device__ __forceinline__ u64 bc2(float x) {
    u64 r; asm("mov.b64 %0, {%1, %1};" : "=l"(r) : "f"(x)); return r;
}
__device__ __forceinline__ float2 unp2(u64 v) {
    float2 f; asm("mov.b64 {%0, %1}, %2;" : "=f"(f.x), "=f"(f.y) : "l"(v)); return f;
}
#define GSTEP(SROW, WROW) { \
    float4 xv = *(const float4*)(SROW); \
    ulonglong2 wA = *(const ulonglong2*)(WROW); \
    ulonglong2 wB = *(const ulonglong2*)((WROW)+4); \
    u64 xb0=bc2(xv.x), xb1=bc2(xv.y), xb2=bc2(xv.z), xb3=bc2(xv.w); \
    fma2(acc[0][0],wA.x,xb0); fma2(acc[0][1],wA.y,xb0); fma2(acc[0][2],wB.x,xb0); fma2(acc[0][3],wB.y,xb0); \
    fma2(acc[1][0],wA.x,xb1); fma2(acc[1][1],wA.y,xb1); fma2(acc[1][2],wB.x,xb1); fma2(acc[1][3],wB.y,xb1); \
    fma2(acc[2][0],wA.x,xb2); fma2(acc[2][1],wA.y,xb2); fma2(acc[2][2],wB.x,xb2); fma2(acc[2][3],wB.y,xb2); \
    fma2(acc[3][0],wA.x,xb3); fma2(acc[3][1],wA.y,xb3); fma2(acc[3][2],wB.x,xb3); fma2(acc[3][3],wB.y,xb3); }
#define ACC_INIT u64 acc[4][4]; _Pragma("unroll") for (int _i=0;_i<4;_i++) _Pragma("unroll") for(int _j=0;_j<4;_j++) acc[_i][_j]=0ull;

// ===================== mma.sync helpers =====================================
// swizzle: XOR 16B-granule index with row low-3-bits (rows are 256B)
#define SWZ(x) ((x) ^ ((((x) >> 8) & 7) << 4))

#define MMA_BF16(D, A, B0, B1) \
    asm volatile("mma.sync.aligned.m16n8k16.row.col.f32.bf16.bf16.f32 " \
        "{%0,%1,%2,%3}, {%4,%5,%6,%7}, {%8,%9}, {%0,%1,%2,%3};" \
        : "+f"((D)[0]), "+f"((D)[1]), "+f"((D)[2]), "+f"((D)[3]) \
        : "r"((A)[0]), "r"((A)[1]), "r"((A)[2]), "r"((A)[3]), "r"(B0), "r"(B1))

__device__ __forceinline__ void split2(float v, __nv_bfloat16 &h, __nv_bfloat16 &l) {
    h = __float2bfloat16(v);
    l = __float2bfloat16(v - __bfloat162float(h));
}

// smem layout for MMA kernels: four 32KB bf16 tiles (128 rows x 256B)
#define OFF_AH 0
#define OFF_AL 32768
#define OFF_BH 65536
#define OFF_BL 98304
#define SMEM_MM 131072

// ===================== scratch globals ======================================
__device__ float g_xc [BATCH*CH*HW];
__device__ float g_xn [BATCH*HW*CH];
__device__ float g_off[BATCH*18*HW];
__device__ __nv_bfloat16 g_wdH[9*16384], g_wdL[9*16384];
__device__ __nv_bfloat16 g_wsH[9*16384], g_wsL[9*16384];
__device__ __nv_bfloat16 g_woH[4*16384], g_woL[4*16384];
__device__ __nv_bfloat16 g_a1H[BATCH*NTILES*16384], g_a1L[BATCH*NTILES*16384];
__device__ __nv_bfloat16 g_a2H[BATCH*NTILES*16384], g_a2L[BATCH*NTILES*16384];

// ===================== k_prep: weight split + swizzled tiles ================
__global__ void k_prep(const float* __restrict__ wdef, const float* __restrict__ wstd,
                       const float* __restrict__ wout) {
    int idx = blockIdx.x * 256 + threadIdx.x;
    if (idx < 147456) {
        int n = idx / 16384, r = idx % 16384;
        int co = r >> 7, ci = r & 127;
        int off = SWZ(co*256 + ci*2);
        int dst = n*16384 + (off >> 1);
        int src = co*1152 + ci*9 + n;
        __nv_bfloat16 h, l;
        split2(wdef[src], h, l); g_wdH[dst] = h; g_wdL[dst] = l;
        split2(wstd[src], h, l); g_wsH[dst] = h; g_wsL[dst] = l;
    } else if (idx < 147456 + 65536) {
        int j = idx - 147456;
        int ci = j & 127, co = (j >> 7) & 127, kc = (j >> 14) & 1, z = (j >> 15) & 1;
        int off = SWZ(co*256 + ci*2);
        int dst = (z*2 + kc)*16384 + (off >> 1);
        __nv_bfloat16 h, l;
        split2(wout[(z*128 + co)*256 + kc*128 + ci], h, l);
        g_woH[dst] = h; g_woL[dst] = l;
    }
}

// ===================== k_conv_in: 1x1 conv -> NCHW + NHWC ===================
__global__ __launch_bounds__(256) void k_conv_in(const float* __restrict__ x,
                                                 const float* __restrict__ w,
                                                 const float* __restrict__ bias) {
    __shared__ float Ws[32*WP];
    __shared__ float Xs[32*64];
    int tid = threadIdx.x;
    int b  = blockIdx.y;
    int p0 = blockIdx.x * 64;
    int ty = tid >> 4, tx = tid & 15;
    int cob = ty*8, pxb = tx*4;

    ACC_INIT
    for (int cb = 0; cb < CH; cb += 32) {
        __syncthreads();
        for (int idx = tid; idx < 4096; idx += 256) {
            int co = idx >> 5, c = idx & 31;
            Ws[c*WP + co] = w[co*CH + cb + c];
        }
        for (int idx = tid; idx < 2048; idx += 256) {
            int c = idx >> 6, p = idx & 63;
            Xs[c*64 + p] = x[((size_t)b*CH + cb + c)*HW + p0 + p];
        }
        __syncthreads();
#pragma unroll 8
        for (int c = 0; c < 32; c++) { GSTEP(&Xs[c*64 + pxb], &Ws[c*WP + cob]) }
    }
    float v[4][8];
#pragma unroll
    for (int k = 0; k < 4; k++)
#pragma unroll
        for (int px = 0; px < 4; px++) {
            float2 f = unp2(acc[px][k]);
            v[px][2*k] = f.x; v[px][2*k+1] = f.y;
        }
    float bb[8];
#pragma unroll
    for (int u = 0; u < 8; u++) bb[u] = __ldg(&bias[cob + u]);
#pragma unroll
    for (int u = 0; u < 8; u++) {
        float4 o = make_float4(v[0][u]+bb[u], v[1][u]+bb[u], v[2][u]+bb[u], v[3][u]+bb[u]);
        *(float4*)&g_xc[((size_t)b*CH + cob + u)*HW + p0 + pxb] = o;
    }
#pragma unroll
    for (int px = 0; px < 4; px++) {
        float4 o0 = make_float4(v[px][0]+bb[0], v[px][1]+bb[1], v[px][2]+bb[2], v[px][3]+bb[3]);
        float4 o1 = make_float4(v[px][4]+bb[4], v[px][5]+bb[5], v[px][6]+bb[6], v[px][7]+bb[7]);
        float* np = g_xn + ((size_t)(b*HW) + p0 + pxb + px)*CH + cob;
        *(float4*)np = o0; *(float4*)(np+4) = o1;
    }
}

// ===================== k_off: 3x3 conv 128->18 ==============================
__global__ __launch_bounds__(384) void k_off(const float* __restrict__ w,
                                             const float* __restrict__ bias) {
    __shared__ float ws[1152*9];
    int tid = threadIdx.x;
    int b = blockIdx.y, cog = blockIdx.z;
    for (int idx = tid; idx < 10368; idx += 384) {
        int co = idx / 1152, cik = idx % 1152;
        ws[cik*9 + co] = w[(cog*9 + co)*1152 + cik];
    }
    __syncthreads();
    int i = blockIdx.x*4 + tid/96;
    int j = tid % 96;
    float acc[9];
#pragma unroll
    for (int c = 0; c < 9; c++) acc[c] = 0.f;
    const float* xb = g_xc + (size_t)b*CH*HW;
    for (int ci = 0; ci < CH; ci++) {
#pragma unroll
        for (int kh = 0; kh < 3; kh++) {
            int row = i + kh - 1;
            bool rok = ((unsigned)row < 96u);
            const float* xr = xb + (size_t)ci*HW + row*WW;
#pragma unroll
            for (int kw = 0; kw < 3; kw++) {
                int col = j + kw - 1;
                float xv = (rok && (unsigned)col < 96u) ? xr[col] : 0.f;
                int wb = (ci*9 + kh*3 + kw)*9;
#pragma unroll
                for (int c = 0; c < 9; c++) acc[c] += ws[wb + c] * xv;
            }
        }
    }
#pragma unroll
    for (int c = 0; c < 9; c++)
        g_off[(size_t)((b*18 + cog*9 + c)*HH + i)*WW + j] = acc[c] + __ldg(&bias[cog*9 + c]);
}

// ===================== MMA K=128 tap: warp computes 32x32 ===================
// pb = warp M base, cb = warp N base; g = lane>>2, t = lane&3
__device__ __forceinline__ void mma_tap(const char* smem, float acc[2][4][4],
                                        int pb, int cb, int g, int t) {
#pragma unroll
    for (int ks = 0; ks < 8; ks++) {
        int kb = ks*32 + t*4;
        u32 ah[2][4], al[2][4];
#pragma unroll
        for (int mt = 0; mt < 2; mt++) {
            int r0 = (pb + mt*16 + g)*256 + kb;
            int r1 = r0 + 8*256;
            int o0 = SWZ(r0), o1 = SWZ(r1), o2 = SWZ(r0 + 16), o3 = SWZ(r1 + 16);
            ah[mt][0] = *(const u32*)(smem + OFF_AH + o0);
            ah[mt][1] = *(const u32*)(smem + OFF_AH + o1);
            ah[mt][2] = *(const u32*)(smem + OFF_AH + o2);
            ah[mt][3] = *(const u32*)(smem + OFF_AH + o3);
            al[mt][0] = *(const u32*)(smem + OFF_AL + o0);
            al[mt][1] = *(const u32*)(smem + OFF_AL + o1);
            al[mt][2] = *(const u32*)(smem + OFF_AL + o2);
            al[mt][3] = *(const u32*)(smem + OFF_AL + o3);
        }
#pragma unroll
        for (int nt = 0; nt < 4; nt++) {
            int rb = (cb + nt*8 + g)*256 + kb;
            int ob0 = SWZ(rb), ob1 = SWZ(rb + 16);
            u32 bh0 = *(const u32*)(smem + OFF_BH + ob0);
            u32 bh1 = *(const u32*)(smem + OFF_BH + ob1);
            u32 bl0 = *(const u32*)(smem + OFF_BL + ob0);
            u32 bl1 = *(const u32*)(smem + OFF_BL + ob1);
#pragma unroll
            for (int mt = 0; mt < 2; mt++) {
                MMA_BF16(acc[mt][nt], ah[mt], bh0, bh1);
                MMA_BF16(acc[mt][nt], ah[mt], bl0, bl1);
                MMA_BF16(acc[mt][nt], al[mt], bh0, bh1);
            }
        }
    }
}

// ===================== k_tdef: deform branch (mma.sync) =====================
__global__ __launch_bounds__(TMM) void k_tdef(const float* __restrict__ bdef,
                                              const float* __restrict__ bn1) {
    extern __shared__ char smem[];
    int tid = threadIdx.x, wid = tid >> 5, lane = tid & 31;
    int g = lane >> 2, t = lane & 3;
    int wm = wid & 3, wn = wid >> 2;
    int pb = wm*32, cb = wn*32;
    int tile = blockIdx.x, b = blockIdx.y;
    int p0 = tile * 128;

    float acc[2][4][4];
#pragma unroll
    for (int i = 0; i < 2; i++)
#pragma unroll
        for (int j = 0; j < 4; j++)
#pragma unroll
            for (int k = 0; k < 4; k++) acc[i][j][k] = 0.f;

    const float* xnb = g_xn + (size_t)b*HW*CH;

    for (int n = 0; n < 9; n++) {
        __syncthreads();
        {   // stage weights (linear, pre-swizzled)
            const float4* shp = (const float4*)(g_wdH + n*16384);
            const float4* slp = (const float4*)(g_wdL + n*16384);
            float4* dh = (float4*)(smem + OFF_BH);
            float4* dl = (float4*)(smem + OFF_BL);
            for (int i2 = tid; i2 < 2048; i2 += TMM) { dh[i2] = shp[i2]; dl[i2] = slp[i2]; }
        }
        float dnx = (float)(n/3 - 1), dny = (float)(n%3 - 1);
#pragma unroll 4
        for (int k = 0; k < 8; k++) {
            int px = wid*8 + k;
            int pix = p0 + px;
            int i = pix / 96, j = pix - i*96;
            float ox = __ldg(&g_off[(size_t)(b*18 + n    )*HW + pix]);
            float oy = __ldg(&g_off[(size_t)(b*18 + n + 9)*HW + pix]);
            float pfx = ox + dnx + (float)(i + 1);
            float pfy = oy + dny + (float)(j + 1);
            float qx = floorf(pfx), qy = floorf(pfy);
            float ltx = fminf(fmaxf(qx,       0.f), 97.f);
            float lty = fminf(fmaxf(qy,       0.f), 97.f);
            float rbx = fminf(fmaxf(qx + 1.f, 0.f), 97.f);
            float rby = fminf(fmaxf(qy + 1.f, 0.f), 97.f);
            float pcx = fminf(fmaxf(pfx, 0.f), 97.f);
            float pcy = fminf(fmaxf(pfy, 0.f), 97.f);
            float glt = (1.f + (ltx - pcx)) * (1.f + (lty - pcy));
            float grb = (1.f - (rbx - pcx)) * (1.f - (rby - pcy));
            float glb = (1.f + (ltx - pcx)) * (1.f - (rby - pcy));
            float grt = (1.f - (rbx - pcx)) * (1.f + (lty - pcy));
            int ax = (int)ltx - 1, ay = (int)lty - 1;
            int bx = (int)rbx - 1, by = (int)rby - 1;
            bool vax = ((unsigned)ax < 96u), vay = ((unsigned)ay < 96u);
            bool vbx = ((unsigned)bx < 96u), vby = ((unsigned)by < 96u);
            bool v_lt = vax && vay, v_rb = vbx && vby;
            bool v_lb = vax && vby, v_rt = vbx && vay;
            const float* plt = xnb + (size_t)(ax*96 + ay)*CH;
            const float* prb = xnb + (size_t)(bx*96 + by)*CH;
            const float* plb = xnb + (size_t)(ax*96 + by)*CH;
            const float* prt = xnb + (size_t)(bx*96 + ay)*CH;
#pragma unroll
            for (int it = 0; it < 2; it++) {
                int ci0 = it*64 + lane*2;
                float v0 = 0.f, v1 = 0.f;
                if (v_lt) { float2 tt = *(const float2*)(plt + ci0); v0 += glt*tt.x; v1 += glt*tt.y; }
                if (v_rb) { float2 tt = *(const float2*)(prb + ci0); v0 += grb*tt.x; v1 += grb*tt.y; }
                if (v_lb) { float2 tt = *(const float2*)(plb + ci0); v0 += glb*tt.x; v1 += glb*tt.y; }
                if (v_rt) { float2 tt = *(const float2*)(prt + ci0); v0 += grt*tt.x; v1 += grt*tt.y; }
                __nv_bfloat16 h0, l0, h1, l1;
                split2(v0, h0, l0); split2(v1, h1, l1);
                int off = SWZ(px*256 + ci0*2);
                __nv_bfloat162 hv; hv.x = h0; hv.y = h1;
                __nv_bfloat162 lv; lv.x = l0; lv.y = l1;
                *(__nv_bfloat162*)(smem + OFF_AH + off) = hv;
                *(__nv_bfloat162*)(smem + OFF_AL + off) = lv;
            }
        }
        __syncthreads();
        mma_tap(smem, acc, pb, cb, g, t);
    }
    // epilogue: +bias, BN1, ReLU -> bf16 split A-tile for k_tout
    char* oH = (char*)(g_a1H + (size_t)(b*NTILES + tile)*16384);
    char* oL = (char*)(g_a1L + (size_t)(b*NTILES + tile)*16384);
#pragma unroll
    for (int mt = 0; mt < 2; mt++)
#pragma unroll
        for (int nt = 0; nt < 4; nt++) {
            int row = pb + mt*16 + g;
            int co  = cb + nt*8 + 2*t;
            float i0 = __ldg(&bn1[co]) / sqrtf(__ldg(&bn1[384+co]) + EPSBN);
            float a0 = __ldg(&bn1[128+co]) - __ldg(&bn1[256+co]) * i0;
            float i1 = __ldg(&bn1[co+1]) / sqrtf(__ldg(&bn1[385+co]) + EPSBN);
            float a1 = __ldg(&bn1[129+co]) - __ldg(&bn1[257+co]) * i1;
            float b0v = __ldg(&bdef[co]), b1v = __ldg(&bdef[co+1]);
            const float* d = acc[mt][nt];
            float f00 = fmaxf((d[0] + b0v)*i0 + a0, 0.f);
            float f01 = fmaxf((d[1] + b1v)*i1 + a1, 0.f);
            float f10 = fmaxf((d[2] + b0v)*i0 + a0, 0.f);
            float f11 = fmaxf((d[3] + b1v)*i1 + a1, 0.f);
            __nv_bfloat16 h0,l0,h1,l1;
            split2(f00,h0,l0); split2(f01,h1,l1);
            int off = SWZ(row*256 + co*2);
            __nv_bfloat162 hv; hv.x=h0; hv.y=h1;
            __nv_bfloat162 lv; lv.x=l0; lv.y=l1;
            *(__nv_bfloat162*)(oH + off) = hv;
            *(__nv_bfloat162*)(oL + off) = lv;
            split2(f10,h0,l0); split2(f11,h1,l1);
            off = SWZ((row+8)*256 + co*2);
            hv.x=h0; hv.y=h1; lv.x=l0; lv.y=l1;
            *(__nv_bfloat162*)(oH + off) = hv;
            *(__nv_bfloat162*)(oL + off) = lv;
        }
}

// ===================== k_tstd: std 3x3 branch (mma.sync) ====================
__global__ __launch_bounds__(TMM) void k_tstd(const float* __restrict__ bstd,
                                              const float* __restrict__ bn2) {
    extern __shared__ char smem[];
    int tid = threadIdx.x, wid = tid >> 5, lane = tid & 31;
    int g = lane >> 2, t = lane & 3;
    int wm = wid & 3, wn = wid >> 2;
    int pb = wm*32, cb = wn*32;
    int tile = blockIdx.x, b = blockIdx.y;
    int p0 = tile * 128;

    float acc[2][4][4];
#pragma unroll
    for (int i = 0; i < 2; i++)
#pragma unroll
        for (int j = 0; j < 4; j++)
#pragma unroll
            for (int k = 0; k < 4; k++) acc[i][j][k] = 0.f;

    const float* xnb = g_xn + (size_t)b*HW*CH;

    for (int n = 0; n < 9; n++) {
        __syncthreads();
        {
            const float4* shp = (const float4*)(g_wsH + n*16384);
            const float4* slp = (const float4*)(g_wsL + n*16384);
            float4* dh = (float4*)(smem + OFF_BH);
            float4* dl = (float4*)(smem + OFF_BL);
            for (int i2 = tid; i2 < 2048; i2 += TMM) { dh[i2] = shp[i2]; dl[i2] = slp[i2]; }
        }
        int di = n/3 - 1, dj = n%3 - 1;
#pragma unroll 4
        for (int k = 0; k < 8; k++) {
            int px = wid*8 + k;
            int pix = p0 + px;
            int i = pix / 96, j = pix - i*96;
            int ii = i + di, jj = j + dj;
            bool ok = ((unsigned)ii < 96u) && ((unsigned)jj < 96u);
            const float* src = xnb + (size_t)(ii*96 + jj)*CH;
#pragma unroll
            for (int it = 0; it < 2; it++) {
                int ci0 = it*64 + lane*2;
                float2 tt = ok ? *(const float2*)(src + ci0) : make_float2(0.f, 0.f);
                __nv_bfloat16 h0, l0, h1, l1;
                split2(tt.x, h0, l0); split2(tt.y, h1, l1);
                int off = SWZ(px*256 + ci0*2);
                __nv_bfloat162 hv; hv.x = h0; hv.y = h1;
                __nv_bfloat162 lv; lv.x = l0; lv.y = l1;
                *(__nv_bfloat162*)(smem + OFF_AH + off) = hv;
                *(__nv_bfloat162*)(smem + OFF_AL + off) = lv;
            }
        }
        __syncthreads();
        mma_tap(smem, acc, pb, cb, g, t);
    }
    char* oH = (char*)(g_a2H + (size_t)(b*NTILES + tile)*16384);
    char* oL = (char*)(g_a2L + (size_t)(b*NTILES + tile)*16384);
#pragma unroll
    for (int mt = 0; mt < 2; mt++)
#pragma unroll
        for (int nt = 0; nt < 4; nt++) {
            int row = pb + mt*16 + g;
            int co  = cb + nt*8 + 2*t;
            float i0 = __ldg(&bn2[co]) / sqrtf(__ldg(&bn2[384+co]) + EPSBN);
            float a0 = __ldg(&bn2[128+co]) - __ldg(&bn2[256+co]) * i0;
            float i1 = __ldg(&bn2[co+1]) / sqrtf(__ldg(&bn2[385+co]) + EPSBN);
            float a1 = __ldg(&bn2[129+co]) - __ldg(&bn2[257+co]) * i1;
            float b0v = __ldg(&bstd[co]), b1v = __ldg(&bstd[co+1]);
            const float* d = acc[mt][nt];
            float2 xc0 = *(const float2*)(xnb + (size_t)(p0 + row)*CH + co);
            float2 xc1 = *(const float2*)(xnb + (size_t)(p0 + row + 8)*CH + co);
            float f00 = fmaxf((d[0] + b0v)*i0 + a0, 0.f) + xc0.x;
            float f01 = fmaxf((d[1] + b1v)*i1 + a1, 0.f) + xc0.y;
            float f10 = fmaxf((d[2] + b0v)*i0 + a0, 0.f) + xc1.x;
            float f11 = fmaxf((d[3] + b1v)*i1 + a1, 0.f) + xc1.y;
            __nv_bfloat16 h0,l0,h1,l1;
            split2(f00,h0,l0); split2(f01,h1,l1);
            int off = SWZ(row*256 + co*2);
            __nv_bfloat162 hv; hv.x=h0; hv.y=h1;
            __nv_bfloat162 lv; lv.x=l0; lv.y=l1;
            *(__nv_bfloat162*)(oH + off) = hv;
            *(__nv_bfloat162*)(oL + off) = lv;
            split2(f10,h0,l0); split2(f11,h1,l1);
            off = SWZ((row+8)*256 + co*2);
            hv.x=h0; hv.y=h1; lv.x=l0; lv.y=l1;
            *(__nv_bfloat162*)(oH + off) = hv;
            *(__nv_bfloat162*)(oL + off) = lv;
        }
}

// ===================== k_tout: final 1x1 conv (mma.sync) ====================
__global__ __launch_bounds__(TMM) void k_tout(const float* __restrict__ bias,
                                              float* __restrict__ out) {
    extern __shared__ char smem[];
    int tid = threadIdx.x, wid = tid >> 5, lane = tid & 31;
    int g = lane >> 2, t = lane & 3;
    int wm = wid & 3, wn = wid >> 2;
    int pb = wm*32, cb = wn*32;
    int tile = blockIdx.x, b = blockIdx.y, z = blockIdx.z;
    int p0 = tile * 128;

    float acc[2][4][4];
#pragma unroll
    for (int i = 0; i < 2; i++)
#pragma unroll
        for (int j = 0; j < 4; j++)
#pragma unroll
            for (int k = 0; k < 4; k++) acc[i][j][k] = 0.f;

    for (int kc = 0; kc < 2; kc++) {
        __syncthreads();
        {
            const float4* wh = (const float4*)(g_woH + (z*2 + kc)*16384);
            const float4* wl = (const float4*)(g_woL + (z*2 + kc)*16384);
            const float4* ah = (const float4*)((kc ? g_a2H : g_a1H) + (size_t)(b*NTILES + tile)*16384);
            const float4* al = (const float4*)((kc ? g_a2L : g_a1L) + (size_t)(b*NTILES + tile)*16384);
            float4* dbh = (float4*)(smem + OFF_BH);
            float4* dbl = (float4*)(smem + OFF_BL);
            float4* dah = (float4*)(smem + OFF_AH);
            float4* dal = (float4*)(smem + OFF_AL);
            for (int i2 = tid; i2 < 2048; i2 += TMM) {
                dbh[i2] = wh[i2]; dbl[i2] = wl[i2];
                dah[i2] = ah[i2]; dal[i2] = al[i2];
            }
        }
        __syncthreads();
        mma_tap(smem, acc, pb, cb, g, t);
    }
#pragma unroll
    for (int mt = 0; mt < 2; mt++)
#pragma unroll
        for (int nt = 0; nt < 4; nt++) {
            int row = p0 + pb + mt*16 + g;
            int co  = z*128 + cb + nt*8 + 2*t;
            float b0v = __ldg(&bias[co]), b1v = __ldg(&bias[co+1]);
            const float* d = acc[mt][nt];
            out[((size_t)(b*256 + co  ))*HW + row]     = d[0] + b0v;
            out[((size_t)(b*256 + co+1))*HW + row]     = d[1] + b1v;
            out[((size_t)(b*256 + co  ))*HW + row + 8] = d[2] + b0v;
            out[((size_t)(b*256 + co+1))*HW + row + 8] = d[3] + b1v;
        }
}

// ===================== launch ===============================================
extern "C" void kernel_launch(void* const* d_in, const int* in_sizes, int n_in,
                              void* d_out, int out_size) {
    const float* x     = (const float*)d_in[0];
    const float* w_in  = (const float*)d_in[1];
    const float* b_in  = (const float*)d_in[2];
    const float* w_off = (const float*)d_in[3];
    const float* b_off = (const float*)d_in[4];
    const float* w_def = (const float*)d_in[5];
    const float* b_def = (const float*)d_in[6];
    const float* bn1   = (const float*)d_in[7];
    const float* w_std = (const float*)d_in[8];
    const float* b_std = (const float*)d_in[9];
    const float* bn2   = (const float*)d_in[10];
    const float* w_out = (const float*)d_in[11];
    const float* b_out = (const float*)d_in[12];
    float* out = (float*)d_out;

    cudaFuncSetAttribute(k_tdef, cudaFuncAttributeMaxDynamicSharedMemorySize, SMEM_MM);
    cudaFuncSetAttribute(k_tstd, cudaFuncAttributeMaxDynamicSharedMemorySize, SMEM_MM);
    cudaFuncSetAttribute(k_tout, cudaFuncAttributeMaxDynamicSharedMemorySize, SMEM_MM);

    k_prep   <<<832, 256>>>(w_def, w_std, w_out);
    k_conv_in<<<dim3(144, BATCH), 256>>>(x, w_in, b_in);
    k_off    <<<dim3(24, BATCH, 2), 384>>>(w_off, b_off);
    k_tdef   <<<dim3(NTILES, BATCH), TMM, SMEM_MM>>>(b_def, bn1);
    k_tstd   <<<dim3(NTILES, BATCH), TMM, SMEM_MM>>>(b_std, bn2);
    k_tout   <<<dim3(NTILES, BATCH, 2), TMM, SMEM_MM>>>(b_out, out);
}

// round 11
// speedup vs baseline: 1.8514x; 1.0742x over previous
#include <cuda_runtime.h>
#include <cuda_bf16.h>
#include <cstdint>

#define BATCH 4
#define CH 128
#define HH 96
#define WW 96
#define HW (HH*WW)
#define P98 9604           // 98*98 padded image
#define EPSBN 1e-5f
#define NTILES 72          // 9216 px / 128

#define WP 132
#define TMM 512            // threads per MMA kernel block

typedef unsigned long long u64;
typedef uint32_t u32;

// ===================== scalar fp32x2 helpers (conv_in) ======================
__device__ __forceinline__ void fma2(u64 &d, u64 a, u64 b) {
    asm("fma.rn.f32x2 %0, %1, %2, %0;" : "+l"(d) : "l"(a), "l"(b));
}
__device__ __forceinline__ u64 bc2(float x) {
    u64 r; asm("mov.b64 %0, {%1, %1};" : "=l"(r) : "f"(x)); return r;
}
__device__ __forceinline__ float2 unp2(u64 v) {
    float2 f; asm("mov.b64 {%0, %1}, %2;" : "=f"(f.x), "=f"(f.y) : "l"(v)); return f;
}
#define GSTEP(SROW, WROW) { \
    float4 xv = *(const float4*)(SROW); \
    ulonglong2 wA = *(const ulonglong2*)(WROW); \
    ulonglong2 wB = *(const ulonglong2*)((WROW)+4); \
    u64 xb0=bc2(xv.x), xb1=bc2(xv.y), xb2=bc2(xv.z), xb3=bc2(xv.w); \
    fma2(acc[0][0],wA.x,xb0); fma2(acc[0][1],wA.y,xb0); fma2(acc[0][2],wB.x,xb0); fma2(acc[0][3],wB.y,xb0); \
    fma2(acc[1][0],wA.x,xb1); fma2(acc[1][1],wA.y,xb1); fma2(acc[1][2],wB.x,xb1); fma2(acc[1][3],wB.y,xb1); \
    fma2(acc[2][0],wA.x,xb2); fma2(acc[2][1],wA.y,xb2); fma2(acc[2][2],wB.x,xb2); fma2(acc[2][3],wB.y,xb2); \
    fma2(acc[3][0],wA.x,xb3); fma2(acc[3][1],wA.y,xb3); fma2(acc[3][2],wB.x,xb3); fma2(acc[3][3],wB.y,xb3); }
#define ACC_INIT u64 acc[4][4]; _Pragma("unroll") for (int _i=0;_i<4;_i++) _Pragma("unroll") for(int _j=0;_j<4;_j++) acc[_i][_j]=0ull;

// ===================== mma.sync + cp.async helpers ==========================
#define SWZ(x) ((x) ^ ((((x) >> 8) & 7) << 4))

#define MMA_BF16(D, A, B0, B1) \
    asm volatile("mma.sync.aligned.m16n8k16.row.col.f32.bf16.bf16.f32 " \
        "{%0,%1,%2,%3}, {%4,%5,%6,%7}, {%8,%9}, {%0,%1,%2,%3};" \
        : "+f"((D)[0]), "+f"((D)[1]), "+f"((D)[2]), "+f"((D)[3]) \
        : "r"((A)[0]), "r"((A)[1]), "r"((A)[2]), "r"((A)[3]), "r"(B0), "r"(B1))

#define CP16(d, s)  asm volatile("cp.async.cg.shared.global [%0], [%1], 16;" :: "r"(d), "l"(s) : "memory")
#define CP_COMMIT() asm volatile("cp.async.commit_group;" ::: "memory")
#define CP_WAIT0()  asm volatile("cp.async.wait_group 0;" ::: "memory")
#define CP_WAIT1()  asm volatile("cp.async.wait_group 1;" ::: "memory")

__device__ __forceinline__ u32 smem_to_u32(const void* p) {
    u32 a;
    asm("{ .reg .u64 t; cvta.to.shared.u64 t, %1; cvt.u32.u64 %0, t; }" : "=r"(a) : "l"(p));
    return a;
}
__device__ __forceinline__ void split2(float v, __nv_bfloat16 &h, __nv_bfloat16 &l) {
    h = __float2bfloat16(v);
    l = __float2bfloat16(v - __bfloat162float(h));
}

// smem layout: A (hi 32K + lo 32K) @0; B stages (hi+lo 64K each) @65536, @131072
#define OFF_A   0
#define OFF_B   65536
#define STAGE   65536
#define SMEM_T2 196608     // tdef/tstd
#define SMEM_TO 131072     // tout (A + single B stage)

// ===================== scratch globals ======================================
__device__ float g_xc [BATCH*CH*HW];            // x_c NCHW (for k_off)
__device__ float g_xp [BATCH*P98*CH];           // x_c padded NHWC fp32
__device__ __nv_bfloat16 g_xpH[BATCH*P98*CH];   // padded NHWC bf16 hi
__device__ __nv_bfloat16 g_xpL[BATCH*P98*CH];   // padded NHWC bf16 lo
__device__ float g_off[BATCH*18*HW];
__device__ __nv_bfloat16 g_wdH[9*16384], g_wdL[9*16384];
__device__ __nv_bfloat16 g_wsH[9*16384], g_wsL[9*16384];
__device__ __nv_bfloat16 g_woH[4*16384], g_woL[4*16384];
__device__ __nv_bfloat16 g_a1H[BATCH*NTILES*16384], g_a1L[BATCH*NTILES*16384];
__device__ __nv_bfloat16 g_a2H[BATCH*NTILES*16384], g_a2L[BATCH*NTILES*16384];

// ===================== k_zero: clear padded buffers =========================
__global__ void k_zero() {
    size_t idx = (size_t)blockIdx.x*256 + threadIdx.x;
    size_t stride = (size_t)gridDim.x*256;
    for (size_t i = idx; i < (size_t)BATCH*P98*CH/4; i += stride)
        ((float4*)g_xp)[i] = make_float4(0.f,0.f,0.f,0.f);
    for (size_t i = idx; i < (size_t)BATCH*P98*CH/8; i += stride) {
        ((uint4*)g_xpH)[i] = make_uint4(0,0,0,0);
        ((uint4*)g_xpL)[i] = make_uint4(0,0,0,0);
    }
}

// ===================== k_prep: weight split + swizzled tiles ================
__global__ void k_prep(const float* __restrict__ wdef, const float* __restrict__ wstd,
                       const float* __restrict__ wout) {
    int idx = blockIdx.x * 256 + threadIdx.x;
    if (idx < 147456) {
        int n = idx / 16384, r = idx % 16384;
        int co = r >> 7, ci = r & 127;
        int off = SWZ(co*256 + ci*2);
        int dst = n*16384 + (off >> 1);
        int src = co*1152 + ci*9 + n;
        __nv_bfloat16 h, l;
        split2(wdef[src], h, l); g_wdH[dst] = h; g_wdL[dst] = l;
        split2(wstd[src], h, l); g_wsH[dst] = h; g_wsL[dst] = l;
    } else if (idx < 147456 + 65536) {
        int j = idx - 147456;
        int ci = j & 127, co = (j >> 7) & 127, kc = (j >> 14) & 1, z = (j >> 15) & 1;
        int off = SWZ(co*256 + ci*2);
        int dst = (z*2 + kc)*16384 + (off >> 1);
        __nv_bfloat16 h, l;
        split2(wout[(z*128 + co)*256 + kc*128 + ci], h, l);
        g_woH[dst] = h; g_woL[dst] = l;
    }
}

// ===================== k_conv_in: 1x1 conv -> NCHW + padded NHWC ============
__global__ __launch_bounds__(256) void k_conv_in(const float* __restrict__ x,
                                                 const float* __restrict__ w,
                                                 const float* __restrict__ bias) {
    __shared__ float Ws[32*WP];
    __shared__ float Xs[32*64];
    int tid = threadIdx.x;
    int b  = blockIdx.y;
    int p0 = blockIdx.x * 64;
    int ty = tid >> 4, tx = tid & 15;
    int cob = ty*8, pxb = tx*4;

    ACC_INIT
    for (int cb = 0; cb < CH; cb += 32) {
        __syncthreads();
        for (int idx = tid; idx < 4096; idx += 256) {
            int co = idx >> 5, c = idx & 31;
            Ws[c*WP + co] = w[co*CH + cb + c];
        }
        for (int idx = tid; idx < 2048; idx += 256) {
            int c = idx >> 6, p = idx & 63;
            Xs[c*64 + p] = x[((size_t)b*CH + cb + c)*HW + p0 + p];
        }
        __syncthreads();
#pragma unroll 8
        for (int c = 0; c < 32; c++) { GSTEP(&Xs[c*64 + pxb], &Ws[c*WP + cob]) }
    }
    float v[4][8];
#pragma unroll
    for (int k = 0; k < 4; k++)
#pragma unroll
        for (int px = 0; px < 4; px++) {
            float2 f = unp2(acc[px][k]);
            v[px][2*k] = f.x; v[px][2*k+1] = f.y;
        }
    float bb[8];
#pragma unroll
    for (int u = 0; u < 8; u++) bb[u] = __ldg(&bias[cob + u]);
#pragma unroll
    for (int u = 0; u < 8; u++) {
        float4 o = make_float4(v[0][u]+bb[u], v[1][u]+bb[u], v[2][u]+bb[u], v[3][u]+bb[u]);
        *(float4*)&g_xc[((size_t)b*CH + cob + u)*HW + p0 + pxb] = o;
    }
#pragma unroll
    for (int px = 0; px < 4; px++) {
        int pix = p0 + pxb + px;
        int i = pix / 96, j = pix - i*96;
        size_t pbase = ((size_t)b*P98 + (i+1)*98 + (j+1))*CH + cob;
        float fv[8];
#pragma unroll
        for (int u = 0; u < 8; u++) fv[u] = v[px][u] + bb[u];
        *(float4*)&g_xp[pbase]   = make_float4(fv[0], fv[1], fv[2], fv[3]);
        *(float4*)&g_xp[pbase+4] = make_float4(fv[4], fv[5], fv[6], fv[7]);
        __nv_bfloat162 hv[4], lv[4];
#pragma unroll
        for (int u = 0; u < 4; u++) {
            __nv_bfloat16 h0,l0,h1,l1;
            split2(fv[2*u], h0, l0); split2(fv[2*u+1], h1, l1);
            hv[u].x = h0; hv[u].y = h1; lv[u].x = l0; lv[u].y = l1;
        }
        *(uint4*)&g_xpH[pbase] = *(uint4*)hv;
        *(uint4*)&g_xpL[pbase] = *(uint4*)lv;
    }
}

// ===================== k_off: 3x3 conv 128->18 ==============================
__global__ __launch_bounds__(384) void k_off(const float* __restrict__ w,
                                             const float* __restrict__ bias) {
    __shared__ float ws[1152*9];
    int tid = threadIdx.x;
    int b = blockIdx.y, cog = blockIdx.z;
    for (int idx = tid; idx < 10368; idx += 384) {
        int co = idx / 1152, cik = idx % 1152;
        ws[cik*9 + co] = w[(cog*9 + co)*1152 + cik];
    }
    __syncthreads();
    int i = blockIdx.x*4 + tid/96;
    int j = tid % 96;
    float acc[9];
#pragma unroll
    for (int c = 0; c < 9; c++) acc[c] = 0.f;
    const float* xb = g_xc + (size_t)b*CH*HW;
    for (int ci = 0; ci < CH; ci++) {
#pragma unroll
        for (int kh = 0; kh < 3; kh++) {
            int row = i + kh - 1;
            bool rok = ((unsigned)row < 96u);
            const float* xr = xb + (size_t)ci*HW + row*WW;
#pragma unroll
            for (int kw = 0; kw < 3; kw++) {
                int col = j + kw - 1;
                float xv = (rok && (unsigned)col < 96u) ? xr[col] : 0.f;
                int wb = (ci*9 + kh*3 + kw)*9;
#pragma unroll
                for (int c = 0; c < 9; c++) acc[c] += ws[wb + c] * xv;
            }
        }
    }
#pragma unroll
    for (int c = 0; c < 9; c++)
        g_off[(size_t)((b*18 + cog*9 + c)*HH + i)*WW + j] = acc[c] + __ldg(&bias[cog*9 + c]);
}

// ===================== MMA K=128 tap: warp computes 32x32 ===================
__device__ __forceinline__ void mma_tap(const char* sA, const char* sB, float acc[2][4][4],
                                        int pb, int cb, int g, int t) {
#pragma unroll
    for (int ks = 0; ks < 8; ks++) {
        int kb = ks*32 + t*4;
        u32 ah[2][4], al[2][4];
#pragma unroll
        for (int mt = 0; mt < 2; mt++) {
            int r0 = (pb + mt*16 + g)*256 + kb;
            int r1 = r0 + 8*256;
            int o0 = SWZ(r0), o1 = SWZ(r1), o2 = SWZ(r0 + 16), o3 = SWZ(r1 + 16);
            ah[mt][0] = *(const u32*)(sA + o0);
            ah[mt][1] = *(const u32*)(sA + o1);
            ah[mt][2] = *(const u32*)(sA + o2);
            ah[mt][3] = *(const u32*)(sA + o3);
            al[mt][0] = *(const u32*)(sA + 32768 + o0);
            al[mt][1] = *(const u32*)(sA + 32768 + o1);
            al[mt][2] = *(const u32*)(sA + 32768 + o2);
            al[mt][3] = *(const u32*)(sA + 32768 + o3);
        }
#pragma unroll
        for (int nt = 0; nt < 4; nt++) {
            int rb = (cb + nt*8 + g)*256 + kb;
            int ob0 = SWZ(rb), ob1 = SWZ(rb + 16);
            u32 bh0 = *(const u32*)(sB + ob0);
            u32 bh1 = *(const u32*)(sB + ob1);
            u32 bl0 = *(const u32*)(sB + 32768 + ob0);
            u32 bl1 = *(const u32*)(sB + 32768 + ob1);
#pragma unroll
            for (int mt = 0; mt < 2; mt++) {
                MMA_BF16(acc[mt][nt], ah[mt], bh0, bh1);
                MMA_BF16(acc[mt][nt], ah[mt], bl0, bl1);
                MMA_BF16(acc[mt][nt], al[mt], bh0, bh1);
            }
        }
    }
}

// weight cp.async stage: 4096 x 16B granules (hi+lo), identity mapping
__device__ __forceinline__ void stage_B(u32 dstu, const __nv_bfloat16* srcH,
                                        const __nv_bfloat16* srcL, int tid) {
    const char* sh = (const char*)srcH;
    const char* sl = (const char*)srcL;
    for (int i2 = tid; i2 < 2048; i2 += TMM) {
        CP16(dstu + i2*16,         sh + i2*16);
        CP16(dstu + 32768 + i2*16, sl + i2*16);
    }
}

// ===================== k_tdef: deform branch ================================
__global__ __launch_bounds__(TMM) void k_tdef(const float* __restrict__ bdef,
                                              const float* __restrict__ bn1) {
    extern __shared__ char smem[];
    u32 sb = smem_to_u32(smem);
    int tid = threadIdx.x, wid = tid >> 5, lane = tid & 31;
    int g = lane >> 2, t = lane & 3;
    int wm = wid & 3, wn = wid >> 2;
    int pb = wm*32, cb = wn*32;
    int tile = blockIdx.x, b = blockIdx.y;
    int p0 = tile * 128;

    float acc[2][4][4];
#pragma unroll
    for (int i = 0; i < 2; i++)
#pragma unroll
        for (int j = 0; j < 4; j++)
#pragma unroll
            for (int k = 0; k < 4; k++) acc[i][j][k] = 0.f;

    const float* xpb = g_xp + (size_t)b*P98*CH;

    // prologue: prefetch weights for tap 0
    stage_B(sb + OFF_B, g_wdH, g_wdL, tid);
    CP_COMMIT();

    for (int n = 0; n < 9; n++) {
        __syncthreads();
        if (n < 8) {
            stage_B(sb + OFF_B + ((n+1)&1)*STAGE, g_wdH + (n+1)*16384, g_wdL + (n+1)*16384, tid);
            CP_COMMIT();
        }
        // gather bilinear samples (padded buffer -> no predicates)
        float dnx = (float)(n/3 - 1), dny = (float)(n%3 - 1);
#pragma unroll 4
        for (int k = 0; k < 8; k++) {
            int px = wid*8 + k;
            int pix = p0 + px;
            int i = pix / 96, j = pix - i*96;
            float ox = __ldg(&g_off[(size_t)(b*18 + n    )*HW + pix]);
            float oy = __ldg(&g_off[(size_t)(b*18 + n + 9)*HW + pix]);
            float pfx = ox + dnx + (float)(i + 1);
            float pfy = oy + dny + (float)(j + 1);
            float qx = floorf(pfx), qy = floorf(pfy);
            float ltx = fminf(fmaxf(qx,       0.f), 97.f);
            float lty = fminf(fmaxf(qy,       0.f), 97.f);
            float rbx = fminf(fmaxf(qx + 1.f, 0.f), 97.f);
            float rby = fminf(fmaxf(qy + 1.f, 0.f), 97.f);
            float pcx = fminf(fmaxf(pfx, 0.f), 97.f);
            float pcy = fminf(fmaxf(pfy, 0.f), 97.f);
            float glt = (1.f + (ltx - pcx)) * (1.f + (lty - pcy));
            float grb = (1.f - (rbx - pcx)) * (1.f - (rby - pcy));
            float glb = (1.f + (ltx - pcx)) * (1.f - (rby - pcy));
            float grt = (1.f - (rbx - pcx)) * (1.f + (lty - pcy));
            int ix0 = (int)ltx, iy0 = (int)lty, ix1 = (int)rbx, iy1 = (int)rby;
            const float* plt = xpb + (size_t)(ix0*98 + iy0)*CH;
            const float* prb = xpb + (size_t)(ix1*98 + iy1)*CH;
            const float* plb = xpb + (size_t)(ix0*98 + iy1)*CH;
            const float* prt = xpb + (size_t)(ix1*98 + iy0)*CH;
#pragma unroll
            for (int it = 0; it < 2; it++) {
                int ci0 = it*64 + lane*2;
                float2 a2 = *(const float2*)(plt + ci0);
                float2 b2 = *(const float2*)(prb + ci0);
                float2 c2 = *(const float2*)(plb + ci0);
                float2 d2 = *(const float2*)(prt + ci0);
                float v0 = glt*a2.x + grb*b2.x + glb*c2.x + grt*d2.x;
                float v1 = glt*a2.y + grb*b2.y + glb*c2.y + grt*d2.y;
                __nv_bfloat16 h0, l0, h1, l1;
                split2(v0, h0, l0); split2(v1, h1, l1);
                int off = SWZ(px*256 + ci0*2);
                __nv_bfloat162 hv; hv.x = h0; hv.y = h1;
                __nv_bfloat162 lv; lv.x = l0; lv.y = l1;
                *(__nv_bfloat162*)(smem + OFF_A + off) = hv;
                *(__nv_bfloat162*)(smem + OFF_A + 32768 + off) = lv;
            }
        }
        if (n < 8) { CP_WAIT1(); } else { CP_WAIT0(); }
        __syncthreads();
        mma_tap(smem + OFF_A, smem + OFF_B + (n&1)*STAGE, acc, pb, cb, g, t);
    }
    // epilogue: +bias, BN1, ReLU -> bf16 split A-tile for k_tout
    char* oH = (char*)(g_a1H + (size_t)(b*NTILES + tile)*16384);
    char* oL = (char*)(g_a1L + (size_t)(b*NTILES + tile)*16384);
#pragma unroll
    for (int mt = 0; mt < 2; mt++)
#pragma unroll
        for (int nt = 0; nt < 4; nt++) {
            int row = pb + mt*16 + g;
            int co  = cb + nt*8 + 2*t;
            float i0 = __ldg(&bn1[co]) / sqrtf(__ldg(&bn1[384+co]) + EPSBN);
            float a0 = __ldg(&bn1[128+co]) - __ldg(&bn1[256+co]) * i0;
            float i1 = __ldg(&bn1[co+1]) / sqrtf(__ldg(&bn1[385+co]) + EPSBN);
            float a1 = __ldg(&bn1[129+co]) - __ldg(&bn1[257+co]) * i1;
            float b0v = __ldg(&bdef[co]), b1v = __ldg(&bdef[co+1]);
            const float* d = acc[mt][nt];
            float f00 = fmaxf((d[0] + b0v)*i0 + a0, 0.f);
            float f01 = fmaxf((d[1] + b1v)*i1 + a1, 0.f);
            float f10 = fmaxf((d[2] + b0v)*i0 + a0, 0.f);
            float f11 = fmaxf((d[3] + b1v)*i1 + a1, 0.f);
            __nv_bfloat16 h0,l0,h1,l1;
            split2(f00,h0,l0); split2(f01,h1,l1);
            int off = SWZ(row*256 + co*2);
            __nv_bfloat162 hv; hv.x=h0; hv.y=h1;
            __nv_bfloat162 lv; lv.x=l0; lv.y=l1;
            *(__nv_bfloat162*)(oH + off) = hv;
            *(__nv_bfloat162*)(oL + off) = lv;
            split2(f10,h0,l0); split2(f11,h1,l1);
            off = SWZ((row+8)*256 + co*2);
            hv.x=h0; hv.y=h1; lv.x=l0; lv.y=l1;
            *(__nv_bfloat162*)(oH + off) = hv;
            *(__nv_bfloat162*)(oL + off) = lv;
        }
}

// ===================== k_tstd: std 3x3 branch ===============================
__global__ __launch_bounds__(TMM) void k_tstd(const float* __restrict__ bstd,
                                              const float* __restrict__ bn2) {
    extern __shared__ char smem[];
    u32 sb = smem_to_u32(smem);
    int tid = threadIdx.x, wid = tid >> 5, lane = tid & 31;
    int g = lane >> 2, t = lane & 3;
    int wm = wid & 3, wn = wid >> 2;
    int pb = wm*32, cb = wn*32;
    int tile = blockIdx.x, b = blockIdx.y;
    int p0 = tile * 128;

    float acc[2][4][4];
#pragma unroll
    for (int i = 0; i < 2; i++)
#pragma unroll
        for (int j = 0; j < 4; j++)
#pragma unroll
            for (int k = 0; k < 4; k++) acc[i][j][k] = 0.f;

    stage_B(sb + OFF_B, g_wsH, g_wsL, tid);
    CP_COMMIT();

    for (int n = 0; n < 9; n++) {
        __syncthreads();
        int di = n/3 - 1, dj = n%3 - 1;
        // A tile: pure cp.async copies from pre-split padded bf16 (zero pad free)
        {
            const char* sh = (const char*)(g_xpH + (size_t)b*P98*CH);
            const char* sl = (const char*)(g_xpL + (size_t)b*P98*CH);
            for (int idx = tid; idx < 2048; idx += TMM) {
                int px = idx >> 4, g16 = idx & 15;
                int pix = p0 + px;
                int i = pix / 96, j = pix - i*96;
                size_t src = ((size_t)((i+1+di)*98 + (j+1+dj))*CH)*2 + g16*16;
                u32 dst = sb + OFF_A + SWZ(px*256 + g16*16);
                CP16(dst, sh + src);
                CP16(dst + 32768, sl + src);
            }
            CP_COMMIT();
        }
        if (n < 8) {
            stage_B(sb + OFF_B + ((n+1)&1)*STAGE, g_wsH + (n+1)*16384, g_wsL + (n+1)*16384, tid);
            CP_COMMIT();
        }
        if (n < 8) { CP_WAIT1(); } else { CP_WAIT0(); }   // A(n)+B(n) done
        __syncthreads();
        mma_tap(smem + OFF_A, smem + OFF_B + (n&1)*STAGE, acc, pb, cb, g, t);
    }
    const float* xpb = g_xp + (size_t)b*P98*CH;
    char* oH = (char*)(g_a2H + (size_t)(b*NTILES + tile)*16384);
    char* oL = (char*)(g_a2L + (size_t)(b*NTILES + tile)*16384);
#pragma unroll
    for (int mt = 0; mt < 2; mt++)
#pragma unroll
        for (int nt = 0; nt < 4; nt++) {
            int row = pb + mt*16 + g;
            int co  = cb + nt*8 + 2*t;
            float i0 = __ldg(&bn2[co]) / sqrtf(__ldg(&bn2[384+co]) + EPSBN);
            float a0 = __ldg(&bn2[128+co]) - __ldg(&bn2[256+co]) * i0;
            float i1 = __ldg(&bn2[co+1]) / sqrtf(__ldg(&bn2[385+co]) + EPSBN);
            float a1 = __ldg(&bn2[129+co]) - __ldg(&bn2[257+co]) * i1;
            float b0v = __ldg(&bstd[co]), b1v = __ldg(&bstd[co+1]);
            const float* d = acc[mt][nt];
            int pix0 = p0 + row, pix1 = p0 + row + 8;
            int i_0 = pix0/96, j_0 = pix0 - i_0*96;
            int i_1 = pix1/96, j_1 = pix1 - i_1*96;
            float2 xc0 = *(const float2*)(xpb + (size_t)((i_0+1)*98 + j_0+1)*CH + co);
            float2 xc1 = *(const float2*)(xpb + (size_t)((i_1+1)*98 + j_1+1)*CH + co);
            float f00 = fmaxf((d[0] + b0v)*i0 + a0, 0.f) + xc0.x;
            float f01 = fmaxf((d[1] + b1v)*i1 + a1, 0.f) + xc0.y;
            float f10 = fmaxf((d[2] + b0v)*i0 + a0, 0.f) + xc1.x;
            float f11 = fmaxf((d[3] + b1v)*i1 + a1, 0.f) + xc1.y;
            __nv_bfloat16 h0,l0,h1,l1;
            split2(f00,h0,l0); split2(f01,h1,l1);
            int off = SWZ(row*256 + co*2);
            __nv_bfloat162 hv; hv.x=h0; hv.y=h1;
            __nv_bfloat162 lv; lv.x=l0; lv.y=l1;
            *(__nv_bfloat162*)(oH + off) = hv;
            *(__nv_bfloat162*)(oL + off) = lv;
            split2(f10,h0,l0); split2(f11,h1,l1);
            off = SWZ((row+8)*256 + co*2);
            hv.x=h0; hv.y=h1; lv.x=l0; lv.y=l1;
            *(__nv_bfloat162*)(oH + off) = hv;
            *(__nv_bfloat162*)(oL + off) = lv;
        }
}

// ===================== k_tout: final 1x1 conv ===============================
__global__ __launch_bounds__(TMM) void k_tout(const float* __restrict__ bias,
                                              float* __restrict__ out) {
    extern __shared__ char smem[];
    u32 sb = smem_to_u32(smem);
    int tid = threadIdx.x, wid = tid >> 5, lane = tid & 31;
    int g = lane >> 2, t = lane & 3;
    int wm = wid & 3, wn = wid >> 2;
    int pb = wm*32, cb = wn*32;
    int tile = blockIdx.x, b = blockIdx.y, z = blockIdx.z;
    int p0 = tile * 128;

    float acc[2][4][4];
#pragma unroll
    for (int i = 0; i < 2; i++)
#pragma unroll
        for (int j = 0; j < 4; j++)
#pragma unroll
            for (int k = 0; k < 4; k++) acc[i][j][k] = 0.f;

    for (int kc = 0; kc < 2; kc++) {
        __syncthreads();
        {
            const char* wh = (const char*)(g_woH + (z*2 + kc)*16384);
            const char* wl = (const char*)(g_woL + (z*2 + kc)*16384);
            const char* ah = (const char*)((kc ? g_a2H : g_a1H) + (size_t)(b*NTILES + tile)*16384);
            const char* al = (const char*)((kc ? g_a2L : g_a1L) + (size_t)(b*NTILES + tile)*16384);
            for (int i2 = tid; i2 < 2048; i2 += TMM) {
                CP16(sb + OFF_A + i2*16,         ah + i2*16);
                CP16(sb + OFF_A + 32768 + i2*16, al + i2*16);
                CP16(sb + OFF_B + i2*16,         wh + i2*16);
                CP16(sb + OFF_B + 32768 + i2*16, wl + i2*16);
            }
            CP_COMMIT();
            CP_WAIT0();
        }
        __syncthreads();
        mma_tap(smem + OFF_A, smem + OFF_B, acc, pb, cb, g, t);
    }
#pragma unroll
    for (int mt = 0; mt < 2; mt++)
#pragma unroll
        for (int nt = 0; nt < 4; nt++) {
            int row = p0 + pb + mt*16 + g;
            int co  = z*128 + cb + nt*8 + 2*t;
            float b0v = __ldg(&bias[co]), b1v = __ldg(&bias[co+1]);
            const float* d = acc[mt][nt];
            out[((size_t)(b*256 + co  ))*HW + row]     = d[0] + b0v;
            out[((size_t)(b*256 + co+1))*HW + row]     = d[1] + b1v;
            out[((size_t)(b*256 + co  ))*HW + row + 8] = d[2] + b0v;
            out[((size_t)(b*256 + co+1))*HW + row + 8] = d[3] + b1v;
        }
}

// ===================== launch ===============================================
extern "C" void kernel_launch(void* const* d_in, const int* in_sizes, int n_in,
                              void* d_out, int out_size) {
    const float* x     = (const float*)d_in[0];
    const float* w_in  = (const float*)d_in[1];
    const float* b_in  = (const float*)d_in[2];
    const float* w_off = (const float*)d_in[3];
    const float* b_off = (const float*)d_in[4];
    const float* w_def = (const float*)d_in[5];
    const float* b_def = (const float*)d_in[6];
    const float* bn1   = (const float*)d_in[7];
    const float* w_std = (const float*)d_in[8];
    const float* b_std = (const float*)d_in[9];
    const float* bn2   = (const float*)d_in[10];
    const float* w_out = (const float*)d_in[11];
    const float* b_out = (const float*)d_in[12];
    float* out = (float*)d_out;

    cudaFuncSetAttribute(k_tdef, cudaFuncAttributeMaxDynamicSharedMemorySize, SMEM_T2);
    cudaFuncSetAttribute(k_tstd, cudaFuncAttributeMaxDynamicSharedMemorySize, SMEM_T2);
    cudaFuncSetAttribute(k_tout, cudaFuncAttributeMaxDynamicSharedMemorySize, SMEM_TO);

    k_zero   <<<2048, 256>>>();
    k_prep   <<<832, 256>>>(w_def, w_std, w_out);
    k_conv_in<<<dim3(144, BATCH), 256>>>(x, w_in, b_in);
    k_off    <<<dim3(24, BATCH, 2), 384>>>(w_off, b_off);
    k_tdef   <<<dim3(NTILES, BATCH), TMM, SMEM_T2>>>(b_def, bn1);
    k_tstd   <<<dim3(NTILES, BATCH), TMM, SMEM_T2>>>(b_std, bn2);
    k_tout   <<<dim3(NTILES, BATCH, 2), TMM, SMEM_TO>>>(b_out, out);
}

// round 12
// speedup vs baseline: 2.1116x; 1.1405x over previous
#include <cuda_runtime.h>
#include <cuda_bf16.h>
#include <cstdint>

#define BATCH 4
#define CH 128
#define HH 96
#define WW 96
#define HW (HH*WW)
#define P98 9604           // 98*98 padded image
#define EPSBN 1e-5f
#define NTILES 72          // 9216 px / 128

#define WP 132
#define TMM 512            // threads per MMA kernel block

typedef unsigned long long u64;
typedef uint32_t u32;

// ===================== scalar fp32x2 helpers (conv_in) ======================
__device__ __forceinline__ void fma2(u64 &d, u64 a, u64 b) {
    asm("fma.rn.f32x2 %0, %1, %2, %0;" : "+l"(d) : "l"(a), "l"(b));
}
__device__ __forceinline__ u64 bc2(float x) {
    u64 r; asm("mov.b64 %0, {%1, %1};" : "=l"(r) : "f"(x)); return r;
}
__device__ __forceinline__ float2 unp2(u64 v) {
    float2 f; asm("mov.b64 {%0, %1}, %2;" : "=f"(f.x), "=f"(f.y) : "l"(v)); return f;
}
#define GSTEP(SROW, WROW) { \
    float4 xv = *(const float4*)(SROW); \
    ulonglong2 wA = *(const ulonglong2*)(WROW); \
    ulonglong2 wB = *(const ulonglong2*)((WROW)+4); \
    u64 xb0=bc2(xv.x), xb1=bc2(xv.y), xb2=bc2(xv.z), xb3=bc2(xv.w); \
    fma2(acc[0][0],wA.x,xb0); fma2(acc[0][1],wA.y,xb0); fma2(acc[0][2],wB.x,xb0); fma2(acc[0][3],wB.y,xb0); \
    fma2(acc[1][0],wA.x,xb1); fma2(acc[1][1],wA.y,xb1); fma2(acc[1][2],wB.x,xb1); fma2(acc[1][3],wB.y,xb1); \
    fma2(acc[2][0],wA.x,xb2); fma2(acc[2][1],wA.y,xb2); fma2(acc[2][2],wB.x,xb2); fma2(acc[2][3],wB.y,xb2); \
    fma2(acc[3][0],wA.x,xb3); fma2(acc[3][1],wA.y,xb3); fma2(acc[3][2],wB.x,xb3); fma2(acc[3][3],wB.y,xb3); }
#define ACC_INIT u64 acc[4][4]; _Pragma("unroll") for (int _i=0;_i<4;_i++) _Pragma("unroll") for(int _j=0;_j<4;_j++) acc[_i][_j]=0ull;

// ===================== mma.sync + cp.async helpers ==========================
#define SWZ(x) ((x) ^ ((((x) >> 8) & 7) << 4))

#define MMA_BF16(D, A, B0, B1) \
    asm volatile("mma.sync.aligned.m16n8k16.row.col.f32.bf16.bf16.f32 " \
        "{%0,%1,%2,%3}, {%4,%5,%6,%7}, {%8,%9}, {%0,%1,%2,%3};" \
        : "+f"((D)[0]), "+f"((D)[1]), "+f"((D)[2]), "+f"((D)[3]) \
        : "r"((A)[0]), "r"((A)[1]), "r"((A)[2]), "r"((A)[3]), "r"(B0), "r"(B1))

#define CP16(d, s)  asm volatile("cp.async.cg.shared.global [%0], [%1], 16;" :: "r"(d), "l"(s) : "memory")
#define CP_COMMIT() asm volatile("cp.async.commit_group;" ::: "memory")
#define CP_WAIT0()  asm volatile("cp.async.wait_group 0;" ::: "memory")
#define CP_WAIT1()  asm volatile("cp.async.wait_group 1;" ::: "memory")

__device__ __forceinline__ u32 smem_to_u32(const void* p) {
    u32 a;
    asm("{ .reg .u64 t; cvta.to.shared.u64 t, %1; cvt.u32.u64 %0, t; }" : "=r"(a) : "l"(p));
    return a;
}
__device__ __forceinline__ void split2(float v, __nv_bfloat16 &h, __nv_bfloat16 &l) {
    h = __float2bfloat16(v);
    l = __float2bfloat16(v - __bfloat162float(h));
}

// smem layout: A (hi 32K + lo 32K) @0; B stages (hi+lo 64K) @65536,@131072;
// B_off (hi 6K + lo 6K) @196608 (k_tstd only)
#define OFF_A   0
#define OFF_B   65536
#define STAGE   65536
#define OFF_BO  196608
#define SMEM_T2 196608     // tdef
#define SMEM_T3 208896     // tstd (with offset-conv B)
#define SMEM_TO 131072     // tout (A + single B stage)

// ===================== scratch globals ======================================
__device__ float g_xp [BATCH*P98*CH];           // x_c padded NHWC fp32
__device__ __nv_bfloat16 g_xpH[BATCH*P98*CH];   // padded NHWC bf16 hi
__device__ __nv_bfloat16 g_xpL[BATCH*P98*CH];   // padded NHWC bf16 lo
__device__ float g_off[BATCH*18*HW];
__device__ __nv_bfloat16 g_wdH[9*16384], g_wdL[9*16384];
__device__ __nv_bfloat16 g_wsH[9*16384], g_wsL[9*16384];
__device__ __nv_bfloat16 g_woH[4*16384], g_woL[4*16384];
__device__ __nv_bfloat16 g_wfH[9*3072],  g_wfL[9*3072];   // offset conv weights (24 rows x 128)
__device__ __nv_bfloat16 g_a1H[BATCH*NTILES*16384], g_a1L[BATCH*NTILES*16384];
__device__ __nv_bfloat16 g_a2H[BATCH*NTILES*16384], g_a2L[BATCH*NTILES*16384];

// ===================== k_zero: clear padded buffers =========================
__global__ void k_zero() {
    size_t idx = (size_t)blockIdx.x*256 + threadIdx.x;
    size_t stride = (size_t)gridDim.x*256;
    for (size_t i = idx; i < (size_t)BATCH*P98*CH/4; i += stride)
        ((float4*)g_xp)[i] = make_float4(0.f,0.f,0.f,0.f);
    for (size_t i = idx; i < (size_t)BATCH*P98*CH/8; i += stride) {
        ((uint4*)g_xpH)[i] = make_uint4(0,0,0,0);
        ((uint4*)g_xpL)[i] = make_uint4(0,0,0,0);
    }
}

// ===================== k_prep: weight split + swizzled tiles ================
__global__ void k_prep(const float* __restrict__ wdef, const float* __restrict__ wstd,
                       const float* __restrict__ wout, const float* __restrict__ woff) {
    int idx = blockIdx.x * 256 + threadIdx.x;
    if (idx < 147456) {
        int n = idx / 16384, r = idx % 16384;
        int co = r >> 7, ci = r & 127;
        int off = SWZ(co*256 + ci*2);
        int dst = n*16384 + (off >> 1);
        int src = co*1152 + ci*9 + n;
        __nv_bfloat16 h, l;
        split2(wdef[src], h, l); g_wdH[dst] = h; g_wdL[dst] = l;
        split2(wstd[src], h, l); g_wsH[dst] = h; g_wsL[dst] = l;
    } else if (idx < 147456 + 65536) {
        int j = idx - 147456;
        int ci = j & 127, co = (j >> 7) & 127, kc = (j >> 14) & 1, z = (j >> 15) & 1;
        int off = SWZ(co*256 + ci*2);
        int dst = (z*2 + kc)*16384 + (off >> 1);
        __nv_bfloat16 h, l;
        split2(wout[(z*128 + co)*256 + kc*128 + ci], h, l);
        g_woH[dst] = h; g_woL[dst] = l;
    } else if (idx < 147456 + 65536 + 27648) {
        int j = idx - 147456 - 65536;
        int n = j / 3072, r = j % 3072;
        int co = r >> 7, ci = r & 127;        // co 0..23
        float v = (co < 18) ? woff[co*1152 + ci*9 + n] : 0.f;
        int off = SWZ(co*256 + ci*2);
        int dst = n*3072 + (off >> 1);
        __nv_bfloat16 h, l;
        split2(v, h, l); g_wfH[dst] = h; g_wfL[dst] = l;
    }
}

// ===================== k_conv_in: 1x1 conv -> padded NHWC ===================
__global__ __launch_bounds__(256) void k_conv_in(const float* __restrict__ x,
                                                 const float* __restrict__ w,
                                                 const float* __restrict__ bias) {
    __shared__ float Ws[32*WP];
    __shared__ float Xs[32*64];
    int tid = threadIdx.x;
    int b  = blockIdx.y;
    int p0 = blockIdx.x * 64;
    int ty = tid >> 4, tx = tid & 15;
    int cob = ty*8, pxb = tx*4;

    ACC_INIT
    for (int cb = 0; cb < CH; cb += 32) {
        __syncthreads();
        for (int idx = tid; idx < 4096; idx += 256) {
            int co = idx >> 5, c = idx & 31;
            Ws[c*WP + co] = w[co*CH + cb + c];
        }
        for (int idx = tid; idx < 2048; idx += 256) {
            int c = idx >> 6, p = idx & 63;
            Xs[c*64 + p] = x[((size_t)b*CH + cb + c)*HW + p0 + p];
        }
        __syncthreads();
#pragma unroll 8
        for (int c = 0; c < 32; c++) { GSTEP(&Xs[c*64 + pxb], &Ws[c*WP + cob]) }
    }
    float v[4][8];
#pragma unroll
    for (int k = 0; k < 4; k++)
#pragma unroll
        for (int px = 0; px < 4; px++) {
            float2 f = unp2(acc[px][k]);
            v[px][2*k] = f.x; v[px][2*k+1] = f.y;
        }
    float bb[8];
#pragma unroll
    for (int u = 0; u < 8; u++) bb[u] = __ldg(&bias[cob + u]);
#pragma unroll
    for (int px = 0; px < 4; px++) {
        int pix = p0 + pxb + px;
        int i = pix / 96, j = pix - i*96;
        size_t pbase = ((size_t)b*P98 + (i+1)*98 + (j+1))*CH + cob;
        float fv[8];
#pragma unroll
        for (int u = 0; u < 8; u++) fv[u] = v[px][u] + bb[u];
        *(float4*)&g_xp[pbase]   = make_float4(fv[0], fv[1], fv[2], fv[3]);
        *(float4*)&g_xp[pbase+4] = make_float4(fv[4], fv[5], fv[6], fv[7]);
        __nv_bfloat162 hv[4], lv[4];
#pragma unroll
        for (int u = 0; u < 4; u++) {
            __nv_bfloat16 h0,l0,h1,l1;
            split2(fv[2*u], h0, l0); split2(fv[2*u+1], h1, l1);
            hv[u].x = h0; hv[u].y = h1; lv[u].x = l0; lv[u].y = l1;
        }
        *(uint4*)&g_xpH[pbase] = *(uint4*)hv;
        *(uint4*)&g_xpL[pbase] = *(uint4*)lv;
    }
}

// ===================== MMA K=128 tap: warp computes 32x32 ===================
__device__ __forceinline__ void mma_tap(const char* sA, const char* sB, float acc[2][4][4],
                                        int pb, int cb, int g, int t) {
#pragma unroll
    for (int ks = 0; ks < 8; ks++) {
        int kb = ks*32 + t*4;
        u32 ah[2][4], al[2][4];
#pragma unroll
        for (int mt = 0; mt < 2; mt++) {
            int r0 = (pb + mt*16 + g)*256 + kb;
            int r1 = r0 + 8*256;
            int o0 = SWZ(r0), o1 = SWZ(r1), o2 = SWZ(r0 + 16), o3 = SWZ(r1 + 16);
            ah[mt][0] = *(const u32*)(sA + o0);
            ah[mt][1] = *(const u32*)(sA + o1);
            ah[mt][2] = *(const u32*)(sA + o2);
            ah[mt][3] = *(const u32*)(sA + o3);
            al[mt][0] = *(const u32*)(sA + 32768 + o0);
            al[mt][1] = *(const u32*)(sA + 32768 + o1);
            al[mt][2] = *(const u32*)(sA + 32768 + o2);
            al[mt][3] = *(const u32*)(sA + 32768 + o3);
        }
#pragma unroll
        for (int nt = 0; nt < 4; nt++) {
            int rb = (cb + nt*8 + g)*256 + kb;
            int ob0 = SWZ(rb), ob1 = SWZ(rb + 16);
            u32 bh0 = *(const u32*)(sB + ob0);
            u32 bh1 = *(const u32*)(sB + ob1);
            u32 bl0 = *(const u32*)(sB + 32768 + ob0);
            u32 bl1 = *(const u32*)(sB + 32768 + ob1);
#pragma unroll
            for (int mt = 0; mt < 2; mt++) {
                MMA_BF16(acc[mt][nt], ah[mt], bh0, bh1);
                MMA_BF16(acc[mt][nt], ah[mt], bl0, bl1);
                MMA_BF16(acc[mt][nt], al[mt], bh0, bh1);
            }
        }
    }
}

// offset-conv extra MMAs: 3 n8-tiles from small B_off tile (hi@sBo, lo@sBo+6144)
__device__ __forceinline__ void mma_tap_off(const char* sA, const char* sBo, float acco[2][3][4],
                                            int pb, int g, int t) {
#pragma unroll
    for (int ks = 0; ks < 8; ks++) {
        int kb = ks*32 + t*4;
        u32 ah[2][4], al[2][4];
#pragma unroll
        for (int mt = 0; mt < 2; mt++) {
            int r0 = (pb + mt*16 + g)*256 + kb;
            int r1 = r0 + 8*256;
            int o0 = SWZ(r0), o1 = SWZ(r1), o2 = SWZ(r0 + 16), o3 = SWZ(r1 + 16);
            ah[mt][0] = *(const u32*)(sA + o0);
            ah[mt][1] = *(const u32*)(sA + o1);
            ah[mt][2] = *(const u32*)(sA + o2);
            ah[mt][3] = *(const u32*)(sA + o3);
            al[mt][0] = *(const u32*)(sA + 32768 + o0);
            al[mt][1] = *(const u32*)(sA + 32768 + o1);
            al[mt][2] = *(const u32*)(sA + 32768 + o2);
            al[mt][3] = *(const u32*)(sA + 32768 + o3);
        }
#pragma unroll
        for (int nt = 0; nt < 3; nt++) {
            int rb = (nt*8 + g)*256 + kb;
            int ob0 = SWZ(rb), ob1 = SWZ(rb + 16);
            u32 bh0 = *(const u32*)(sBo + ob0);
            u32 bh1 = *(const u32*)(sBo + ob1);
            u32 bl0 = *(const u32*)(sBo + 6144 + ob0);
            u32 bl1 = *(const u32*)(sBo + 6144 + ob1);
#pragma unroll
            for (int mt = 0; mt < 2; mt++) {
                MMA_BF16(acco[mt][nt], ah[mt], bh0, bh1);
                MMA_BF16(acco[mt][nt], ah[mt], bl0, bl1);
                MMA_BF16(acco[mt][nt], al[mt], bh0, bh1);
            }
        }
    }
}

// weight cp.async stage: 4096 x 16B granules (hi+lo), identity mapping
__device__ __forceinline__ void stage_B(u32 dstu, const __nv_bfloat16* srcH,
                                        const __nv_bfloat16* srcL, int tid) {
    const char* sh = (const char*)srcH;
    const char* sl = (const char*)srcL;
    for (int i2 = tid; i2 < 2048; i2 += TMM) {
        CP16(dstu + i2*16,         sh + i2*16);
        CP16(dstu + 32768 + i2*16, sl + i2*16);
    }
}

// ===================== k_tstd: std 3x3 branch + fused offset conv ===========
__global__ __launch_bounds__(TMM) void k_tstd(const float* __restrict__ bstd,
                                              const float* __restrict__ bn2,
                                              const float* __restrict__ boff) {
    extern __shared__ char smem[];
    u32 sb = smem_to_u32(smem);
    int tid = threadIdx.x, wid = tid >> 5, lane = tid & 31;
    int g = lane >> 2, t = lane & 3;
    int wm = wid & 3, wn = wid >> 2;
    int pb = wm*32, cb = wn*32;
    int tile = blockIdx.x, b = blockIdx.y;
    int p0 = tile * 128;

    float acc[2][4][4];
    float acco[2][3][4];
#pragma unroll
    for (int i = 0; i < 2; i++) {
#pragma unroll
        for (int j = 0; j < 4; j++)
#pragma unroll
            for (int k = 0; k < 4; k++) acc[i][j][k] = 0.f;
#pragma unroll
        for (int j = 0; j < 3; j++)
#pragma unroll
            for (int k = 0; k < 4; k++) acco[i][j][k] = 0.f;
    }

    stage_B(sb + OFF_B, g_wsH, g_wsL, tid);
    CP_COMMIT();

    for (int n = 0; n < 9; n++) {
        __syncthreads();
        int di = n/3 - 1, dj = n%3 - 1;
        // A tile + B_off: cp.async from pre-split padded bf16 / offset weights
        {
            const char* sh = (const char*)(g_xpH + (size_t)b*P98*CH);
            const char* sl = (const char*)(g_xpL + (size_t)b*P98*CH);
            for (int idx = tid; idx < 2048; idx += TMM) {
                int px = idx >> 4, g16 = idx & 15;
                int pix = p0 + px;
                int i = pix / 96, j = pix - i*96;
                size_t src = ((size_t)((i+1+di)*98 + (j+1+dj))*CH)*2 + g16*16;
                u32 dst = sb + OFF_A + SWZ(px*256 + g16*16);
                CP16(dst, sh + src);
                CP16(dst + 32768, sl + src);
            }
            if (tid < 384) {
                CP16(sb + OFF_BO + tid*16,        ((const char*)g_wfH) + (size_t)n*6144 + tid*16);
                CP16(sb + OFF_BO + 6144 + tid*16, ((const char*)g_wfL) + (size_t)n*6144 + tid*16);
            }
            CP_COMMIT();
        }
        if (n < 8) {
            stage_B(sb + OFF_B + ((n+1)&1)*STAGE, g_wsH + (n+1)*16384, g_wsL + (n+1)*16384, tid);
            CP_COMMIT();
        }
        if (n < 8) { CP_WAIT1(); } else { CP_WAIT0(); }   // A(n)+Boff(n)+B(n) done
        __syncthreads();
        mma_tap(smem + OFF_A, smem + OFF_B + (n&1)*STAGE, acc, pb, cb, g, t);
        if (wn == 3) mma_tap_off(smem + OFF_A, smem + OFF_BO, acco, pb, g, t);
    }
    const float* xpb = g_xp + (size_t)b*P98*CH;
    char* oH = (char*)(g_a2H + (size_t)(b*NTILES + tile)*16384);
    char* oL = (char*)(g_a2L + (size_t)(b*NTILES + tile)*16384);
#pragma unroll
    for (int mt = 0; mt < 2; mt++)
#pragma unroll
        for (int nt = 0; nt < 4; nt++) {
            int row = pb + mt*16 + g;
            int co  = cb + nt*8 + 2*t;
            float i0 = __ldg(&bn2[co]) / sqrtf(__ldg(&bn2[384+co]) + EPSBN);
            float a0 = __ldg(&bn2[128+co]) - __ldg(&bn2[256+co]) * i0;
            float i1 = __ldg(&bn2[co+1]) / sqrtf(__ldg(&bn2[385+co]) + EPSBN);
            float a1 = __ldg(&bn2[129+co]) - __ldg(&bn2[257+co]) * i1;
            float b0v = __ldg(&bstd[co]), b1v = __ldg(&bstd[co+1]);
            const float* d = acc[mt][nt];
            int pix0 = p0 + row, pix1 = p0 + row + 8;
            int i_0 = pix0/96, j_0 = pix0 - i_0*96;
            int i_1 = pix1/96, j_1 = pix1 - i_1*96;
            float2 xc0 = *(const float2*)(xpb + (size_t)((i_0+1)*98 + j_0+1)*CH + co);
            float2 xc1 = *(const float2*)(xpb + (size_t)((i_1+1)*98 + j_1+1)*CH + co);
            float f00 = fmaxf((d[0] + b0v)*i0 + a0, 0.f) + xc0.x;
            float f01 = fmaxf((d[1] + b1v)*i1 + a1, 0.f) + xc0.y;
            float f10 = fmaxf((d[2] + b0v)*i0 + a0, 0.f) + xc1.x;
            float f11 = fmaxf((d[3] + b1v)*i1 + a1, 0.f) + xc1.y;
            __nv_bfloat16 h0,l0,h1,l1;
            split2(f00,h0,l0); split2(f01,h1,l1);
            int off = SWZ(row*256 + co*2);
            __nv_bfloat162 hv; hv.x=h0; hv.y=h1;
            __nv_bfloat162 lv; lv.x=l0; lv.y=l1;
            *(__nv_bfloat162*)(oH + off) = hv;
            *(__nv_bfloat162*)(oL + off) = lv;
            split2(f10,h0,l0); split2(f11,h1,l1);
            off = SWZ((row+8)*256 + co*2);
            hv.x=h0; hv.y=h1; lv.x=l0; lv.y=l1;
            *(__nv_bfloat162*)(oH + off) = hv;
            *(__nv_bfloat162*)(oL + off) = lv;
        }
    // offset conv epilogue (wn==3 warps): write g_off NCHW
    if (wn == 3) {
#pragma unroll
        for (int mt = 0; mt < 2; mt++)
#pragma unroll
            for (int nt = 0; nt < 3; nt++) {
                int co = nt*8 + 2*t;
                if (co < 18) {
                    int row = pb + mt*16 + g;
                    const float* d = acco[mt][nt];
                    g_off[(size_t)(b*18 + co  )*HW + p0 + row]     = d[0] + __ldg(&boff[co]);
                    g_off[(size_t)(b*18 + co+1)*HW + p0 + row]     = d[1] + __ldg(&boff[co+1]);
                    g_off[(size_t)(b*18 + co  )*HW + p0 + row + 8] = d[2] + __ldg(&boff[co]);
                    g_off[(size_t)(b*18 + co+1)*HW + p0 + row + 8] = d[3] + __ldg(&boff[co+1]);
                }
            }
    }
}

// ===================== k_tdef: deform branch ================================
__global__ __launch_bounds__(TMM) void k_tdef(const float* __restrict__ bdef,
                                              const float* __restrict__ bn1) {
    extern __shared__ char smem[];
    u32 sb = smem_to_u32(smem);
    int tid = threadIdx.x, wid = tid >> 5, lane = tid & 31;
    int g = lane >> 2, t = lane & 3;
    int wm = wid & 3, wn = wid >> 2;
    int pb = wm*32, cb = wn*32;
    int tile = blockIdx.x, b = blockIdx.y;
    int p0 = tile * 128;

    float acc[2][4][4];
#pragma unroll
    for (int i = 0; i < 2; i++)
#pragma unroll
        for (int j = 0; j < 4; j++)
#pragma unroll
            for (int k = 0; k < 4; k++) acc[i][j][k] = 0.f;

    const float* xpb = g_xp + (size_t)b*P98*CH;

    stage_B(sb + OFF_B, g_wdH, g_wdL, tid);
    CP_COMMIT();

    for (int n = 0; n < 9; n++) {
        __syncthreads();
        if (n < 8) {
            stage_B(sb + OFF_B + ((n+1)&1)*STAGE, g_wdH + (n+1)*16384, g_wdL + (n+1)*16384, tid);
            CP_COMMIT();
        }
        float dnx = (float)(n/3 - 1), dny = (float)(n%3 - 1);
#pragma unroll 4
        for (int k = 0; k < 8; k++) {
            int px = wid*8 + k;
            int pix = p0 + px;
            int i = pix / 96, j = pix - i*96;
            float ox = __ldg(&g_off[(size_t)(b*18 + n    )*HW + pix]);
            float oy = __ldg(&g_off[(size_t)(b*18 + n + 9)*HW + pix]);
            float pfx = ox + dnx + (float)(i + 1);
            float pfy = oy + dny + (float)(j + 1);
            float qx = floorf(pfx), qy = floorf(pfy);
            float ltx = fminf(fmaxf(qx,       0.f), 97.f);
            float lty = fminf(fmaxf(qy,       0.f), 97.f);
            float rbx = fminf(fmaxf(qx + 1.f, 0.f), 97.f);
            float rby = fminf(fmaxf(qy + 1.f, 0.f), 97.f);
            float pcx = fminf(fmaxf(pfx, 0.f), 97.f);
            float pcy = fminf(fmaxf(pfy, 0.f), 97.f);
            float glt = (1.f + (ltx - pcx)) * (1.f + (lty - pcy));
            float grb = (1.f - (rbx - pcx)) * (1.f - (rby - pcy));
            float glb = (1.f + (ltx - pcx)) * (1.f - (rby - pcy));
            float grt = (1.f - (rbx - pcx)) * (1.f + (lty - pcy));
            int ix0 = (int)ltx, iy0 = (int)lty, ix1 = (int)rbx, iy1 = (int)rby;
            const float* plt = xpb + (size_t)(ix0*98 + iy0)*CH;
            const float* prb = xpb + (size_t)(ix1*98 + iy1)*CH;
            const float* plb = xpb + (size_t)(ix0*98 + iy1)*CH;
            const float* prt = xpb + (size_t)(ix1*98 + iy0)*CH;
#pragma unroll
            for (int it = 0; it < 2; it++) {
                int ci0 = it*64 + lane*2;
                float2 a2 = *(const float2*)(plt + ci0);
                float2 b2 = *(const float2*)(prb + ci0);
                float2 c2 = *(const float2*)(plb + ci0);
                float2 d2 = *(const float2*)(prt + ci0);
                float v0 = glt*a2.x + grb*b2.x + glb*c2.x + grt*d2.x;
                float v1 = glt*a2.y + grb*b2.y + glb*c2.y + grt*d2.y;
                __nv_bfloat16 h0, l0, h1, l1;
                split2(v0, h0, l0); split2(v1, h1, l1);
                int off = SWZ(px*256 + ci0*2);
                __nv_bfloat162 hv; hv.x = h0; hv.y = h1;
                __nv_bfloat162 lv; lv.x = l0; lv.y = l1;
                *(__nv_bfloat162*)(smem + OFF_A + off) = hv;
                *(__nv_bfloat162*)(smem + OFF_A + 32768 + off) = lv;
            }
        }
        if (n < 8) { CP_WAIT1(); } else { CP_WAIT0(); }
        __syncthreads();
        mma_tap(smem + OFF_A, smem + OFF_B + (n&1)*STAGE, acc, pb, cb, g, t);
    }
    char* oH = (char*)(g_a1H + (size_t)(b*NTILES + tile)*16384);
    char* oL = (char*)(g_a1L + (size_t)(b*NTILES + tile)*16384);
#pragma unroll
    for (int mt = 0; mt < 2; mt++)
#pragma unroll
        for (int nt = 0; nt < 4; nt++) {
            int row = pb + mt*16 + g;
            int co  = cb + nt*8 + 2*t;
            float i0 = __ldg(&bn1[co]) / sqrtf(__ldg(&bn1[384+co]) + EPSBN);
            float a0 = __ldg(&bn1[128+co]) - __ldg(&bn1[256+co]) * i0;
            float i1 = __ldg(&bn1[co+1]) / sqrtf(__ldg(&bn1[385+co]) + EPSBN);
            float a1 = __ldg(&bn1[129+co]) - __ldg(&bn1[257+co]) * i1;
            float b0v = __ldg(&bdef[co]), b1v = __ldg(&bdef[co+1]);
            const float* d = acc[mt][nt];
            float f00 = fmaxf((d[0] + b0v)*i0 + a0, 0.f);
            float f01 = fmaxf((d[1] + b1v)*i1 + a1, 0.f);
            float f10 = fmaxf((d[2] + b0v)*i0 + a0, 0.f);
            float f11 = fmaxf((d[3] + b1v)*i1 + a1, 0.f);
            __nv_bfloat16 h0,l0,h1,l1;
            split2(f00,h0,l0); split2(f01,h1,l1);
            int off = SWZ(row*256 + co*2);
            __nv_bfloat162 hv; hv.x=h0; hv.y=h1;
            __nv_bfloat162 lv; lv.x=l0; lv.y=l1;
            *(__nv_bfloat162*)(oH + off) = hv;
            *(__nv_bfloat162*)(oL + off) = lv;
            split2(f10,h0,l0); split2(f11,h1,l1);
            off = SWZ((row+8)*256 + co*2);
            hv.x=h0; hv.y=h1; lv.x=l0; lv.y=l1;
            *(__nv_bfloat162*)(oH + off) = hv;
            *(__nv_bfloat162*)(oL + off) = lv;
        }
}

// ===================== k_tout: final 1x1 conv ===============================
__global__ __launch_bounds__(TMM) void k_tout(const float* __restrict__ bias,
                                              float* __restrict__ out) {
    extern __shared__ char smem[];
    u32 sb = smem_to_u32(smem);
    int tid = threadIdx.x, wid = tid >> 5, lane = tid & 31;
    int g = lane >> 2, t = lane & 3;
    int wm = wid & 3, wn = wid >> 2;
    int pb = wm*32, cb = wn*32;
    int tile = blockIdx.x, b = blockIdx.y, z = blockIdx.z;
    int p0 = tile * 128;

    float acc[2][4][4];
#pragma unroll
    for (int i = 0; i < 2; i++)
#pragma unroll
        for (int j = 0; j < 4; j++)
#pragma unroll
            for (int k = 0; k < 4; k++) acc[i][j][k] = 0.f;

    for (int kc = 0; kc < 2; kc++) {
        __syncthreads();
        {
            const char* wh = (const char*)(g_woH + (z*2 + kc)*16384);
            const char* wl = (const char*)(g_woL + (z*2 + kc)*16384);
            const char* ah = (const char*)((kc ? g_a2H : g_a1H) + (size_t)(b*NTILES + tile)*16384);
            const char* al = (const char*)((kc ? g_a2L : g_a1L) + (size_t)(b*NTILES + tile)*16384);
            for (int i2 = tid; i2 < 2048; i2 += TMM) {
                CP16(sb + OFF_A + i2*16,         ah + i2*16);
                CP16(sb + OFF_A + 32768 + i2*16, al + i2*16);
                CP16(sb + OFF_B + i2*16,         wh + i2*16);
                CP16(sb + OFF_B + 32768 + i2*16, wl + i2*16);
            }
            CP_COMMIT();
            CP_WAIT0();
        }
        __syncthreads();
        mma_tap(smem + OFF_A, smem + OFF_B, acc, pb, cb, g, t);
    }
#pragma unroll
    for (int mt = 0; mt < 2; mt++)
#pragma unroll
        for (int nt = 0; nt < 4; nt++) {
            int row = p0 + pb + mt*16 + g;
            int co  = z*128 + cb + nt*8 + 2*t;
            float b0v = __ldg(&bias[co]), b1v = __ldg(&bias[co+1]);
            const float* d = acc[mt][nt];
            out[((size_t)(b*256 + co  ))*HW + row]     = d[0] + b0v;
            out[((size_t)(b*256 + co+1))*HW + row]     = d[1] + b1v;
            out[((size_t)(b*256 + co  ))*HW + row + 8] = d[2] + b0v;
            out[((size_t)(b*256 + co+1))*HW + row + 8] = d[3] + b1v;
        }
}

// ===================== launch ===============================================
extern "C" void kernel_launch(void* const* d_in, const int* in_sizes, int n_in,
                              void* d_out, int out_size) {
    const float* x     = (const float*)d_in[0];
    const float* w_in  = (const float*)d_in[1];
    const float* b_in  = (const float*)d_in[2];
    const float* w_off = (const float*)d_in[3];
    const float* b_off = (const float*)d_in[4];
    const float* w_def = (const float*)d_in[5];
    const float* b_def = (const float*)d_in[6];
    const float* bn1   = (const float*)d_in[7];
    const float* w_std = (const float*)d_in[8];
    const float* b_std = (const float*)d_in[9];
    const float* bn2   = (const float*)d_in[10];
    const float* w_out = (const float*)d_in[11];
    const float* b_out = (const float*)d_in[12];
    float* out = (float*)d_out;

    cudaFuncSetAttribute(k_tdef, cudaFuncAttributeMaxDynamicSharedMemorySize, SMEM_T2);
    cudaFuncSetAttribute(k_tstd, cudaFuncAttributeMaxDynamicSharedMemorySize, SMEM_T3);
    cudaFuncSetAttribute(k_tout, cudaFuncAttributeMaxDynamicSharedMemorySize, SMEM_TO);

    k_zero   <<<2048, 256>>>();
    k_prep   <<<940, 256>>>(w_def, w_std, w_out, w_off);
    k_conv_in<<<dim3(144, BATCH), 256>>>(x, w_in, b_in);
    k_tstd   <<<dim3(NTILES, BATCH), TMM, SMEM_T3>>>(b_std, bn2, b_off);
    k_tdef   <<<dim3(NTILES, BATCH), TMM, SMEM_T2>>>(b_def, bn1);
    k_tout   <<<dim3(NTILES, BATCH, 2), TMM, SMEM_TO>>>(b_out, out);
}

// round 13
// speedup vs baseline: 2.1454x; 1.0160x over previous
#include <cuda_runtime.h>
#include <cuda_bf16.h>
#include <cstdint>

#define BATCH 4
#define CH 128
#define HH 96
#define WW 96
#define HW (HH*WW)
#define P98 9604           // 98*98 padded image
#define EPSBN 1e-5f
#define NTILES 72          // 9216 px / 128

#define WP 132
#define TMM 512            // threads per MMA kernel block

typedef unsigned long long u64;
typedef uint32_t u32;

// ===================== scalar fp32x2 helpers (conv_in) ======================
__device__ __forceinline__ void fma2(u64 &d, u64 a, u64 b) {
    asm("fma.rn.f32x2 %0, %1, %2, %0;" : "+l"(d) : "l"(a), "l"(b));
}
__device__ __forceinline__ u64 bc2(float x) {
    u64 r; asm("mov.b64 %0, {%1, %1};" : "=l"(r) : "f"(x)); return r;
}
__device__ __forceinline__ float2 unp2(u64 v) {
    float2 f; asm("mov.b64 {%0, %1}, %2;" : "=f"(f.x), "=f"(f.y) : "l"(v)); return f;
}
#define GSTEP(SROW, WROW) { \
    float4 xv = *(const float4*)(SROW); \
    ulonglong2 wA = *(const ulonglong2*)(WROW); \
    ulonglong2 wB = *(const ulonglong2*)((WROW)+4); \
    u64 xb0=bc2(xv.x), xb1=bc2(xv.y), xb2=bc2(xv.z), xb3=bc2(xv.w); \
    fma2(acc[0][0],wA.x,xb0); fma2(acc[0][1],wA.y,xb0); fma2(acc[0][2],wB.x,xb0); fma2(acc[0][3],wB.y,xb0); \
    fma2(acc[1][0],wA.x,xb1); fma2(acc[1][1],wA.y,xb1); fma2(acc[1][2],wB.x,xb1); fma2(acc[1][3],wB.y,xb1); \
    fma2(acc[2][0],wA.x,xb2); fma2(acc[2][1],wA.y,xb2); fma2(acc[2][2],wB.x,xb2); fma2(acc[2][3],wB.y,xb2); \
    fma2(acc[3][0],wA.x,xb3); fma2(acc[3][1],wA.y,xb3); fma2(acc[3][2],wB.x,xb3); fma2(acc[3][3],wB.y,xb3); }
#define ACC_INIT u64 acc[4][4]; _Pragma("unroll") for (int _i=0;_i<4;_i++) _Pragma("unroll") for(int _j=0;_j<4;_j++) acc[_i][_j]=0ull;

// ===================== mma.sync + cp.async helpers ==========================
#define SWZ(x) ((x) ^ ((((x) >> 8) & 7) << 4))

#define MMA_BF16(D, A, B0, B1) \
    asm volatile("mma.sync.aligned.m16n8k16.row.col.f32.bf16.bf16.f32 " \
        "{%0,%1,%2,%3}, {%4,%5,%6,%7}, {%8,%9}, {%0,%1,%2,%3};" \
        : "+f"((D)[0]), "+f"((D)[1]), "+f"((D)[2]), "+f"((D)[3]) \
        : "r"((A)[0]), "r"((A)[1]), "r"((A)[2]), "r"((A)[3]), "r"(B0), "r"(B1))

#define CP16(d, s)  asm volatile("cp.async.cg.shared.global [%0], [%1], 16;" :: "r"(d), "l"(s) : "memory")
#define CP_COMMIT() asm volatile("cp.async.commit_group;" ::: "memory")
#define CP_WAIT0()  asm volatile("cp.async.wait_group 0;" ::: "memory")

__device__ __forceinline__ u32 smem_to_u32(const void* p) {
    u32 a;
    asm("{ .reg .u64 t; cvta.to.shared.u64 t, %1; cvt.u32.u64 %0, t; }" : "=r"(a) : "l"(p));
    return a;
}
__device__ __forceinline__ void split2(float v, __nv_bfloat16 &h, __nv_bfloat16 &l) {
    h = __float2bfloat16(v);
    l = __float2bfloat16(v - __bfloat162float(h));
}

// smem layouts (each A buffer: hi 32K then lo 32K)
#define TD_A0   0
#define TD_A1   65536
#define TD_B    131072
#define SMEM_TD 196608     // tdef: A0,A1,B
#define TS_A0   0
#define TS_A1   65536
#define TS_B    131072
#define TS_BO0  196608
#define TS_BO1  208896
#define SMEM_TS 221184     // tstd: A0,A1,B,Bo0,Bo1
#define TO_A    0
#define TO_B    65536
#define SMEM_TO 131072     // tout

// ===================== scratch globals ======================================
__device__ float g_xp [BATCH*P98*CH];           // x_c padded NHWC fp32
__device__ __nv_bfloat16 g_xpH[BATCH*P98*CH];   // padded NHWC bf16 hi
__device__ __nv_bfloat16 g_xpL[BATCH*P98*CH];   // padded NHWC bf16 lo
__device__ float g_off[BATCH*18*HW];
__device__ __nv_bfloat16 g_wdH[9*16384], g_wdL[9*16384];
__device__ __nv_bfloat16 g_wsH[9*16384], g_wsL[9*16384];
__device__ __nv_bfloat16 g_woH[4*16384], g_woL[4*16384];
__device__ __nv_bfloat16 g_wfH[9*3072],  g_wfL[9*3072];   // offset conv weights (24 rows x 128)
__device__ __nv_bfloat16 g_a1H[BATCH*NTILES*16384], g_a1L[BATCH*NTILES*16384];
__device__ __nv_bfloat16 g_a2H[BATCH*NTILES*16384], g_a2L[BATCH*NTILES*16384];

// ===================== k_zero: clear padded buffers =========================
__global__ void k_zero() {
    size_t idx = (size_t)blockIdx.x*256 + threadIdx.x;
    size_t stride = (size_t)gridDim.x*256;
    for (size_t i = idx; i < (size_t)BATCH*P98*CH/4; i += stride)
        ((float4*)g_xp)[i] = make_float4(0.f,0.f,0.f,0.f);
    for (size_t i = idx; i < (size_t)BATCH*P98*CH/8; i += stride) {
        ((uint4*)g_xpH)[i] = make_uint4(0,0,0,0);
        ((uint4*)g_xpL)[i] = make_uint4(0,0,0,0);
    }
}

// ===================== k_prep: weight split + swizzled tiles ================
__global__ void k_prep(const float* __restrict__ wdef, const float* __restrict__ wstd,
                       const float* __restrict__ wout, const float* __restrict__ woff) {
    int idx = blockIdx.x * 256 + threadIdx.x;
    if (idx < 147456) {
        int n = idx / 16384, r = idx % 16384;
        int co = r >> 7, ci = r & 127;
        int off = SWZ(co*256 + ci*2);
        int dst = n*16384 + (off >> 1);
        int src = co*1152 + ci*9 + n;
        __nv_bfloat16 h, l;
        split2(wdef[src], h, l); g_wdH[dst] = h; g_wdL[dst] = l;
        split2(wstd[src], h, l); g_wsH[dst] = h; g_wsL[dst] = l;
    } else if (idx < 147456 + 65536) {
        int j = idx - 147456;
        int ci = j & 127, co = (j >> 7) & 127, kc = (j >> 14) & 1, z = (j >> 15) & 1;
        int off = SWZ(co*256 + ci*2);
        int dst = (z*2 + kc)*16384 + (off >> 1);
        __nv_bfloat16 h, l;
        split2(wout[(z*128 + co)*256 + kc*128 + ci], h, l);
        g_woH[dst] = h; g_woL[dst] = l;
    } else if (idx < 147456 + 65536 + 27648) {
        int j = idx - 147456 - 65536;
        int n = j / 3072, r = j % 3072;
        int co = r >> 7, ci = r & 127;        // co 0..23
        float v = (co < 18) ? woff[co*1152 + ci*9 + n] : 0.f;
        int off = SWZ(co*256 + ci*2);
        int dst = n*3072 + (off >> 1);
        __nv_bfloat16 h, l;
        split2(v, h, l); g_wfH[dst] = h; g_wfL[dst] = l;
    }
}

// ===================== k_conv_in: 1x1 conv -> padded NHWC ===================
__global__ __launch_bounds__(256) void k_conv_in(const float* __restrict__ x,
                                                 const float* __restrict__ w,
                                                 const float* __restrict__ bias) {
    __shared__ float Ws[32*WP];
    __shared__ float Xs[32*64];
    int tid = threadIdx.x;
    int b  = blockIdx.y;
    int p0 = blockIdx.x * 64;
    int ty = tid >> 4, tx = tid & 15;
    int cob = ty*8, pxb = tx*4;

    ACC_INIT
    for (int cb = 0; cb < CH; cb += 32) {
        __syncthreads();
        for (int idx = tid; idx < 4096; idx += 256) {
            int co = idx >> 5, c = idx & 31;
            Ws[c*WP + co] = w[co*CH + cb + c];
        }
        for (int idx = tid; idx < 2048; idx += 256) {
            int c = idx >> 6, p = idx & 63;
            Xs[c*64 + p] = x[((size_t)b*CH + cb + c)*HW + p0 + p];
        }
        __syncthreads();
#pragma unroll 8
        for (int c = 0; c < 32; c++) { GSTEP(&Xs[c*64 + pxb], &Ws[c*WP + cob]) }
    }
    float v[4][8];
#pragma unroll
    for (int k = 0; k < 4; k++)
#pragma unroll
        for (int px = 0; px < 4; px++) {
            float2 f = unp2(acc[px][k]);
            v[px][2*k] = f.x; v[px][2*k+1] = f.y;
        }
    float bb[8];
#pragma unroll
    for (int u = 0; u < 8; u++) bb[u] = __ldg(&bias[cob + u]);
#pragma unroll
    for (int px = 0; px < 4; px++) {
        int pix = p0 + pxb + px;
        int i = pix / 96, j = pix - i*96;
        size_t pbase = ((size_t)b*P98 + (i+1)*98 + (j+1))*CH + cob;
        float fv[8];
#pragma unroll
        for (int u = 0; u < 8; u++) fv[u] = v[px][u] + bb[u];
        *(float4*)&g_xp[pbase]   = make_float4(fv[0], fv[1], fv[2], fv[3]);
        *(float4*)&g_xp[pbase+4] = make_float4(fv[4], fv[5], fv[6], fv[7]);
        __nv_bfloat162 hv[4], lv[4];
#pragma unroll
        for (int u = 0; u < 4; u++) {
            __nv_bfloat16 h0,l0,h1,l1;
            split2(fv[2*u], h0, l0); split2(fv[2*u+1], h1, l1);
            hv[u].x = h0; hv[u].y = h1; lv[u].x = l0; lv[u].y = l1;
        }
        *(uint4*)&g_xpH[pbase] = *(uint4*)hv;
        *(uint4*)&g_xpL[pbase] = *(uint4*)lv;
    }
}

// ===================== MMA K=128 tap: warp computes 32x32 ===================
__device__ __forceinline__ void mma_tap(const char* sA, const char* sB, float acc[2][4][4],
                                        int pb, int cb, int g, int t) {
#pragma unroll
    for (int ks = 0; ks < 8; ks++) {
        int kb = ks*32 + t*4;
        u32 ah[2][4], al[2][4];
#pragma unroll
        for (int mt = 0; mt < 2; mt++) {
            int r0 = (pb + mt*16 + g)*256 + kb;
            int r1 = r0 + 8*256;
            int o0 = SWZ(r0), o1 = SWZ(r1), o2 = SWZ(r0 + 16), o3 = SWZ(r1 + 16);
            ah[mt][0] = *(const u32*)(sA + o0);
            ah[mt][1] = *(const u32*)(sA + o1);
            ah[mt][2] = *(const u32*)(sA + o2);
            ah[mt][3] = *(const u32*)(sA + o3);
            al[mt][0] = *(const u32*)(sA + 32768 + o0);
            al[mt][1] = *(const u32*)(sA + 32768 + o1);
            al[mt][2] = *(const u32*)(sA + 32768 + o2);
            al[mt][3] = *(const u32*)(sA + 32768 + o3);
        }
#pragma unroll
        for (int nt = 0; nt < 4; nt++) {
            int rb = (cb + nt*8 + g)*256 + kb;
            int ob0 = SWZ(rb), ob1 = SWZ(rb + 16);
            u32 bh0 = *(const u32*)(sB + ob0);
            u32 bh1 = *(const u32*)(sB + ob1);
            u32 bl0 = *(const u32*)(sB + 32768 + ob0);
            u32 bl1 = *(const u32*)(sB + 32768 + ob1);
#pragma unroll
            for (int mt = 0; mt < 2; mt++) {
                MMA_BF16(acc[mt][nt], ah[mt], bh0, bh1);
                MMA_BF16(acc[mt][nt], ah[mt], bl0, bl1);
                MMA_BF16(acc[mt][nt], al[mt], bh0, bh1);
            }
        }
    }
}

// offset-conv extra MMAs: 3 n8-tiles from small B_off tile (hi@sBo, lo@sBo+6144)
__device__ __forceinline__ void mma_tap_off(const char* sA, const char* sBo, float acco[2][3][4],
                                            int pb, int g, int t) {
#pragma unroll
    for (int ks = 0; ks < 8; ks++) {
        int kb = ks*32 + t*4;
        u32 ah[2][4], al[2][4];
#pragma unroll
        for (int mt = 0; mt < 2; mt++) {
            int r0 = (pb + mt*16 + g)*256 + kb;
            int r1 = r0 + 8*256;
            int o0 = SWZ(r0), o1 = SWZ(r1), o2 = SWZ(r0 + 16), o3 = SWZ(r1 + 16);
            ah[mt][0] = *(const u32*)(sA + o0);
            ah[mt][1] = *(const u32*)(sA + o1);
            ah[mt][2] = *(const u32*)(sA + o2);
            ah[mt][3] = *(const u32*)(sA + o3);
            al[mt][0] = *(const u32*)(sA + 32768 + o0);
            al[mt][1] = *(const u32*)(sA + 32768 + o1);
            al[mt][2] = *(const u32*)(sA + 32768 + o2);
            al[mt][3] = *(const u32*)(sA + 32768 + o3);
        }
#pragma unroll
        for (int nt = 0; nt < 3; nt++) {
            int rb = (nt*8 + g)*256 + kb;
            int ob0 = SWZ(rb), ob1 = SWZ(rb + 16);
            u32 bh0 = *(const u32*)(sBo + ob0);
            u32 bh1 = *(const u32*)(sBo + ob1);
            u32 bl0 = *(const u32*)(sBo + 6144 + ob0);
            u32 bl1 = *(const u32*)(sBo + 6144 + ob1);
#pragma unroll
            for (int mt = 0; mt < 2; mt++) {
                MMA_BF16(acco[mt][nt], ah[mt], bh0, bh1);
                MMA_BF16(acco[mt][nt], ah[mt], bl0, bl1);
                MMA_BF16(acco[mt][nt], al[mt], bh0, bh1);
            }
        }
    }
}

// weight cp.async stage: 4096 x 16B granules (hi+lo), identity mapping
__device__ __forceinline__ void stage_B(u32 dstu, const __nv_bfloat16* srcH,
                                        const __nv_bfloat16* srcL, int tid) {
    const char* sh = (const char*)srcH;
    const char* sl = (const char*)srcL;
    for (int i2 = tid; i2 < 2048; i2 += TMM) {
        CP16(dstu + i2*16,         sh + i2*16);
        CP16(dstu + 32768 + i2*16, sl + i2*16);
    }
}

// A tile cp.async stage for std branch (shifted window from padded buffer)
__device__ __forceinline__ void stage_A_std(u32 abase, int b, int p0, int n, int tid) {
    int di = n/3 - 1, dj = n%3 - 1;
    const char* sh = (const char*)(g_xpH + (size_t)b*P98*CH);
    const char* sl = (const char*)(g_xpL + (size_t)b*P98*CH);
    for (int idx = tid; idx < 2048; idx += TMM) {
        int px = idx >> 4, g16 = idx & 15;
        int pix = p0 + px;
        int i = pix / 96, j = pix - i*96;
        size_t src = ((size_t)((i+1+di)*98 + (j+1+dj))*CH)*2 + g16*16;
        u32 dst = abase + SWZ(px*256 + g16*16);
        CP16(dst, sh + src);
        CP16(dst + 32768, sl + src);
    }
}

// ===================== k_tstd: std 3x3 branch + fused offset conv ===========
__global__ __launch_bounds__(TMM) void k_tstd(const float* __restrict__ bstd,
                                              const float* __restrict__ bn2,
                                              const float* __restrict__ boff) {
    extern __shared__ char smem[];
    u32 sb = smem_to_u32(smem);
    int tid = threadIdx.x, wid = tid >> 5, lane = tid & 31;
    int g = lane >> 2, t = lane & 3;
    int wm = wid & 3, wn = wid >> 2;
    int pb = wm*32, cb = wn*32;
    int tile = blockIdx.x, b = blockIdx.y;
    int p0 = tile * 128;

    float acc[2][4][4];
    float acco[2][3][4];
#pragma unroll
    for (int i = 0; i < 2; i++) {
#pragma unroll
        for (int j = 0; j < 4; j++)
#pragma unroll
            for (int k = 0; k < 4; k++) acc[i][j][k] = 0.f;
#pragma unroll
        for (int j = 0; j < 3; j++)
#pragma unroll
            for (int k = 0; k < 4; k++) acco[i][j][k] = 0.f;
    }

    // prologue: A(0)+Boff(0) group, then B(0) group
    stage_A_std(sb + TS_A0, b, p0, 0, tid);
    if (tid < 384) {
        CP16(sb + TS_BO0 + tid*16,        ((const char*)g_wfH) + tid*16);
        CP16(sb + TS_BO0 + 6144 + tid*16, ((const char*)g_wfL) + tid*16);
    }
    CP_COMMIT();
    stage_B(sb + TS_B, g_wsH, g_wsL, tid);
    CP_COMMIT();

    for (int n = 0; n < 9; n++) {
        CP_WAIT0();
        __syncthreads();                  // A(n), Boff(n), B(n) resident
        if (n < 8) {                      // prefetch A(n+1)+Boff(n+1) under MMA(n)
            u32 anext = sb + (((n+1)&1) ? TS_A1 : TS_A0);
            stage_A_std(anext, b, p0, n+1, tid);
            u32 bonext = sb + (((n+1)&1) ? TS_BO1 : TS_BO0);
            if (tid < 384) {
                CP16(bonext + tid*16,        ((const char*)g_wfH) + (size_t)(n+1)*6144 + tid*16);
                CP16(bonext + 6144 + tid*16, ((const char*)g_wfL) + (size_t)(n+1)*6144 + tid*16);
            }
            CP_COMMIT();
        }
        const char* sA = smem + ((n&1) ? TS_A1 : TS_A0);
        mma_tap(sA, smem + TS_B, acc, pb, cb, g, t);
        if (wn == 3) mma_tap_off(sA, smem + ((n&1) ? TS_BO1 : TS_BO0), acco, pb, g, t);
        __syncthreads();                  // all warps done reading B(n)
        if (n < 8) {
            stage_B(sb + TS_B, g_wsH + (n+1)*16384, g_wsL + (n+1)*16384, tid);
            CP_COMMIT();
        }
    }
    const float* xpb = g_xp + (size_t)b*P98*CH;
    char* oH = (char*)(g_a2H + (size_t)(b*NTILES + tile)*16384);
    char* oL = (char*)(g_a2L + (size_t)(b*NTILES + tile)*16384);
#pragma unroll
    for (int mt = 0; mt < 2; mt++)
#pragma unroll
        for (int nt = 0; nt < 4; nt++) {
            int row = pb + mt*16 + g;
            int co  = cb + nt*8 + 2*t;
            float i0 = __ldg(&bn2[co]) / sqrtf(__ldg(&bn2[384+co]) + EPSBN);
            float a0 = __ldg(&bn2[128+co]) - __ldg(&bn2[256+co]) * i0;
            float i1 = __ldg(&bn2[co+1]) / sqrtf(__ldg(&bn2[385+co]) + EPSBN);
            float a1 = __ldg(&bn2[129+co]) - __ldg(&bn2[257+co]) * i1;
            float b0v = __ldg(&bstd[co]), b1v = __ldg(&bstd[co+1]);
            const float* d = acc[mt][nt];
            int pix0 = p0 + row, pix1 = p0 + row + 8;
            int i_0 = pix0/96, j_0 = pix0 - i_0*96;
            int i_1 = pix1/96, j_1 = pix1 - i_1*96;
            float2 xc0 = *(const float2*)(xpb + (size_t)((i_0+1)*98 + j_0+1)*CH + co);
            float2 xc1 = *(const float2*)(xpb + (size_t)((i_1+1)*98 + j_1+1)*CH + co);
            float f00 = fmaxf((d[0] + b0v)*i0 + a0, 0.f) + xc0.x;
            float f01 = fmaxf((d[1] + b1v)*i1 + a1, 0.f) + xc0.y;
            float f10 = fmaxf((d[2] + b0v)*i0 + a0, 0.f) + xc1.x;
            float f11 = fmaxf((d[3] + b1v)*i1 + a1, 0.f) + xc1.y;
            __nv_bfloat16 h0,l0,h1,l1;
            split2(f00,h0,l0); split2(f01,h1,l1);
            int off = SWZ(row*256 + co*2);
            __nv_bfloat162 hv; hv.x=h0; hv.y=h1;
            __nv_bfloat162 lv; lv.x=l0; lv.y=l1;
            *(__nv_bfloat162*)(oH + off) = hv;
            *(__nv_bfloat162*)(oL + off) = lv;
            split2(f10,h0,l0); split2(f11,h1,l1);
            off = SWZ((row+8)*256 + co*2);
            hv.x=h0; hv.y=h1; lv.x=l0; lv.y=l1;
            *(__nv_bfloat162*)(oH + off) = hv;
            *(__nv_bfloat162*)(oL + off) = lv;
        }
    if (wn == 3) {
#pragma unroll
        for (int mt = 0; mt < 2; mt++)
#pragma unroll
            for (int nt = 0; nt < 3; nt++) {
                int co = nt*8 + 2*t;
                if (co < 18) {
                    int row = pb + mt*16 + g;
                    const float* d = acco[mt][nt];
                    g_off[(size_t)(b*18 + co  )*HW + p0 + row]     = d[0] + __ldg(&boff[co]);
                    g_off[(size_t)(b*18 + co+1)*HW + p0 + row]     = d[1] + __ldg(&boff[co+1]);
                    g_off[(size_t)(b*18 + co  )*HW + p0 + row + 8] = d[2] + __ldg(&boff[co]);
                    g_off[(size_t)(b*18 + co+1)*HW + p0 + row + 8] = d[3] + __ldg(&boff[co+1]);
                }
            }
    }
}

// ===================== deform gather: fill one A buffer for tap n ===========
__device__ __forceinline__ void gather_tap(char* sA, const float* xpb, int b, int p0,
                                           int n, int wid, int lane) {
    float dnx = (float)(n/3 - 1), dny = (float)(n%3 - 1);
#pragma unroll 4
    for (int k = 0; k < 8; k++) {
        int px = wid*8 + k;
        int pix = p0 + px;
        int i = pix / 96, j = pix - i*96;
        float ox = __ldg(&g_off[(size_t)(b*18 + n    )*HW + pix]);
        float oy = __ldg(&g_off[(size_t)(b*18 + n + 9)*HW + pix]);
        float pfx = ox + dnx + (float)(i + 1);
        float pfy = oy + dny + (float)(j + 1);
        float qx = floorf(pfx), qy = floorf(pfy);
        float ltx = fminf(fmaxf(qx,       0.f), 97.f);
        float lty = fminf(fmaxf(qy,       0.f), 97.f);
        float rbx = fminf(fmaxf(qx + 1.f, 0.f), 97.f);
        float rby = fminf(fmaxf(qy + 1.f, 0.f), 97.f);
        float pcx = fminf(fmaxf(pfx, 0.f), 97.f);
        float pcy = fminf(fmaxf(pfy, 0.f), 97.f);
        float glt = (1.f + (ltx - pcx)) * (1.f + (lty - pcy));
        float grb = (1.f - (rbx - pcx)) * (1.f - (rby - pcy));
        float glb = (1.f + (ltx - pcx)) * (1.f - (rby - pcy));
        float grt = (1.f - (rbx - pcx)) * (1.f + (lty - pcy));
        int ix0 = (int)ltx, iy0 = (int)lty, ix1 = (int)rbx, iy1 = (int)rby;
        const float* plt = xpb + (size_t)(ix0*98 + iy0)*CH;
        const float* prb = xpb + (size_t)(ix1*98 + iy1)*CH;
        const float* plb = xpb + (size_t)(ix0*98 + iy1)*CH;
        const float* prt = xpb + (size_t)(ix1*98 + iy0)*CH;
#pragma unroll
        for (int it = 0; it < 2; it++) {
            int ci0 = it*64 + lane*2;
            float2 a2 = *(const float2*)(plt + ci0);
            float2 b2 = *(const float2*)(prb + ci0);
            float2 c2 = *(const float2*)(plb + ci0);
            float2 d2 = *(const float2*)(prt + ci0);
            float v0 = glt*a2.x + grb*b2.x + glb*c2.x + grt*d2.x;
            float v1 = glt*a2.y + grb*b2.y + glb*c2.y + grt*d2.y;
            __nv_bfloat16 h0, l0, h1, l1;
            split2(v0, h0, l0); split2(v1, h1, l1);
            int off = SWZ(px*256 + ci0*2);
            __nv_bfloat162 hv; hv.x = h0; hv.y = h1;
            __nv_bfloat162 lv; lv.x = l0; lv.y = l1;
            *(__nv_bfloat162*)(sA + off) = hv;
            *(__nv_bfloat162*)(sA + 32768 + off) = lv;
        }
    }
}

// ===================== k_tdef: deform branch (pipelined gather) =============
__global__ __launch_bounds__(TMM) void k_tdef(const float* __restrict__ bdef,
                                              const float* __restrict__ bn1) {
    extern __shared__ char smem[];
    u32 sb = smem_to_u32(smem);
    int tid = threadIdx.x, wid = tid >> 5, lane = tid & 31;
    int g = lane >> 2, t = lane & 3;
    int wm = wid & 3, wn = wid >> 2;
    int pb = wm*32, cb = wn*32;
    int tile = blockIdx.x, b = blockIdx.y;
    int p0 = tile * 128;

    float acc[2][4][4];
#pragma unroll
    for (int i = 0; i < 2; i++)
#pragma unroll
        for (int j = 0; j < 4; j++)
#pragma unroll
            for (int k = 0; k < 4; k++) acc[i][j][k] = 0.f;

    const float* xpb = g_xp + (size_t)b*P98*CH;

    // prologue: B(0) cp.async; gather A(0)
    stage_B(sb + TD_B, g_wdH, g_wdL, tid);
    CP_COMMIT();
    gather_tap(smem + TD_A0, xpb, b, p0, 0, wid, lane);

    for (int n = 0; n < 9; n++) {
        CP_WAIT0();
        __syncthreads();                  // A(n) gathered by all, B(n) resident
        if (n < 8)                        // gather A(n+1) overlaps other warps' MMA(n)
            gather_tap(smem + (((n+1)&1) ? TD_A1 : TD_A0), xpb, b, p0, n+1, wid, lane);
        mma_tap(smem + ((n&1) ? TD_A1 : TD_A0), smem + TD_B, acc, pb, cb, g, t);
        __syncthreads();                  // all warps done with B(n) + gathers done
        if (n < 8) {
            stage_B(sb + TD_B, g_wdH + (n+1)*16384, g_wdL + (n+1)*16384, tid);
            CP_COMMIT();
        }
    }
    char* oH = (char*)(g_a1H + (size_t)(b*NTILES + tile)*16384);
    char* oL = (char*)(g_a1L + (size_t)(b*NTILES + tile)*16384);
#pragma unroll
    for (int mt = 0; mt < 2; mt++)
#pragma unroll
        for (int nt = 0; nt < 4; nt++) {
            int row = pb + mt*16 + g;
            int co  = cb + nt*8 + 2*t;
            float i0 = __ldg(&bn1[co]) / sqrtf(__ldg(&bn1[384+co]) + EPSBN);
            float a0 = __ldg(&bn1[128+co]) - __ldg(&bn1[256+co]) * i0;
            float i1 = __ldg(&bn1[co+1]) / sqrtf(__ldg(&bn1[385+co]) + EPSBN);
            float a1 = __ldg(&bn1[129+co]) - __ldg(&bn1[257+co]) * i1;
            float b0v = __ldg(&bdef[co]), b1v = __ldg(&bdef[co+1]);
            const float* d = acc[mt][nt];
            float f00 = fmaxf((d[0] + b0v)*i0 + a0, 0.f);
            float f01 = fmaxf((d[1] + b1v)*i1 + a1, 0.f);
            float f10 = fmaxf((d[2] + b0v)*i0 + a0, 0.f);
            float f11 = fmaxf((d[3] + b1v)*i1 + a1, 0.f);
            __nv_bfloat16 h0,l0,h1,l1;
            split2(f00,h0,l0); split2(f01,h1,l1);
            int off = SWZ(row*256 + co*2);
            __nv_bfloat162 hv; hv.x=h0; hv.y=h1;
            __nv_bfloat162 lv; lv.x=l0; lv.y=l1;
            *(__nv_bfloat162*)(oH + off) = hv;
            *(__nv_bfloat162*)(oL + off) = lv;
            split2(f10,h0,l0); split2(f11,h1,l1);
            off = SWZ((row+8)*256 + co*2);
            hv.x=h0; hv.y=h1; lv.x=l0; lv.y=l1;
            *(__nv_bfloat162*)(oH + off) = hv;
            *(__nv_bfloat162*)(oL + off) = lv;
        }
}

// ===================== k_tout: final 1x1 conv ===============================
__global__ __launch_bounds__(TMM) void k_tout(const float* __restrict__ bias,
                                              float* __restrict__ out) {
    extern __shared__ char smem[];
    u32 sb = smem_to_u32(smem);
    int tid = threadIdx.x, wid = tid >> 5, lane = tid & 31;
    int g = lane >> 2, t = lane & 3;
    int wm = wid & 3, wn = wid >> 2;
    int pb = wm*32, cb = wn*32;
    int tile = blockIdx.x, b = blockIdx.y, z = blockIdx.z;
    int p0 = tile * 128;

    float acc[2][4][4];
#pragma unroll
    for (int i = 0; i < 2; i++)
#pragma unroll
        for (int j = 0; j < 4; j++)
#pragma unroll
            for (int k = 0; k < 4; k++) acc[i][j][k] = 0.f;

    for (int kc = 0; kc < 2; kc++) {
        __syncthreads();
        {
            const char* wh = (const char*)(g_woH + (z*2 + kc)*16384);
            const char* wl = (const char*)(g_woL + (z*2 + kc)*16384);
            const char* ah = (const char*)((kc ? g_a2H : g_a1H) + (size_t)(b*NTILES + tile)*16384);
            const char* al = (const char*)((kc ? g_a2L : g_a1L) + (size_t)(b*NTILES + tile)*16384);
            for (int i2 = tid; i2 < 2048; i2 += TMM) {
                CP16(sb + TO_A + i2*16,         ah + i2*16);
                CP16(sb + TO_A + 32768 + i2*16, al + i2*16);
                CP16(sb + TO_B + i2*16,         wh + i2*16);
                CP16(sb + TO_B + 32768 + i2*16, wl + i2*16);
            }
            CP_COMMIT();
            CP_WAIT0();
        }
        __syncthreads();
        mma_tap(smem + TO_A, smem + TO_B, acc, pb, cb, g, t);
    }
#pragma unroll
    for (int mt = 0; mt < 2; mt++)
#pragma unroll
        for (int nt = 0; nt < 4; nt++) {
            int row = p0 + pb + mt*16 + g;
            int co  = z*128 + cb + nt*8 + 2*t;
            float b0v = __ldg(&bias[co]), b1v = __ldg(&bias[co+1]);
            const float* d = acc[mt][nt];
            out[((size_t)(b*256 + co  ))*HW + row]     = d[0] + b0v;
            out[((size_t)(b*256 + co+1))*HW + row]     = d[1] + b1v;
            out[((size_t)(b*256 + co  ))*HW + row + 8] = d[2] + b0v;
            out[((size_t)(b*256 + co+1))*HW + row + 8] = d[3] + b1v;
        }
}

// ===================== launch ===============================================
extern "C" void kernel_launch(void* const* d_in, const int* in_sizes, int n_in,
                              void* d_out, int out_size) {
    const float* x     = (const float*)d_in[0];
    const float* w_in  = (const float*)d_in[1];
    const float* b_in  = (const float*)d_in[2];
    const float* w_off = (const float*)d_in[3];
    const float* b_off = (const float*)d_in[4];
    const float* w_def = (const float*)d_in[5];
    const float* b_def = (const float*)d_in[6];
    const float* bn1   = (const float*)d_in[7];
    const float* w_std = (const float*)d_in[8];
    const float* b_std = (const float*)d_in[9];
    const float* bn2   = (const float*)d_in[10];
    const float* w_out = (const float*)d_in[11];
    const float* b_out = (const float*)d_in[12];
    float* out = (float*)d_out;

    cudaFuncSetAttribute(k_tdef, cudaFuncAttributeMaxDynamicSharedMemorySize, SMEM_TD);
    cudaFuncSetAttribute(k_tstd, cudaFuncAttributeMaxDynamicSharedMemorySize, SMEM_TS);
    cudaFuncSetAttribute(k_tout, cudaFuncAttributeMaxDynamicSharedMemorySize, SMEM_TO);

    k_zero   <<<2048, 256>>>();
    k_prep   <<<940, 256>>>(w_def, w_std, w_out, w_off);
    k_conv_in<<<dim3(144, BATCH), 256>>>(x, w_in, b_in);
    k_tstd   <<<dim3(NTILES, BATCH), TMM, SMEM_TS>>>(b_std, bn2, b_off);
    k_tdef   <<<dim3(NTILES, BATCH), TMM, SMEM_TD>>>(b_def, bn1);
    k_tout   <<<dim3(NTILES, BATCH, 2), TMM, SMEM_TO>>>(b_out, out);
}

// round 16
// speedup vs baseline: 2.5958x; 1.2099x over previous
#include <cuda_runtime.h>
#include <cuda_bf16.h>
#include <cstdint>

#define BATCH 4
#define CH 128
#define HH 96
#define WW 96
#define HW (HH*WW)
#define P98 9604           // 98*98 padded image
#define EPSBN 1e-5f
#define NTILES 72          // 9216 px / 128

#define WP 132
#define TMM 512            // threads per MMA kernel block

typedef unsigned long long u64;
typedef uint32_t u32;

// ===================== scalar fp32x2 helpers (conv_in) ======================
__device__ __forceinline__ void fma2(u64 &d, u64 a, u64 b) {
    asm("fma.rn.f32x2 %0, %1, %2, %0;" : "+l"(d) : "l"(a), "l"(b));
}
__device__ __forceinline__ u64 bc2(float x) {
    u64 r; asm("mov.b64 %0, {%1, %1};" : "=l"(r) : "f"(x)); return r;
}
__device__ __forceinline__ float2 unp2(u64 v) {
    float2 f; asm("mov.b64 {%0, %1}, %2;" : "=f"(f.x), "=f"(f.y) : "l"(v)); return f;
}
#define GSTEP(SROW, WROW) { \
    float4 xv = *(const float4*)(SROW); \
    ulonglong2 wA = *(const ulonglong2*)(WROW); \
    ulonglong2 wB = *(const ulonglong2*)((WROW)+4); \
    u64 xb0=bc2(xv.x), xb1=bc2(xv.y), xb2=bc2(xv.z), xb3=bc2(xv.w); \
    fma2(acc[0][0],wA.x,xb0); fma2(acc[0][1],wA.y,xb0); fma2(acc[0][2],wB.x,xb0); fma2(acc[0][3],wB.y,xb0); \
    fma2(acc[1][0],wA.x,xb1); fma2(acc[1][1],wA.y,xb1); fma2(acc[1][2],wB.x,xb1); fma2(acc[1][3],wB.y,xb1); \
    fma2(acc[2][0],wA.x,xb2); fma2(acc[2][1],wA.y,xb2); fma2(acc[2][2],wB.x,xb2); fma2(acc[2][3],wB.y,xb2); \
    fma2(acc[3][0],wA.x,xb3); fma2(acc[3][1],wA.y,xb3); fma2(acc[3][2],wB.x,xb3); fma2(acc[3][3],wB.y,xb3); }
#define ACC_INIT u64 acc[4][4]; _Pragma("unroll") for (int _i=0;_i<4;_i++) _Pragma("unroll") for(int _j=0;_j<4;_j++) acc[_i][_j]=0ull;

// ===================== mma.sync + ldmatrix + cp.async helpers ===============
#define SWZ(x) ((x) ^ ((((x) >> 8) & 7) << 4))

#define MMA_BF16(D, A, B0, B1) \
    asm volatile("mma.sync.aligned.m16n8k16.row.col.f32.bf16.bf16.f32 " \
        "{%0,%1,%2,%3}, {%4,%5,%6,%7}, {%8,%9}, {%0,%1,%2,%3};" \
        : "+f"((D)[0]), "+f"((D)[1]), "+f"((D)[2]), "+f"((D)[3]) \
        : "r"((A)[0]), "r"((A)[1]), "r"((A)[2]), "r"((A)[3]), "r"(B0), "r"(B1))

__device__ __forceinline__ void ldsm4(u32* r, u32 a) {
    asm volatile("ldmatrix.sync.aligned.m8n8.x4.shared.b16 {%0,%1,%2,%3}, [%4];"
        : "=r"(r[0]), "=r"(r[1]), "=r"(r[2]), "=r"(r[3]) : "r"(a));
}
__device__ __forceinline__ void ldsm2(u32* r, u32 a) {
    asm volatile("ldmatrix.sync.aligned.m8n8.x2.shared.b16 {%0,%1}, [%2];"
        : "=r"(r[0]), "=r"(r[1]) : "r"(a));
}

#define CP16(d, s)  asm volatile("cp.async.cg.shared.global [%0], [%1], 16;" :: "r"(d), "l"(s) : "memory")
#define CP_COMMIT() asm volatile("cp.async.commit_group;" ::: "memory")
#define CP_WAIT0()  asm volatile("cp.async.wait_group 0;" ::: "memory")

__device__ __forceinline__ u32 smem_to_u32(const void* p) {
    u32 a;
    asm("{ .reg .u64 t; cvta.to.shared.u64 t, %1; cvt.u32.u64 %0, t; }" : "=r"(a) : "l"(p));
    return a;
}
__device__ __forceinline__ void split2(float v, __nv_bfloat16 &h, __nv_bfloat16 &l) {
    h = __float2bfloat16(v);
    l = __float2bfloat16(v - __bfloat162float(h));
}

// smem layouts (each A buffer: hi 32K then lo 32K)
#define TD_A0   0
#define TD_A1   65536
#define TD_B    131072
#define SMEM_TD 196608     // tdef: A0,A1,B
#define TS_A0   0
#define TS_A1   65536
#define TS_B    131072
#define TS_BO0  196608
#define TS_BO1  208896
#define SMEM_TS 221184     // tstd: A0,A1,B,Bo0,Bo1
#define TO_A    0
#define TO_B    65536
#define SMEM_TO 131072     // tout

// ===================== scratch globals ======================================
__device__ float g_xp [BATCH*P98*CH];           // x_c padded NHWC fp32
__device__ __nv_bfloat16 g_xpH[BATCH*P98*CH];   // padded NHWC bf16 hi
__device__ __nv_bfloat16 g_xpL[BATCH*P98*CH];   // padded NHWC bf16 lo
__device__ float g_off[BATCH*18*HW];
__device__ __nv_bfloat16 g_wdH[9*16384], g_wdL[9*16384];
__device__ __nv_bfloat16 g_wsH[9*16384], g_wsL[9*16384];
__device__ __nv_bfloat16 g_woH[4*16384], g_woL[4*16384];
__device__ __nv_bfloat16 g_wfH[9*3072],  g_wfL[9*3072];   // offset conv weights (24 rows x 128)
__device__ __nv_bfloat16 g_a1H[BATCH*NTILES*16384], g_a1L[BATCH*NTILES*16384];
__device__ __nv_bfloat16 g_a2H[BATCH*NTILES*16384], g_a2L[BATCH*NTILES*16384];

// ===================== k_zero: clear padded buffers =========================
__global__ void k_zero() {
    size_t idx = (size_t)blockIdx.x*256 + threadIdx.x;
    size_t stride = (size_t)gridDim.x*256;
    for (size_t i = idx; i < (size_t)BATCH*P98*CH/4; i += stride)
        ((float4*)g_xp)[i] = make_float4(0.f,0.f,0.f,0.f);
    for (size_t i = idx; i < (size_t)BATCH*P98*CH/8; i += stride) {
        ((uint4*)g_xpH)[i] = make_uint4(0,0,0,0);
        ((uint4*)g_xpL)[i] = make_uint4(0,0,0,0);
    }
}

// ===================== k_prep: weight split + swizzled tiles ================
__global__ void k_prep(const float* __restrict__ wdef, const float* __restrict__ wstd,
                       const float* __restrict__ wout, const float* __restrict__ woff) {
    int idx = blockIdx.x * 256 + threadIdx.x;
    if (idx < 147456) {
        int n = idx / 16384, r = idx % 16384;
        int co = r >> 7, ci = r & 127;
        int off = SWZ(co*256 + ci*2);
        int dst = n*16384 + (off >> 1);
        int src = co*1152 + ci*9 + n;
        __nv_bfloat16 h, l;
        split2(wdef[src], h, l); g_wdH[dst] = h; g_wdL[dst] = l;
        split2(wstd[src], h, l); g_wsH[dst] = h; g_wsL[dst] = l;
    } else if (idx < 147456 + 65536) {
        int j = idx - 147456;
        int ci = j & 127, co = (j >> 7) & 127, kc = (j >> 14) & 1, z = (j >> 15) & 1;
        int off = SWZ(co*256 + ci*2);
        int dst = (z*2 + kc)*16384 + (off >> 1);
        __nv_bfloat16 h, l;
        split2(wout[(z*128 + co)*256 + kc*128 + ci], h, l);
        g_woH[dst] = h; g_woL[dst] = l;
    } else if (idx < 147456 + 65536 + 27648) {
        int j = idx - 147456 - 65536;
        int n = j / 3072, r = j % 3072;
        int co = r >> 7, ci = r & 127;        // co 0..23
        float v = (co < 18) ? woff[co*1152 + ci*9 + n] : 0.f;
        int off = SWZ(co*256 + ci*2);
        int dst = n*3072 + (off >> 1);
        __nv_bfloat16 h, l;
        split2(v, h, l); g_wfH[dst] = h; g_wfL[dst] = l;
    }
}

// ===================== k_conv_in: 1x1 conv -> padded NHWC ===================
__global__ __launch_bounds__(256) void k_conv_in(const float* __restrict__ x,
                                                 const float* __restrict__ w,
                                                 const float* __restrict__ bias) {
    __shared__ float Ws[32*WP];
    __shared__ float Xs[32*64];
    int tid = threadIdx.x;
    int b  = blockIdx.y;
    int p0 = blockIdx.x * 64;
    int ty = tid >> 4, tx = tid & 15;
    int cob = ty*8, pxb = tx*4;

    ACC_INIT
    for (int cb = 0; cb < CH; cb += 32) {
        __syncthreads();
        for (int idx = tid; idx < 4096; idx += 256) {
            int co = idx >> 5, c = idx & 31;
            Ws[c*WP + co] = w[co*CH + cb + c];
        }
        for (int idx = tid; idx < 2048; idx += 256) {
            int c = idx >> 6, p = idx & 63;
            Xs[c*64 + p] = x[((size_t)b*CH + cb + c)*HW + p0 + p];
        }
        __syncthreads();
#pragma unroll 8
        for (int c = 0; c < 32; c++) { GSTEP(&Xs[c*64 + pxb], &Ws[c*WP + cob]) }
    }
    float v[4][8];
#pragma unroll
    for (int k = 0; k < 4; k++)
#pragma unroll
        for (int px = 0; px < 4; px++) {
            float2 f = unp2(acc[px][k]);
            v[px][2*k] = f.x; v[px][2*k+1] = f.y;
        }
    float bb[8];
#pragma unroll
    for (int u = 0; u < 8; u++) bb[u] = __ldg(&bias[cob + u]);
#pragma unroll
    for (int px = 0; px < 4; px++) {
        int pix = p0 + pxb + px;
        int i = pix / 96, j = pix - i*96;
        size_t pbase = ((size_t)b*P98 + (i+1)*98 + (j+1))*CH + cob;
        float fv[8];
#pragma unroll
        for (int u = 0; u < 8; u++) fv[u] = v[px][u] + bb[u];
        *(float4*)&g_xp[pbase]   = make_float4(fv[0], fv[1], fv[2], fv[3]);
        *(float4*)&g_xp[pbase+4] = make_float4(fv[4], fv[5], fv[6], fv[7]);
        __nv_bfloat162 hv[4], lv[4];
#pragma unroll
        for (int u = 0; u < 4; u++) {
            __nv_bfloat16 h0,l0,h1,l1;
            split2(fv[2*u], h0, l0); split2(fv[2*u+1], h1, l1);
            hv[u].x = h0; hv[u].y = h1; lv[u].x = l0; lv[u].y = l1;
        }
        *(uint4*)&g_xpH[pbase] = *(uint4*)hv;
        *(uint4*)&g_xpL[pbase] = *(uint4*)lv;
    }
}

// ===================== MMA K=128 tap (ldmatrix): warp computes 32x32 ========
__device__ __forceinline__ void mma_tap(u32 sA, u32 sB, float acc[2][4][4],
                                        int pb, int cb, int lane) {
    int l15 = lane & 15;
    u32 hA = (u32)((lane >> 4) << 4);
    int rA = pb + l15;
    u32 mA = (u32)((rA & 7) << 4);
    u32 baseA0 = sA + rA*256;
    u32 baseA1 = baseA0 + 16*256;
    int rB = cb + ((lane >> 4) & 1)*8 + (lane & 7);
    u32 hB = (u32)(((lane >> 3) & 1) << 4);
    u32 mB = (u32)((rB & 7) << 4);
    u32 baseB0 = sB + rB*256;
    u32 baseB1 = baseB0 + 16*256;
#pragma unroll
    for (int ks = 0; ks < 8; ks++) {
        u32 offA = ((u32)(ks*32) + hA) ^ mA;
        u32 offB = ((u32)(ks*32) + hB) ^ mB;
        u32 ah0[4], ah1[4], al0[4], al1[4];
        ldsm4(ah0, baseA0 + offA);
        ldsm4(ah1, baseA1 + offA);
        ldsm4(al0, baseA0 + 32768 + offA);
        ldsm4(al1, baseA1 + 32768 + offA);
        u32 bh[8], bl[8];
        ldsm4(bh,     baseB0 + offB);
        ldsm4(bh + 4, baseB1 + offB);
        ldsm4(bl,     baseB0 + 32768 + offB);
        ldsm4(bl + 4, baseB1 + 32768 + offB);
#pragma unroll
        for (int nt = 0; nt < 4; nt++) {
            u32 b0h = bh[nt*2], b1h = bh[nt*2+1];
            u32 b0l = bl[nt*2], b1l = bl[nt*2+1];
            MMA_BF16(acc[0][nt], ah0, b0h, b1h);
            MMA_BF16(acc[0][nt], ah0, b0l, b1l);
            MMA_BF16(acc[0][nt], al0, b0h, b1h);
            MMA_BF16(acc[1][nt], ah1, b0h, b1h);
            MMA_BF16(acc[1][nt], ah1, b0l, b1l);
            MMA_BF16(acc[1][nt], al1, b0h, b1h);
        }
    }
}

// offset-conv extra MMAs (ldmatrix): 3 n8-tiles from 24x128 B_off tile
__device__ __forceinline__ void mma_tap_off(u32 sA, u32 sBo, float acco[2][3][4],
                                            int pb, int lane) {
    int l15 = lane & 15;
    u32 hA = (u32)((lane >> 4) << 4);
    int rA = pb + l15;
    u32 mA = (u32)((rA & 7) << 4);
    u32 baseA0 = sA + rA*256;
    u32 baseA1 = baseA0 + 16*256;
    int rB = ((lane >> 4) & 1)*8 + (lane & 7);
    u32 hB = (u32)(((lane >> 3) & 1) << 4);
    u32 mB = (u32)((rB & 7) << 4);
    u32 baseO0 = sBo + rB*256;
    int rB2 = 16 + (lane & 7);
    u32 mB2 = (u32)((rB2 & 7) << 4);
    u32 baseO2 = sBo + rB2*256;
#pragma unroll
    for (int ks = 0; ks < 8; ks++) {
        u32 offA  = ((u32)(ks*32) + hA) ^ mA;
        u32 offB  = ((u32)(ks*32) + hB) ^ mB;
        u32 offB2 = ((u32)(ks*32) + hB) ^ mB2;
        u32 ah0[4], ah1[4], al0[4], al1[4];
        ldsm4(ah0, baseA0 + offA);
        ldsm4(ah1, baseA1 + offA);
        ldsm4(al0, baseA0 + 32768 + offA);
        ldsm4(al1, baseA1 + 32768 + offA);
        u32 bh[6], bl[6];
        ldsm4(bh,     baseO0 + offB);
        ldsm2(bh + 4, baseO2 + offB2);
        ldsm4(bl,     baseO0 + 6144 + offB);
        ldsm2(bl + 4, baseO2 + 6144 + offB2);
#pragma unroll
        for (int nt = 0; nt < 3; nt++) {
            u32 b0h = bh[nt*2], b1h = bh[nt*2+1];
            u32 b0l = bl[nt*2], b1l = bl[nt*2+1];
            MMA_BF16(acco[0][nt], ah0, b0h, b1h);
            MMA_BF16(acco[0][nt], ah0, b0l, b1l);
            MMA_BF16(acco[0][nt], al0, b0h, b1h);
            MMA_BF16(acco[1][nt], ah1, b0h, b1h);
            MMA_BF16(acco[1][nt], ah1, b0l, b1l);
            MMA_BF16(acco[1][nt], al1, b0h, b1h);
        }
    }
}

// weight cp.async stage: 4096 x 16B granules (hi+lo), identity mapping
__device__ __forceinline__ void stage_B(u32 dstu, const __nv_bfloat16* srcH,
                                        const __nv_bfloat16* srcL, int tid) {
    const char* sh = (const char*)srcH;
    const char* sl = (const char*)srcL;
    for (int i2 = tid; i2 < 2048; i2 += TMM) {
        CP16(dstu + i2*16,         sh + i2*16);
        CP16(dstu + 32768 + i2*16, sl + i2*16);
    }
}

// A tile cp.async stage for std branch (shifted window from padded buffer)
__device__ __forceinline__ void stage_A_std(u32 abase, int b, int p0, int n, int tid) {
    int di = n/3 - 1, dj = n%3 - 1;
    const char* sh = (const char*)(g_xpH + (size_t)b*P98*CH);
    const char* sl = (const char*)(g_xpL + (size_t)b*P98*CH);
    for (int idx = tid; idx < 2048; idx += TMM) {
        int px = idx >> 4, g16 = idx & 15;
        int pix = p0 + px;
        int i = pix / 96, j = pix - i*96;
        size_t src = ((size_t)((i+1+di)*98 + (j+1+dj))*CH)*2 + g16*16;
        u32 dst = abase + SWZ(px*256 + g16*16);
        CP16(dst, sh + src);
        CP16(dst + 32768, sl + src);
    }
}

// ===================== k_tstd: std 3x3 branch + fused offset conv ===========
__global__ __launch_bounds__(TMM) void k_tstd(const float* __restrict__ bstd,
                                              const float* __restrict__ bn2,
                                              const float* __restrict__ boff) {
    extern __shared__ char smem[];
    u32 sb = smem_to_u32(smem);
    int tid = threadIdx.x, wid = tid >> 5, lane = tid & 31;
    int g = lane >> 2, t = lane & 3;
    int wm = wid & 3, wn = wid >> 2;
    int pb = wm*32, cb = wn*32;
    int tile = blockIdx.x, b = blockIdx.y;
    int p0 = tile * 128;

    float acc[2][4][4];
    float acco[2][3][4];
#pragma unroll
    for (int i = 0; i < 2; i++) {
#pragma unroll
        for (int j = 0; j < 4; j++)
#pragma unroll
            for (int k = 0; k < 4; k++) acc[i][j][k] = 0.f;
#pragma unroll
        for (int j = 0; j < 3; j++)
#pragma unroll
            for (int k = 0; k < 4; k++) acco[i][j][k] = 0.f;
    }

    // prologue: A(0)+Boff(0) group, then B(0) group
    stage_A_std(sb + TS_A0, b, p0, 0, tid);
    if (tid < 384) {
        CP16(sb + TS_BO0 + tid*16,        ((const char*)g_wfH) + tid*16);
        CP16(sb + TS_BO0 + 6144 + tid*16, ((const char*)g_wfL) + tid*16);
    }
    CP_COMMIT();
    stage_B(sb + TS_B, g_wsH, g_wsL, tid);
    CP_COMMIT();

    for (int n = 0; n < 9; n++) {
        CP_WAIT0();
        __syncthreads();                  // A(n), Boff(n), B(n) resident
        if (n < 8) {                      // prefetch A(n+1)+Boff(n+1) under MMA(n)
            u32 anext = sb + (((n+1)&1) ? TS_A1 : TS_A0);
            stage_A_std(anext, b, p0, n+1, tid);
            u32 bonext = sb + (((n+1)&1) ? TS_BO1 : TS_BO0);
            if (tid < 384) {
                CP16(bonext + tid*16,        ((const char*)g_wfH) + (size_t)(n+1)*6144 + tid*16);
                CP16(bonext + 6144 + tid*16, ((const char*)g_wfL) + (size_t)(n+1)*6144 + tid*16);
            }
            CP_COMMIT();
        }
        u32 sA = sb + ((n&1) ? TS_A1 : TS_A0);
        mma_tap(sA, sb + TS_B, acc, pb, cb, lane);
        if (wn == 3) mma_tap_off(sA, sb + ((n&1) ? TS_BO1 : TS_BO0), acco, pb, lane);
        __syncthreads();                  // all warps done reading B(n)
        if (n < 8) {
            stage_B(sb + TS_B, g_wsH + (n+1)*16384, g_wsL + (n+1)*16384, tid);
            CP_COMMIT();
        }
    }
    const float* xpb = g_xp + (size_t)b*P98*CH;
    char* oH = (char*)(g_a2H + (size_t)(b*NTILES + tile)*16384);
    char* oL = (char*)(g_a2L + (size_t)(b*NTILES + tile)*16384);
#pragma unroll
    for (int mt = 0; mt < 2; mt++)
#pragma unroll
        for (int nt = 0; nt < 4; nt++) {
            int row = pb + mt*16 + g;
            int co  = cb + nt*8 + 2*t;
            float i0 = __ldg(&bn2[co]) / sqrtf(__ldg(&bn2[384+co]) + EPSBN);
            float a0 = __ldg(&bn2[128+co]) - __ldg(&bn2[256+co]) * i0;
            float i1 = __ldg(&bn2[co+1]) / sqrtf(__ldg(&bn2[385+co]) + EPSBN);
            float a1 = __ldg(&bn2[129+co]) - __ldg(&bn2[257+co]) * i1;
            float b0v = __ldg(&bstd[co]), b1v = __ldg(&bstd[co+1]);
            const float* d = acc[mt][nt];
            int pix0 = p0 + row, pix1 = p0 + row + 8;
            int i_0 = pix0/96, j_0 = pix0 - i_0*96;
            int i_1 = pix1/96, j_1 = pix1 - i_1*96;
            float2 xc0 = *(const float2*)(xpb + (size_t)((i_0+1)*98 + j_0+1)*CH + co);
            float2 xc1 = *(const float2*)(xpb + (size_t)((i_1+1)*98 + j_1+1)*CH + co);
            float f00 = fmaxf((d[0] + b0v)*i0 + a0, 0.f) + xc0.x;
            float f01 = fmaxf((d[1] + b1v)*i1 + a1, 0.f) + xc0.y;
            float f10 = fmaxf((d[2] + b0v)*i0 + a0, 0.f) + xc1.x;
            float f11 = fmaxf((d[3] + b1v)*i1 + a1, 0.f) + xc1.y;
            __nv_bfloat16 h0,l0,h1,l1;
            split2(f00,h0,l0); split2(f01,h1,l1);
            int off = SWZ(row*256 + co*2);
            __nv_bfloat162 hv; hv.x=h0; hv.y=h1;
            __nv_bfloat162 lv; lv.x=l0; lv.y=l1;
            *(__nv_bfloat162*)(oH + off) = hv;
            *(__nv_bfloat162*)(oL + off) = lv;
            split2(f10,h0,l0); split2(f11,h1,l1);
            off = SWZ((row+8)*256 + co*2);
            hv.x=h0; hv.y=h1; lv.x=l0; lv.y=l1;
            *(__nv_bfloat162*)(oH + off) = hv;
            *(__nv_bfloat162*)(oL + off) = lv;
        }
    if (wn == 3) {
#pragma unroll
        for (int mt = 0; mt < 2; mt++)
#pragma unroll
            for (int nt = 0; nt < 3; nt++) {
                int co = nt*8 + 2*t;
                if (co < 18) {
                    int row = pb + mt*16 + g;
                    const float* d = acco[mt][nt];
                    g_off[(size_t)(b*18 + co  )*HW + p0 + row]     = d[0] + __ldg(&boff[co]);
                    g_off[(size_t)(b*18 + co+1)*HW + p0 + row]     = d[1] + __ldg(&boff[co+1]);
                    g_off[(size_t)(b*18 + co  )*HW + p0 + row + 8] = d[2] + __ldg(&boff[co]);
                    g_off[(size_t)(b*18 + co+1)*HW + p0 + row + 8] = d[3] + __ldg(&boff[co+1]);
                }
            }
    }
}

// ===================== deform gather: fill one A buffer for tap n ===========
__device__ __forceinline__ void gather_tap(char* sA, const float* xpb, int b, int p0,
                                           int n, int wid, int lane) {
    float dnx = (float)(n/3 - 1), dny = (float)(n%3 - 1);
#pragma unroll 4
    for (int k = 0; k < 8; k++) {
        int px = wid*8 + k;
        int pix = p0 + px;
        int i = pix / 96, j = pix - i*96;
        float ox = __ldg(&g_off[(size_t)(b*18 + n    )*HW + pix]);
        float oy = __ldg(&g_off[(size_t)(b*18 + n + 9)*HW + pix]);
        float pfx = ox + dnx + (float)(i + 1);
        float pfy = oy + dny + (float)(j + 1);
        float qx = floorf(pfx), qy = floorf(pfy);
        float ltx = fminf(fmaxf(qx,       0.f), 97.f);
        float lty = fminf(fmaxf(qy,       0.f), 97.f);
        float rbx = fminf(fmaxf(qx + 1.f, 0.f), 97.f);
        float rby = fminf(fmaxf(qy + 1.f, 0.f), 97.f);
        float pcx = fminf(fmaxf(pfx, 0.f), 97.f);
        float pcy = fminf(fmaxf(pfy, 0.f), 97.f);
        float glt = (1.f + (ltx - pcx)) * (1.f + (lty - pcy));
        float grb = (1.f - (rbx - pcx)) * (1.f - (rby - pcy));
        float glb = (1.f + (ltx - pcx)) * (1.f - (rby - pcy));
        float grt = (1.f - (rbx - pcx)) * (1.f + (lty - pcy));
        int ix0 = (int)ltx, iy0 = (int)lty, ix1 = (int)rbx, iy1 = (int)rby;
        const float* plt = xpb + (size_t)(ix0*98 + iy0)*CH;
        const float* prb = xpb + (size_t)(ix1*98 + iy1)*CH;
        const float* plb = xpb + (size_t)(ix0*98 + iy1)*CH;
        const float* prt = xpb + (size_t)(ix1*98 + iy0)*CH;
#pragma unroll
        for (int it = 0; it < 2; it++) {
            int ci0 = it*64 + lane*2;
            float2 a2 = *(const float2*)(plt + ci0);
            float2 b2 = *(const float2*)(prb + ci0);
            float2 c2 = *(const float2*)(plb + ci0);
            float2 d2 = *(const float2*)(prt + ci0);
            float v0 = glt*a2.x + grb*b2.x + glb*c2.x + grt*d2.x;
            float v1 = glt*a2.y + grb*b2.y + glb*c2.y + grt*d2.y;
            __nv_bfloat16 h0, l0, h1, l1;
            split2(v0, h0, l0); split2(v1, h1, l1);
            int off = SWZ(px*256 + ci0*2);
            __nv_bfloat162 hv; hv.x = h0; hv.y = h1;
            __nv_bfloat162 lv; lv.x = l0; lv.y = l1;
            *(__nv_bfloat162*)(sA + off) = hv;
            *(__nv_bfloat162*)(sA + 32768 + off) = lv;
        }
    }
}

// ===================== k_tdef: deform branch (pipelined gather) =============
__global__ __launch_bounds__(TMM) void k_tdef(const float* __restrict__ bdef,
                                              const float* __restrict__ bn1) {
    extern __shared__ char smem[];
    u32 sb = smem_to_u32(smem);
    int tid = threadIdx.x, wid = tid >> 5, lane = tid & 31;
    int g = lane >> 2, t = lane & 3;
    int wm = wid & 3, wn = wid >> 2;
    int pb = wm*32, cb = wn*32;
    int tile = blockIdx.x, b = blockIdx.y;
    int p0 = tile * 128;

    float acc[2][4][4];
#pragma unroll
    for (int i = 0; i < 2; i++)
#pragma unroll
        for (int j = 0; j < 4; j++)
#pragma unroll
            for (int k = 0; k < 4; k++) acc[i][j][k] = 0.f;

    const float* xpb = g_xp + (size_t)b*P98*CH;

    // prologue: B(0) cp.async; gather A(0)
    stage_B(sb + TD_B, g_wdH, g_wdL, tid);
    CP_COMMIT();
    gather_tap(smem + TD_A0, xpb, b, p0, 0, wid, lane);

    for (int n = 0; n < 9; n++) {
        CP_WAIT0();
        __syncthreads();                  // A(n) gathered by all, B(n) resident
        if (n < 8)                        // gather A(n+1) overlaps other warps' MMA(n)
            gather_tap(smem + (((n+1)&1) ? TD_A1 : TD_A0), xpb, b, p0, n+1, wid, lane);
        mma_tap(sb + ((n&1) ? TD_A1 : TD_A0), sb + TD_B, acc, pb, cb, lane);
        __syncthreads();                  // all warps done with B(n) + gathers done
        if (n < 8) {
            stage_B(sb + TD_B, g_wdH + (n+1)*16384, g_wdL + (n+1)*16384, tid);
            CP_COMMIT();
        }
    }
    char* oH = (char*)(g_a1H + (size_t)(b*NTILES + tile)*16384);
    char* oL = (char*)(g_a1L + (size_t)(b*NTILES + tile)*16384);
#pragma unroll
    for (int mt = 0; mt < 2; mt++)
#pragma unroll
        for (int nt = 0; nt < 4; nt++) {
            int row = pb + mt*16 + g;
            int co  = cb + nt*8 + 2*t;
            float i0 = __ldg(&bn1[co]) / sqrtf(__ldg(&bn1[384+co]) + EPSBN);
            float a0 = __ldg(&bn1[128+co]) - __ldg(&bn1[256+co]) * i0;
            float i1 = __ldg(&bn1[co+1]) / sqrtf(__ldg(&bn1[385+co]) + EPSBN);
            float a1 = __ldg(&bn1[129+co]) - __ldg(&bn1[257+co]) * i1;
            float b0v = __ldg(&bdef[co]), b1v = __ldg(&bdef[co+1]);
            const float* d = acc[mt][nt];
            float f00 = fmaxf((d[0] + b0v)*i0 + a0, 0.f);
            float f01 = fmaxf((d[1] + b1v)*i1 + a1, 0.f);
            float f10 = fmaxf((d[2] + b0v)*i0 + a0, 0.f);
            float f11 = fmaxf((d[3] + b1v)*i1 + a1, 0.f);
            __nv_bfloat16 h0,l0,h1,l1;
            split2(f00,h0,l0); split2(f01,h1,l1);
            int off = SWZ(row*256 + co*2);
            __nv_bfloat162 hv; hv.x=h0; hv.y=h1;
            __nv_bfloat162 lv; lv.x=l0; lv.y=l1;
            *(__nv_bfloat162*)(oH + off) = hv;
            *(__nv_bfloat162*)(oL + off) = lv;
            split2(f10,h0,l0); split2(f11,h1,l1);
            off = SWZ((row+8)*256 + co*2);
            hv.x=h0; hv.y=h1; lv.x=l0; lv.y=l1;
            *(__nv_bfloat162*)(oH + off) = hv;
            *(__nv_bfloat162*)(oL + off) = lv;
        }
}

// ===================== k_tout: final 1x1 conv ===============================
__global__ __launch_bounds__(TMM) void k_tout(const float* __restrict__ bias,
                                              float* __restrict__ out) {
    extern __shared__ char smem[];
    u32 sb = smem_to_u32(smem);
    int tid = threadIdx.x, wid = tid >> 5, lane = tid & 31;
    int g = lane >> 2, t = lane & 3;
    int wm = wid & 3, wn = wid >> 2;
    int pb = wm*32, cb = wn*32;
    int tile = blockIdx.x, b = blockIdx.y, z = blockIdx.z;
    int p0 = tile * 128;

    float acc[2][4][4];
#pragma unroll
    for (int i = 0; i < 2; i++)
#pragma unroll
        for (int j = 0; j < 4; j++)
#pragma unroll
            for (int k = 0; k < 4; k++) acc[i][j][k] = 0.f;

    for (int kc = 0; kc < 2; kc++) {
        __syncthreads();
        {
            const char* wh = (const char*)(g_woH + (z*2 + kc)*16384);
            const char* wl = (const char*)(g_woL + (z*2 + kc)*16384);
            const char* ah = (const char*)((kc ? g_a2H : g_a1H) + (size_t)(b*NTILES + tile)*16384);
            const char* al = (const char*)((kc ? g_a2L : g_a1L) + (size_t)(b*NTILES + tile)*16384);
            for (int i2 = tid; i2 < 2048; i2 += TMM) {
                CP16(sb + TO_A + i2*16,         ah + i2*16);
                CP16(sb + TO_A + 32768 + i2*16, al + i2*16);
                CP16(sb + TO_B + i2*16,         wh + i2*16);
                CP16(sb + TO_B + 32768 + i2*16, wl + i2*16);
            }
            CP_COMMIT();
            CP_WAIT0();
        }
        __syncthreads();
        mma_tap(sb + TO_A, sb + TO_B, acc, pb, cb, lane);
    }
#pragma unroll
    for (int mt = 0; mt < 2; mt++)
#pragma unroll
        for (int nt = 0; nt < 4; nt++) {
            int row = p0 + pb + mt*16 + g;
            int co  = z*128 + cb + nt*8 + 2*t;
            float b0v = __ldg(&bias[co]), b1v = __ldg(&bias[co+1]);
            const float* d = acc[mt][nt];
            out[((size_t)(b*256 + co  ))*HW + row]     = d[0] + b0v;
            out[((size_t)(b*256 + co+1))*HW + row]     = d[1] + b1v;
            out[((size_t)(b*256 + co  ))*HW + row + 8] = d[2] + b0v;
            out[((size_t)(b*256 + co+1))*HW + row + 8] = d[3] + b1v;
        }
}

// ===================== launch ===============================================
extern "C" void kernel_launch(void* const* d_in, const int* in_sizes, int n_in,
                              void* d_out, int out_size) {
    const float* x     = (const float*)d_in[0];
    const float* w_in  = (const float*)d_in[1];
    const float* b_in  = (const float*)d_in[2];
    const float* w_off = (const float*)d_in[3];
    const float* b_off = (const float*)d_in[4];
    const float* w_def = (const float*)d_in[5];
    const float* b_def = (const float*)d_in[6];
    const float* bn1   = (const float*)d_in[7];
    const float* w_std = (const float*)d_in[8];
    const float* b_std = (const float*)d_in[9];
    const float* bn2   = (const float*)d_in[10];
    const float* w_out = (const float*)d_in[11];
    const float* b_out = (const float*)d_in[12];
    float* out = (float*)d_out;

    cudaFuncSetAttribute(k_tdef, cudaFuncAttributeMaxDynamicSharedMemorySize, SMEM_TD);
    cudaFuncSetAttribute(k_tstd, cudaFuncAttributeMaxDynamicSharedMemorySize, SMEM_TS);
    cudaFuncSetAttribute(k_tout, cudaFuncAttributeMaxDynamicSharedMemorySize, SMEM_TO);

    k_zero   <<<2048, 256>>>();
    k_prep   <<<940, 256>>>(w_def, w_std, w_out, w_off);
    k_conv_in<<<dim3(144, BATCH), 256>>>(x, w_in, b_in);
    k_tstd   <<<dim3(NTILES, BATCH), TMM, SMEM_TS>>>(b_std, bn2, b_off);
    k_tdef   <<<dim3(NTILES, BATCH), TMM, SMEM_TD>>>(b_def, bn1);
    k_tout   <<<dim3(NTILES, BATCH, 2), TMM, SMEM_TO>>>(b_out, out);
}